// round 1
// baseline (speedup 1.0000x reference)
#include <cuda_runtime.h>
#include <math.h>

// Problem constants (fixed by setup_inputs)
#define BB    2
#define TT    4096
#define DDIM  2048
#define NH    32
#define NKV   8
#define DHD   64
#define TCC   4096
#define WIN   1024
#define WSTART (TCC - WIN)   // 3072
#define SCALE 0.125f         // 1/sqrt(64)

// Scratch (device globals — allocation-free rule)
__device__ float g_q [(size_t)BB * NH * TT * DHD];   // [B,H,T,DH] after RoPE
__device__ float g_ao[(size_t)BB * TT * DDIM];       // [B,T,H*DH] attention out

// ============================================================================
// Kernel 1: q = RoPE(x @ Wq^T), written as [B,H,T,DH]
// SGEMM: C[M=8192, N=2048] = A[M,K=2048] * Wq[N,K]^T
// 128x128 block tile, BK=16, 256 threads, 8x8 per-thread micro-tile.
// ============================================================================
__global__ void __launch_bounds__(256) qgemm_rope_kernel(
    const float* __restrict__ A, const float* __restrict__ W)
{
    __shared__ float As[16][128];
    __shared__ float Bs[16][128];
    const int tid = threadIdx.x;
    const int bn = blockIdx.x, bm = blockIdx.y;
    const int tx = tid & 15, ty = tid >> 4;
    const int lr = tid >> 2;          // 0..63
    const int lc = (tid & 3) << 2;    // 0,4,8,12

    const float* Ag = A + (size_t)(bm * 128 + lr) * DDIM + lc;
    const float* Wg = W + (size_t)(bn * 128 + lr) * DDIM + lc;

    float acc[8][8];
#pragma unroll
    for (int i = 0; i < 8; i++)
#pragma unroll
        for (int j = 0; j < 8; j++) acc[i][j] = 0.f;

    for (int k0 = 0; k0 < DDIM; k0 += 16) {
#pragma unroll
        for (int hh = 0; hh < 2; ++hh) {
            float4 av = *(const float4*)(Ag + (size_t)hh * 64 * DDIM + k0);
            As[lc + 0][lr + hh * 64] = av.x;
            As[lc + 1][lr + hh * 64] = av.y;
            As[lc + 2][lr + hh * 64] = av.z;
            As[lc + 3][lr + hh * 64] = av.w;
            float4 wv = *(const float4*)(Wg + (size_t)hh * 64 * DDIM + k0);
            Bs[lc + 0][lr + hh * 64] = wv.x;
            Bs[lc + 1][lr + hh * 64] = wv.y;
            Bs[lc + 2][lr + hh * 64] = wv.z;
            Bs[lc + 3][lr + hh * 64] = wv.w;
        }
        __syncthreads();
#pragma unroll
        for (int k = 0; k < 16; ++k) {
            float ar[8], br[8];
            *(float4*)&ar[0] = *(const float4*)&As[k][ty * 8];
            *(float4*)&ar[4] = *(const float4*)&As[k][ty * 8 + 4];
            *(float4*)&br[0] = *(const float4*)&Bs[k][tx * 8];
            *(float4*)&br[4] = *(const float4*)&Bs[k][tx * 8 + 4];
#pragma unroll
            for (int i = 0; i < 8; i++)
#pragma unroll
                for (int j = 0; j < 8; j++)
                    acc[i][j] = fmaf(ar[i], br[j], acc[i][j]);
        }
        __syncthreads();
    }

    // Epilogue: interleaved RoPE, scatter to g_q[B,H,T,DH]
    const int n0 = bn * 128 + tx * 8;   // even-aligned
    const int hh = n0 >> 6;
    const int d0 = n0 & 63;
    float invf[4];
#pragma unroll
    for (int jp = 0; jp < 4; jp++) {
        int idx = (d0 >> 1) + jp;       // frequency index 0..31
        invf[jp] = (float)exp(-(double)idx * (9.210340371976184 / 32.0)); // 10000^(-idx/32)
    }
#pragma unroll
    for (int i = 0; i < 8; i++) {
        int mrow = bm * 128 + ty * 8 + i;
        int b = mrow >> 12;             // / 4096
        int t = mrow & 4095;
        float ov[8];
#pragma unroll
        for (int jp = 0; jp < 4; jp++) {
            float ph = (float)t * invf[jp];
            float sn, cn;
            sincosf(ph, &sn, &cn);
            float e = acc[i][2 * jp], od = acc[i][2 * jp + 1];
            ov[2 * jp]     = e * cn - od * sn;
            ov[2 * jp + 1] = e * sn + od * cn;
        }
        float* qp = g_q + ((size_t)(b * NH + hh) * TT + t) * DHD + d0;
        *(float4*)(qp)     = *(float4*)&ov[0];
        *(float4*)(qp + 4) = *(float4*)&ov[4];
    }
}

// ============================================================================
// Kernel 2: windowed causal attention with online softmax.
// Block = (qt, bh): 64 queries x up to 1024 keys in 64-key tiles.
// Thread (r = tid/4, sg = tid%4): row r, 16-wide column group sg.
// ============================================================================
#define PAD 68
__global__ void __launch_bounds__(256) attn_kernel(
    const float* __restrict__ kc, const float* __restrict__ vc)
{
    extern __shared__ float smraw[];
    float (*Qs)[PAD] = (float(*)[PAD])(smraw);
    float (*Ks)[PAD] = (float(*)[PAD])(smraw + 64 * PAD);       // [d][s]
    float (*Vs)[PAD] = (float(*)[PAD])(smraw + 2 * 64 * PAD);   // [s][d]
    float (*Ps)[PAD] = (float(*)[PAD])(smraw + 3 * 64 * PAD);   // [r][s]

    const int qt = blockIdx.x;      // 0..63
    const int bh = blockIdx.y;      // 0..63
    const int b  = bh >> 5, h = bh & 31;
    const int kv = h >> 2;          // GQA: rep = 4
    const int tid = threadIdx.x;
    const int r  = tid >> 2, sg = tid & 3;

    // Load Q tile (64 x 64)
    {
        const float* qp = g_q + ((size_t)bh * TT + (size_t)qt * 64) * DHD;
        int rr = tid >> 4;              // 0..15
        int c4 = (tid & 15) << 2;       // 0..60
#pragma unroll
        for (int p = 0; p < 4; ++p) {
            int row = rr + p * 16;
            *(float4*)&Qs[row][c4] = *(const float4*)(qp + (size_t)row * DHD + c4);
        }
    }

    const float* kbase = kc + ((size_t)(b * NKV + kv) * TCC + WSTART) * DHD;
    const float* vbase = vc + ((size_t)(b * NKV + kv) * TCC + WSTART) * DHD;

    float mrow = -INFINITY, lrow = 0.f;
    float o[16];
#pragma unroll
    for (int i = 0; i < 16; i++) o[i] = 0.f;

    const int kbmax = (qt < 16) ? qt : 15;
    for (int kb = 0; kb <= kbmax; ++kb) {
        __syncthreads();   // protect Qs (first iter) and Ks/Vs/Ps reuse
        {
            int rr = tid >> 4, c4 = (tid & 15) << 2;
#pragma unroll
            for (int p = 0; p < 4; ++p) {
                int s = rr + p * 16;
                float4 kvv = *(const float4*)(kbase + (size_t)(kb * 64 + s) * DHD + c4);
                Ks[c4 + 0][s] = kvv.x;
                Ks[c4 + 1][s] = kvv.y;
                Ks[c4 + 2][s] = kvv.z;
                Ks[c4 + 3][s] = kvv.w;
                *(float4*)&Vs[s][c4] = *(const float4*)(vbase + (size_t)(kb * 64 + s) * DHD + c4);
            }
        }
        __syncthreads();

        // S[r][sg*16 + i] = sum_d Q[r][d] * K[s][d]
        float sreg[16];
#pragma unroll
        for (int i = 0; i < 16; i++) sreg[i] = 0.f;
#pragma unroll 4
        for (int d = 0; d < 64; ++d) {
            float qv = Qs[r][d];
            float kvr[16];
            const float* kr = &Ks[d][sg * 16];
            *(float4*)&kvr[0]  = *(const float4*)(kr);
            *(float4*)&kvr[4]  = *(const float4*)(kr + 4);
            *(float4*)&kvr[8]  = *(const float4*)(kr + 8);
            *(float4*)&kvr[12] = *(const float4*)(kr + 12);
#pragma unroll
            for (int i = 0; i < 16; i++) sreg[i] = fmaf(qv, kvr[i], sreg[i]);
        }

        // scale + causal mask (only diagonal block of early q-tiles)
        const bool diag = (qt < 16) && (kb == qt);
#pragma unroll
        for (int i = 0; i < 16; i++) {
            float sv = sreg[i] * SCALE;
            if (diag && (sg * 16 + i) > r) sv = -INFINITY;
            sreg[i] = sv;
        }

        // row max (4 threads per row are consecutive lanes)
        float mb = sreg[0];
#pragma unroll
        for (int i = 1; i < 16; i++) mb = fmaxf(mb, sreg[i]);
        mb = fmaxf(mb, __shfl_xor_sync(0xffffffffu, mb, 1));
        mb = fmaxf(mb, __shfl_xor_sync(0xffffffffu, mb, 2));

        float mnew = fmaxf(mrow, mb);
        float corr = __expf(mrow - mnew);   // exp(-inf) = 0 on first block
        float lsum = 0.f;
#pragma unroll
        for (int i = 0; i < 16; i++) {
            float p = __expf(sreg[i] - mnew);
            sreg[i] = p;
            lsum += p;
        }
        lsum += __shfl_xor_sync(0xffffffffu, lsum, 1);
        lsum += __shfl_xor_sync(0xffffffffu, lsum, 2);
        lrow = lrow * corr + lsum;
        mrow = mnew;
#pragma unroll
        for (int i = 0; i < 16; i++) o[i] *= corr;

        *(float4*)&Ps[r][sg * 16]      = *(float4*)&sreg[0];
        *(float4*)&Ps[r][sg * 16 + 4]  = *(float4*)&sreg[4];
        *(float4*)&Ps[r][sg * 16 + 8]  = *(float4*)&sreg[8];
        *(float4*)&Ps[r][sg * 16 + 12] = *(float4*)&sreg[12];
        __syncthreads();

        // O[r][sg*16 + j] += sum_s P[r][s] * V[s][sg*16 + j]
#pragma unroll 4
        for (int s = 0; s < 64; ++s) {
            float p = Ps[r][s];
            float vv[16];
            const float* vr = &Vs[s][sg * 16];
            *(float4*)&vv[0]  = *(const float4*)(vr);
            *(float4*)&vv[4]  = *(const float4*)(vr + 4);
            *(float4*)&vv[8]  = *(const float4*)(vr + 8);
            *(float4*)&vv[12] = *(const float4*)(vr + 12);
#pragma unroll
            for (int i = 0; i < 16; i++) o[i] = fmaf(p, vv[i], o[i]);
        }
    }

    // finalize: divide by l, write [B,T,H*DH]
    float invl = 1.f / lrow;
    float ov[16];
#pragma unroll
    for (int i = 0; i < 16; i++) ov[i] = o[i] * invl;
    float* op = g_ao + ((size_t)(b * TT + qt * 64 + r)) * DDIM + h * DHD + sg * 16;
    *(float4*)(op)      = *(float4*)&ov[0];
    *(float4*)(op + 4)  = *(float4*)&ov[4];
    *(float4*)(op + 8)  = *(float4*)&ov[8];
    *(float4*)(op + 12) = *(float4*)&ov[12];
}

// ============================================================================
// Kernel 3: out = g_ao @ Wo^T  (same SGEMM, plain store)
// ============================================================================
__global__ void __launch_bounds__(256) ogemm_kernel(
    const float* __restrict__ W, float* __restrict__ Cout)
{
    __shared__ float As[16][128];
    __shared__ float Bs[16][128];
    const int tid = threadIdx.x;
    const int bn = blockIdx.x, bm = blockIdx.y;
    const int tx = tid & 15, ty = tid >> 4;
    const int lr = tid >> 2;
    const int lc = (tid & 3) << 2;

    const float* Ag = g_ao + (size_t)(bm * 128 + lr) * DDIM + lc;
    const float* Wg = W    + (size_t)(bn * 128 + lr) * DDIM + lc;

    float acc[8][8];
#pragma unroll
    for (int i = 0; i < 8; i++)
#pragma unroll
        for (int j = 0; j < 8; j++) acc[i][j] = 0.f;

    for (int k0 = 0; k0 < DDIM; k0 += 16) {
#pragma unroll
        for (int hh = 0; hh < 2; ++hh) {
            float4 av = *(const float4*)(Ag + (size_t)hh * 64 * DDIM + k0);
            As[lc + 0][lr + hh * 64] = av.x;
            As[lc + 1][lr + hh * 64] = av.y;
            As[lc + 2][lr + hh * 64] = av.z;
            As[lc + 3][lr + hh * 64] = av.w;
            float4 wv = *(const float4*)(Wg + (size_t)hh * 64 * DDIM + k0);
            Bs[lc + 0][lr + hh * 64] = wv.x;
            Bs[lc + 1][lr + hh * 64] = wv.y;
            Bs[lc + 2][lr + hh * 64] = wv.z;
            Bs[lc + 3][lr + hh * 64] = wv.w;
        }
        __syncthreads();
#pragma unroll
        for (int k = 0; k < 16; ++k) {
            float ar[8], br[8];
            *(float4*)&ar[0] = *(const float4*)&As[k][ty * 8];
            *(float4*)&ar[4] = *(const float4*)&As[k][ty * 8 + 4];
            *(float4*)&br[0] = *(const float4*)&Bs[k][tx * 8];
            *(float4*)&br[4] = *(const float4*)&Bs[k][tx * 8 + 4];
#pragma unroll
            for (int i = 0; i < 8; i++)
#pragma unroll
                for (int j = 0; j < 8; j++)
                    acc[i][j] = fmaf(ar[i], br[j], acc[i][j]);
        }
        __syncthreads();
    }

#pragma unroll
    for (int i = 0; i < 8; i++) {
        int mrow = bm * 128 + ty * 8 + i;
        float* cp = Cout + (size_t)mrow * DDIM + bn * 128 + tx * 8;
        *(float4*)(cp)     = make_float4(acc[i][0], acc[i][1], acc[i][2], acc[i][3]);
        *(float4*)(cp + 4) = make_float4(acc[i][4], acc[i][5], acc[i][6], acc[i][7]);
    }
}

// ============================================================================
extern "C" void kernel_launch(void* const* d_in, const int* in_sizes, int n_in,
                              void* d_out, int out_size)
{
    const float* x  = (const float*)d_in[0];
    const float* kc = (const float*)d_in[1];
    const float* vc = (const float*)d_in[2];
    const float* Wq = (const float*)d_in[3];
    const float* Wo = (const float*)d_in[4];
    float* out = (float*)d_out;

    (void)in_sizes; (void)n_in; (void)out_size;

    const int attn_smem = 4 * 64 * PAD * (int)sizeof(float);   // 69,632 B
    cudaFuncSetAttribute(attn_kernel, cudaFuncAttributeMaxDynamicSharedMemorySize, attn_smem);

    dim3 gblk(256);
    dim3 ggrid(DDIM / 128, (BB * TT) / 128);   // (16, 64)
    qgemm_rope_kernel<<<ggrid, gblk>>>(x, Wq);

    dim3 agrid(TT / 64, BB * NH);              // (64, 64)
    attn_kernel<<<agrid, gblk, attn_smem>>>(kc, vc);

    ogemm_kernel<<<ggrid, gblk>>>(Wo, out);
}

// round 4
// speedup vs baseline: 1.2446x; 1.2446x over previous
#include <cuda_runtime.h>
#include <cuda_bf16.h>
#include <math.h>
#include <stdint.h>

// Problem constants
#define BB    2
#define TT    4096
#define DDIM  2048
#define NH    32
#define NKV   8
#define DHD   64
#define TCC   4096
#define WIN   1024
#define WSTART 3072
#define SCALE 0.125f

// ---------------------------------------------------------------------------
// Scratch (device globals — allocation-free rule)
// ---------------------------------------------------------------------------
__device__ float         g_q    [(size_t)BB * NH * TT * DHD];    // RoPE'd q [B,H,T,DH]
__device__ __nv_bfloat16 g_x_hi [(size_t)BB * TT * DDIM];
__device__ __nv_bfloat16 g_x_lo [(size_t)BB * TT * DDIM];
__device__ __nv_bfloat16 g_wq_hi[(size_t)DDIM * DDIM];
__device__ __nv_bfloat16 g_wq_lo[(size_t)DDIM * DDIM];
__device__ __nv_bfloat16 g_wo_hi[(size_t)DDIM * DDIM];
__device__ __nv_bfloat16 g_wo_lo[(size_t)DDIM * DDIM];
__device__ __nv_bfloat16 g_ao_hi[(size_t)BB * TT * DDIM];
__device__ __nv_bfloat16 g_ao_lo[(size_t)BB * TT * DDIM];
__device__ float         g_invfreq[32];

extern __shared__ char smraw[];

// ---------------------------------------------------------------------------
// Helpers (baseline PTX only: ldmatrix / mma.sync / cp.async — all sm_80+)
// ---------------------------------------------------------------------------
__device__ __forceinline__ uint32_t smem_u32(const void* p) {
    uint32_t a;
    asm("{ .reg .u64 t; cvta.to.shared.u64 t, %1; cvt.u32.u64 %0, t; }"
        : "=r"(a) : "l"(p));
    return a;
}

__device__ __forceinline__ void ldsm4(uint32_t* r, uint32_t addr) {
    asm volatile("ldmatrix.sync.aligned.m8n8.x4.shared.b16 {%0,%1,%2,%3}, [%4];"
        : "=r"(r[0]), "=r"(r[1]), "=r"(r[2]), "=r"(r[3]) : "r"(addr));
}

__device__ __forceinline__ void mma16816(float* c, const uint32_t* a, const uint32_t* b) {
    asm volatile(
        "mma.sync.aligned.m16n8k16.row.col.f32.bf16.bf16.f32 "
        "{%0,%1,%2,%3}, {%4,%5,%6,%7}, {%8,%9}, {%0,%1,%2,%3};"
        : "+f"(c[0]), "+f"(c[1]), "+f"(c[2]), "+f"(c[3])
        : "r"(a[0]), "r"(a[1]), "r"(a[2]), "r"(a[3]), "r"(b[0]), "r"(b[1]));
}

#define CP_ASYNC16(dst, src) \
    asm volatile("cp.async.cg.shared.global [%0], [%1], 16;" \
                 :: "r"(dst), "l"(src) : "memory")
#define CP_COMMIT() asm volatile("cp.async.commit_group;" ::: "memory")
#define CP_WAIT1()  asm volatile("cp.async.wait_group 1;" ::: "memory")
#define CP_WAIT0()  asm volatile("cp.async.wait_group 0;" ::: "memory")

// ---------------------------------------------------------------------------
// Split kernels: fp32 -> bf16 hi + bf16 lo
// ---------------------------------------------------------------------------
__global__ void __launch_bounds__(256) split_kernel(
    const float4* __restrict__ in, uint2* __restrict__ hi, uint2* __restrict__ lo, int n4)
{
    int i = blockIdx.x * 256 + threadIdx.x;
    if (i >= n4) return;
    float4 v = in[i];
    float vv[4] = {v.x, v.y, v.z, v.w};
    __nv_bfloat16 h[4], l[4];
#pragma unroll
    for (int j = 0; j < 4; ++j) {
        h[j] = __float2bfloat16(vv[j]);
        l[j] = __float2bfloat16(vv[j] - __bfloat162float(h[j]));
    }
    hi[i] = *(const uint2*)h;
    lo[i] = *(const uint2*)l;
}

__global__ void initfreq_kernel() {
    int i = threadIdx.x;   // 32 threads
    g_invfreq[i] = (float)exp(-(double)i * (9.210340371976184 / 32.0));
}

// ---------------------------------------------------------------------------
// GEMM mainloop (HMMA split precision): acc += Ah.Bh^T + Al.Bh^T + Ah.Bl^T
// CTA tile 128x128, 8 warps (wm=w>>1 in 0..3 -> 32 rows, wn=w&1 -> 64 cols).
// SMEM per stage: 4 tiles (Ah,Al,Bh,Bl), each 128 rows x 32 bf16, row stride
// 80B (LDSM conflict-free). Double-buffered cp.async pipeline, 64 K-chunks.
// ---------------------------------------------------------------------------
#define TILEB      (128 * 80)        // 10240 B per tile
#define STAGEB     (4 * TILEB)       // 40960 B per stage
#define GEMM_SMEM  (2 * STAGEB)      // 81920 B

__device__ __forceinline__ void issue_chunk(
    const __nv_bfloat16* __restrict__ Ah, const __nv_bfloat16* __restrict__ Al,
    const __nv_bfloat16* __restrict__ Bh, const __nv_bfloat16* __restrict__ Bl,
    uint32_t stage, int k0, int tid)
{
    const __nv_bfloat16* srcs[4] = {Ah, Al, Bh, Bl};
#pragma unroll
    for (int t = 0; t < 4; ++t) {
#pragma unroll
        for (int i = 0; i < 2; ++i) {
            int idx = tid + i * 256;            // 0..511
            int r = idx >> 2, cc = idx & 3;
            uint64_t src = __cvta_generic_to_global(srcs[t] + (size_t)r * DDIM + k0 + cc * 8);
            uint32_t dst = stage + t * TILEB + r * 80 + cc * 16;
            CP_ASYNC16(dst, src);
        }
    }
}

__device__ __forceinline__ void compute_stage(
    uint32_t stage, int wm, int wn, int lane, float acc[2][8][4])
{
    const uint32_t a_off = (uint32_t)((lane & 15) * 80 + (lane >> 4) * 16);
    const uint32_t b_row = (uint32_t)((lane & 7) + ((lane & 16) >> 1));
    const uint32_t b_off = b_row * 80 + ((lane >> 3) & 1) * 16;

#pragma unroll
    for (int s2 = 0; s2 < 2; ++s2) {
        const uint32_t kb = s2 * 32;

        uint32_t ah[2][4], al[2][4];
#pragma unroll
        for (int mt = 0; mt < 2; ++mt) {
            uint32_t base = stage + (uint32_t)(wm * 32 + mt * 16) * 80 + a_off + kb;
            ldsm4(ah[mt], base);
            ldsm4(al[mt], base + TILEB);
        }

        uint32_t bfr[8][2];
#pragma unroll
        for (int ng = 0; ng < 4; ++ng) {
            uint32_t base = stage + 2 * TILEB + (uint32_t)(wn * 64 + ng * 16) * 80 + b_off + kb;
            uint32_t t4[4];
            ldsm4(t4, base);                       // Bh
            bfr[ng * 2][0] = t4[0]; bfr[ng * 2][1] = t4[1];
            bfr[ng * 2 + 1][0] = t4[2]; bfr[ng * 2 + 1][1] = t4[3];
        }
#pragma unroll
        for (int mt = 0; mt < 2; ++mt)
#pragma unroll
            for (int nt = 0; nt < 8; ++nt) {
                mma16816(acc[mt][nt], ah[mt], bfr[nt]);   // Ah.Bh
                mma16816(acc[mt][nt], al[mt], bfr[nt]);   // Al.Bh
            }
#pragma unroll
        for (int ng = 0; ng < 4; ++ng) {
            uint32_t base = stage + 3 * TILEB + (uint32_t)(wn * 64 + ng * 16) * 80 + b_off + kb;
            uint32_t t4[4];
            ldsm4(t4, base);                       // Bl
            bfr[ng * 2][0] = t4[0]; bfr[ng * 2][1] = t4[1];
            bfr[ng * 2 + 1][0] = t4[2]; bfr[ng * 2 + 1][1] = t4[3];
        }
#pragma unroll
        for (int mt = 0; mt < 2; ++mt)
#pragma unroll
            for (int nt = 0; nt < 8; ++nt)
                mma16816(acc[mt][nt], ah[mt], bfr[nt]);   // Ah.Bl
    }
}

__device__ __forceinline__ void gemm_mainloop(
    const __nv_bfloat16* __restrict__ Ah, const __nv_bfloat16* __restrict__ Al,
    const __nv_bfloat16* __restrict__ Bh, const __nv_bfloat16* __restrict__ Bl,
    float acc[2][8][4])
{
    const uint32_t sb = smem_u32(smraw);
    const int tid = threadIdx.x;
    const int lane = tid & 31, w = tid >> 5;
    const int wm = w >> 1, wn = w & 1;

#pragma unroll
    for (int mt = 0; mt < 2; ++mt)
#pragma unroll
        for (int nt = 0; nt < 8; ++nt)
#pragma unroll
            for (int j = 0; j < 4; ++j) acc[mt][nt][j] = 0.f;

    issue_chunk(Ah, Al, Bh, Bl, sb, 0, tid);
    CP_COMMIT();

    for (int c = 0; c < 64; ++c) {
        uint32_t stage = sb + (uint32_t)(c & 1) * STAGEB;
        if (c + 1 < 64) {
            issue_chunk(Ah, Al, Bh, Bl, sb + (uint32_t)((c + 1) & 1) * STAGEB,
                        (c + 1) * 32, tid);
            CP_COMMIT();
            CP_WAIT1();
        } else {
            CP_WAIT0();
        }
        __syncthreads();
        compute_stage(stage, wm, wn, lane, acc);
        __syncthreads();
    }
}

// ---------------------------------------------------------------------------
// Kernel 1: q = RoPE(x @ Wq^T) -> g_q [B,H,T,DH]
// ---------------------------------------------------------------------------
__global__ void __launch_bounds__(256, 1) qgemm_rope_kernel()
{
    const int bn = blockIdx.x, bm = blockIdx.y;
    float acc[2][8][4];
    gemm_mainloop(g_x_hi + (size_t)bm * 128 * DDIM, g_x_lo + (size_t)bm * 128 * DDIM,
                  g_wq_hi + (size_t)bn * 128 * DDIM, g_wq_lo + (size_t)bn * 128 * DDIM,
                  acc);

    const int tid = threadIdx.x, lane = tid & 31, w = tid >> 5;
    const int wm = w >> 1, wn = w & 1;
    const int h = bn * 2 + wn;
    const int fc = lane & 3;

#pragma unroll
    for (int mt = 0; mt < 2; ++mt) {
        const int m0 = bm * 128 + wm * 32 + mt * 16 + (lane >> 2);
#pragma unroll
        for (int rh = 0; rh < 2; ++rh) {
            const int m = m0 + rh * 8;
            const int b = m >> 12, t = m & 4095;
            float* qrow = g_q + ((size_t)(b * NH + h) * TT + t) * DHD;
#pragma unroll
            for (int nt = 0; nt < 8; ++nt) {
                float e = acc[mt][nt][rh * 2 + 0];
                float o = acc[mt][nt][rh * 2 + 1];
                float ph = (float)t * g_invfreq[nt * 4 + fc];
                float sn, cn;
                sincosf(ph, &sn, &cn);
                float2 v = make_float2(e * cn - o * sn, e * sn + o * cn);
                *(float2*)(qrow + nt * 8 + fc * 2) = v;
            }
        }
    }
}

// ---------------------------------------------------------------------------
// Kernel 3: out = ao @ Wo^T -> d_out fp32
// ---------------------------------------------------------------------------
__global__ void __launch_bounds__(256, 1) ogemm_kernel(float* __restrict__ out)
{
    const int bn = blockIdx.x, bm = blockIdx.y;
    float acc[2][8][4];
    gemm_mainloop(g_ao_hi + (size_t)bm * 128 * DDIM, g_ao_lo + (size_t)bm * 128 * DDIM,
                  g_wo_hi + (size_t)bn * 128 * DDIM, g_wo_lo + (size_t)bn * 128 * DDIM,
                  acc);

    const int tid = threadIdx.x, lane = tid & 31, w = tid >> 5;
    const int wm = w >> 1, wn = w & 1;
    const int col = bn * 128 + wn * 64 + (lane & 3) * 2;

#pragma unroll
    for (int mt = 0; mt < 2; ++mt) {
        const int m0 = bm * 128 + wm * 32 + mt * 16 + (lane >> 2);
#pragma unroll
        for (int rh = 0; rh < 2; ++rh) {
            float* crow = out + (size_t)(m0 + rh * 8) * DDIM + col;
#pragma unroll
            for (int nt = 0; nt < 8; ++nt) {
                float2 v = make_float2(acc[mt][nt][rh * 2 + 0], acc[mt][nt][rh * 2 + 1]);
                *(float2*)(crow + nt * 8) = v;
            }
        }
    }
}

// ---------------------------------------------------------------------------
// Kernel 2: windowed causal attention, online softmax (SIMT fp32).
// Epilogue writes bf16 hi/lo split for the Wo GEMM.
// ---------------------------------------------------------------------------
#define PAD 68
#define ATTN_SMEM (4 * 64 * PAD * (int)sizeof(float))
__global__ void __launch_bounds__(256) attn_kernel(
    const float* __restrict__ kc, const float* __restrict__ vc)
{
    float* smf = (float*)smraw;
    float (*Qs)[PAD] = (float(*)[PAD])(smf);
    float (*Ks)[PAD] = (float(*)[PAD])(smf + 64 * PAD);       // [d][s]
    float (*Vs)[PAD] = (float(*)[PAD])(smf + 2 * 64 * PAD);   // [s][d]
    float (*Ps)[PAD] = (float(*)[PAD])(smf + 3 * 64 * PAD);   // [r][s]

    const int qt = blockIdx.x;
    const int bh = blockIdx.y;
    const int b  = bh >> 5, h = bh & 31;
    const int kv = h >> 2;
    const int tid = threadIdx.x;
    const int r  = tid >> 2, sg = tid & 3;

    {
        const float* qp = g_q + ((size_t)bh * TT + (size_t)qt * 64) * DHD;
        int rr = tid >> 4;
        int c4 = (tid & 15) << 2;
#pragma unroll
        for (int p = 0; p < 4; ++p) {
            int row = rr + p * 16;
            *(float4*)&Qs[row][c4] = *(const float4*)(qp + (size_t)row * DHD + c4);
        }
    }

    const float* kbase = kc + ((size_t)(b * NKV + kv) * TCC + WSTART) * DHD;
    const float* vbase = vc + ((size_t)(b * NKV + kv) * TCC + WSTART) * DHD;

    float mrow = -INFINITY, lrow = 0.f;
    float o[16];
#pragma unroll
    for (int i = 0; i < 16; i++) o[i] = 0.f;

    const int kbmax = (qt < 16) ? qt : 15;
    for (int kb = 0; kb <= kbmax; ++kb) {
        __syncthreads();
        {
            int rr = tid >> 4, c4 = (tid & 15) << 2;
#pragma unroll
            for (int p = 0; p < 4; ++p) {
                int s = rr + p * 16;
                float4 kvv = *(const float4*)(kbase + (size_t)(kb * 64 + s) * DHD + c4);
                Ks[c4 + 0][s] = kvv.x;
                Ks[c4 + 1][s] = kvv.y;
                Ks[c4 + 2][s] = kvv.z;
                Ks[c4 + 3][s] = kvv.w;
                *(float4*)&Vs[s][c4] = *(const float4*)(vbase + (size_t)(kb * 64 + s) * DHD + c4);
            }
        }
        __syncthreads();

        float sreg[16];
#pragma unroll
        for (int i = 0; i < 16; i++) sreg[i] = 0.f;
#pragma unroll 4
        for (int d = 0; d < 64; ++d) {
            float qv = Qs[r][d];
            float kvr[16];
            const float* kr = &Ks[d][sg * 16];
            *(float4*)&kvr[0]  = *(const float4*)(kr);
            *(float4*)&kvr[4]  = *(const float4*)(kr + 4);
            *(float4*)&kvr[8]  = *(const float4*)(kr + 8);
            *(float4*)&kvr[12] = *(const float4*)(kr + 12);
#pragma unroll
            for (int i = 0; i < 16; i++) sreg[i] = fmaf(qv, kvr[i], sreg[i]);
        }

        const bool diag = (qt < 16) && (kb == qt);
#pragma unroll
        for (int i = 0; i < 16; i++) {
            float sv = sreg[i] * SCALE;
            if (diag && (sg * 16 + i) > r) sv = -INFINITY;
            sreg[i] = sv;
        }

        float mb = sreg[0];
#pragma unroll
        for (int i = 1; i < 16; i++) mb = fmaxf(mb, sreg[i]);
        mb = fmaxf(mb, __shfl_xor_sync(0xffffffffu, mb, 1));
        mb = fmaxf(mb, __shfl_xor_sync(0xffffffffu, mb, 2));

        float mnew = fmaxf(mrow, mb);
        float corr = __expf(mrow - mnew);
        float lsum = 0.f;
#pragma unroll
        for (int i = 0; i < 16; i++) {
            float p = __expf(sreg[i] - mnew);
            sreg[i] = p;
            lsum += p;
        }
        lsum += __shfl_xor_sync(0xffffffffu, lsum, 1);
        lsum += __shfl_xor_sync(0xffffffffu, lsum, 2);
        lrow = lrow * corr + lsum;
        mrow = mnew;
#pragma unroll
        for (int i = 0; i < 16; i++) o[i] *= corr;

        *(float4*)&Ps[r][sg * 16]      = *(float4*)&sreg[0];
        *(float4*)&Ps[r][sg * 16 + 4]  = *(float4*)&sreg[4];
        *(float4*)&Ps[r][sg * 16 + 8]  = *(float4*)&sreg[8];
        *(float4*)&Ps[r][sg * 16 + 12] = *(float4*)&sreg[12];
        __syncthreads();

#pragma unroll 4
        for (int s = 0; s < 64; ++s) {
            float p = Ps[r][s];
            float vv[16];
            const float* vr = &Vs[s][sg * 16];
            *(float4*)&vv[0]  = *(const float4*)(vr);
            *(float4*)&vv[4]  = *(const float4*)(vr + 4);
            *(float4*)&vv[8]  = *(const float4*)(vr + 8);
            *(float4*)&vv[12] = *(const float4*)(vr + 12);
#pragma unroll
            for (int i = 0; i < 16; i++) o[i] = fmaf(p, vv[i], o[i]);
        }
    }

    // finalize: bf16 hi/lo split store for the Wo GEMM
    float invl = 1.f / lrow;
    __nv_bfloat16 hv[16], lv[16];
#pragma unroll
    for (int i = 0; i < 16; i++) {
        float v = o[i] * invl;
        __nv_bfloat16 hx = __float2bfloat16(v);
        hv[i] = hx;
        lv[i] = __float2bfloat16(v - __bfloat162float(hx));
    }
    size_t base = ((size_t)(b * TT + qt * 64 + r)) * DDIM + h * DHD + sg * 16;
    *(uint4*)(g_ao_hi + base)     = *(const uint4*)&hv[0];
    *(uint4*)(g_ao_hi + base + 8) = *(const uint4*)&hv[8];
    *(uint4*)(g_ao_lo + base)     = *(const uint4*)&lv[0];
    *(uint4*)(g_ao_lo + base + 8) = *(const uint4*)&lv[8];
}

// ---------------------------------------------------------------------------
extern "C" void kernel_launch(void* const* d_in, const int* in_sizes, int n_in,
                              void* d_out, int out_size)
{
    const float* x  = (const float*)d_in[0];
    const float* kc = (const float*)d_in[1];
    const float* vc = (const float*)d_in[2];
    const float* Wq = (const float*)d_in[3];
    const float* Wo = (const float*)d_in[4];
    float* out = (float*)d_out;
    (void)in_sizes; (void)n_in; (void)out_size;

    cudaFuncSetAttribute(attn_kernel, cudaFuncAttributeMaxDynamicSharedMemorySize, ATTN_SMEM);
    cudaFuncSetAttribute(qgemm_rope_kernel, cudaFuncAttributeMaxDynamicSharedMemorySize, GEMM_SMEM);
    cudaFuncSetAttribute(ogemm_kernel, cudaFuncAttributeMaxDynamicSharedMemorySize, GEMM_SMEM);

    // resolve device-global addresses for the split kernels
    __nv_bfloat16 *xh, *xl, *wqh, *wql, *woh, *wol;
    cudaGetSymbolAddress((void**)&xh,  g_x_hi);
    cudaGetSymbolAddress((void**)&xl,  g_x_lo);
    cudaGetSymbolAddress((void**)&wqh, g_wq_hi);
    cudaGetSymbolAddress((void**)&wql, g_wq_lo);
    cudaGetSymbolAddress((void**)&woh, g_wo_hi);
    cudaGetSymbolAddress((void**)&wol, g_wo_lo);

    initfreq_kernel<<<1, 32>>>();

    const int nx4 = (BB * TT * DDIM) / 4;
    const int nw4 = (DDIM * DDIM) / 4;
    split_kernel<<<nx4 / 256, 256>>>((const float4*)x,  (uint2*)xh,  (uint2*)xl,  nx4);
    split_kernel<<<nw4 / 256, 256>>>((const float4*)Wq, (uint2*)wqh, (uint2*)wql, nw4);
    split_kernel<<<nw4 / 256, 256>>>((const float4*)Wo, (uint2*)woh, (uint2*)wol, nw4);

    dim3 ggrid(DDIM / 128, (BB * TT) / 128);   // (16, 64)
    qgemm_rope_kernel<<<ggrid, 256, GEMM_SMEM>>>();

    dim3 agrid(TT / 64, BB * NH);              // (64, 64)
    attn_kernel<<<agrid, 256, ATTN_SMEM>>>(kc, vc);

    ogemm_kernel<<<ggrid, 256, GEMM_SMEM>>>(out);
}

// round 5
// speedup vs baseline: 1.2448x; 1.0002x over previous
#include <cuda_runtime.h>
#include <cuda_bf16.h>
#include <math.h>
#include <stdint.h>

// Problem constants
#define BB    2
#define TT    4096
#define DDIM  2048
#define NH    32
#define NKV   8
#define DHD   64
#define TCC   4096
#define WIN   1024
#define WSTART 3072
#define SCALE 0.125f

// ---------------------------------------------------------------------------
// Scratch (device globals — allocation-free rule)
// ---------------------------------------------------------------------------
__device__ float         g_q    [(size_t)BB * NH * TT * DHD];    // RoPE'd q [B,H,T,DH]
__device__ __nv_bfloat16 g_x_hi [(size_t)BB * TT * DDIM];
__device__ __nv_bfloat16 g_x_lo [(size_t)BB * TT * DDIM];
__device__ __nv_bfloat16 g_wq_hi[(size_t)DDIM * DDIM];
__device__ __nv_bfloat16 g_wq_lo[(size_t)DDIM * DDIM];
__device__ __nv_bfloat16 g_wo_hi[(size_t)DDIM * DDIM];
__device__ __nv_bfloat16 g_wo_lo[(size_t)DDIM * DDIM];
__device__ __nv_bfloat16 g_ao_hi[(size_t)BB * TT * DDIM];
__device__ __nv_bfloat16 g_ao_lo[(size_t)BB * TT * DDIM];
__device__ float         g_invfreq[32];

extern __shared__ char smraw[];

// ---------------------------------------------------------------------------
// Helpers (baseline PTX only: ldmatrix / mma.sync / cp.async — all sm_80+)
// ---------------------------------------------------------------------------
__device__ __forceinline__ uint32_t smem_u32(const void* p) {
    uint32_t a;
    asm("{ .reg .u64 t; cvta.to.shared.u64 t, %1; cvt.u32.u64 %0, t; }"
        : "=r"(a) : "l"(p));
    return a;
}

__device__ __forceinline__ void ldsm4(uint32_t* r, uint32_t addr) {
    asm volatile("ldmatrix.sync.aligned.m8n8.x4.shared.b16 {%0,%1,%2,%3}, [%4];"
        : "=r"(r[0]), "=r"(r[1]), "=r"(r[2]), "=r"(r[3]) : "r"(addr));
}

// NOTE: no volatile — let the compiler/ptxas interleave independent MMAs.
__device__ __forceinline__ void mma16816(float* c, const uint32_t* a, const uint32_t* b) {
    asm("mma.sync.aligned.m16n8k16.row.col.f32.bf16.bf16.f32 "
        "{%0,%1,%2,%3}, {%4,%5,%6,%7}, {%8,%9}, {%0,%1,%2,%3};"
        : "+f"(c[0]), "+f"(c[1]), "+f"(c[2]), "+f"(c[3])
        : "r"(a[0]), "r"(a[1]), "r"(a[2]), "r"(a[3]), "r"(b[0]), "r"(b[1]));
}

#define CP_ASYNC16(dst, src) \
    asm volatile("cp.async.cg.shared.global [%0], [%1], 16;" \
                 :: "r"(dst), "l"(src) : "memory")
#define CP_COMMIT() asm volatile("cp.async.commit_group;" ::: "memory")
#define CP_WAIT1()  asm volatile("cp.async.wait_group 1;" ::: "memory")
#define CP_WAIT0()  asm volatile("cp.async.wait_group 0;" ::: "memory")

// ---------------------------------------------------------------------------
// Split kernels: fp32 -> bf16 hi + bf16 lo
// ---------------------------------------------------------------------------
__global__ void __launch_bounds__(256) split_kernel(
    const float4* __restrict__ in, uint2* __restrict__ hi, uint2* __restrict__ lo, int n4)
{
    int i = blockIdx.x * 256 + threadIdx.x;
    if (i >= n4) return;
    float4 v = in[i];
    float vv[4] = {v.x, v.y, v.z, v.w};
    __nv_bfloat16 h[4], l[4];
#pragma unroll
    for (int j = 0; j < 4; ++j) {
        h[j] = __float2bfloat16(vv[j]);
        l[j] = __float2bfloat16(vv[j] - __bfloat162float(h[j]));
    }
    hi[i] = *(const uint2*)h;
    lo[i] = *(const uint2*)l;
}

__global__ void initfreq_kernel() {
    int i = threadIdx.x;   // 32 threads
    g_invfreq[i] = (float)exp(-(double)i * (9.210340371976184 / 32.0));
}

// ---------------------------------------------------------------------------
// GEMM mainloop (HMMA split precision): acc += Ah.Bh^T + Al.Bh^T + Ah.Bl^T
// CTA tile 128x128, 8 warps (wm=w>>1 -> 32 rows, wn=w&1 -> 64 cols).
// SMEM per stage: 4 tiles (Ah,Al,Bh,Bl), each 128 rows x 32 bf16, row stride
// 80B (LDSM conflict-free). 3-stage cp.async pipeline, one sync per chunk.
// MMAs grouped into passes of 16 independent instructions (RAW distance 16).
// ---------------------------------------------------------------------------
#define TILEB      (128 * 80)        // 10240 B per tile
#define STAGEB     (4 * TILEB)       // 40960 B per stage
#define NSTAGE     3
#define GEMM_SMEM  (NSTAGE * STAGEB) // 122880 B

__device__ __forceinline__ void issue_chunk(
    const __nv_bfloat16* __restrict__ Ah, const __nv_bfloat16* __restrict__ Al,
    const __nv_bfloat16* __restrict__ Bh, const __nv_bfloat16* __restrict__ Bl,
    uint32_t stage, int k0, int tid)
{
    const __nv_bfloat16* srcs[4] = {Ah, Al, Bh, Bl};
#pragma unroll
    for (int t = 0; t < 4; ++t) {
#pragma unroll
        for (int i = 0; i < 2; ++i) {
            int idx = tid + i * 256;            // 0..511
            int r = idx >> 2, cc = idx & 3;
            uint64_t src = __cvta_generic_to_global(srcs[t] + (size_t)r * DDIM + k0 + cc * 8);
            uint32_t dst = stage + t * TILEB + r * 80 + cc * 16;
            CP_ASYNC16(dst, src);
        }
    }
}

__device__ __forceinline__ void compute_stage(
    uint32_t stage, int wm, int wn, int lane, float acc[2][8][4])
{
    const uint32_t a_off = (uint32_t)((lane & 15) * 80 + (lane >> 4) * 16);
    const uint32_t b_row = (uint32_t)((lane & 7) + ((lane & 16) >> 1));
    const uint32_t b_off = b_row * 80 + ((lane >> 3) & 1) * 16;

#pragma unroll
    for (int s2 = 0; s2 < 2; ++s2) {
        const uint32_t kb = s2 * 32;

        uint32_t ah[2][4], al[2][4];
#pragma unroll
        for (int mt = 0; mt < 2; ++mt) {
            uint32_t base = stage + (uint32_t)(wm * 32 + mt * 16) * 80 + a_off + kb;
            ldsm4(ah[mt], base);
            ldsm4(al[mt], base + TILEB);
        }

        uint32_t bfr[8][2];
#pragma unroll
        for (int ng = 0; ng < 4; ++ng) {
            uint32_t base = stage + 2 * TILEB + (uint32_t)(wn * 64 + ng * 16) * 80 + b_off + kb;
            uint32_t t4[4];
            ldsm4(t4, base);                       // Bh
            bfr[ng * 2][0] = t4[0]; bfr[ng * 2][1] = t4[1];
            bfr[ng * 2 + 1][0] = t4[2]; bfr[ng * 2 + 1][1] = t4[3];
        }
        // pass 1: Ah.Bh — 16 independent MMAs
#pragma unroll
        for (int mt = 0; mt < 2; ++mt)
#pragma unroll
            for (int nt = 0; nt < 8; ++nt)
                mma16816(acc[mt][nt], ah[mt], bfr[nt]);
        // pass 2: Al.Bh — 16 independent MMAs
#pragma unroll
        for (int mt = 0; mt < 2; ++mt)
#pragma unroll
            for (int nt = 0; nt < 8; ++nt)
                mma16816(acc[mt][nt], al[mt], bfr[nt]);

#pragma unroll
        for (int ng = 0; ng < 4; ++ng) {
            uint32_t base = stage + 3 * TILEB + (uint32_t)(wn * 64 + ng * 16) * 80 + b_off + kb;
            uint32_t t4[4];
            ldsm4(t4, base);                       // Bl
            bfr[ng * 2][0] = t4[0]; bfr[ng * 2][1] = t4[1];
            bfr[ng * 2 + 1][0] = t4[2]; bfr[ng * 2 + 1][1] = t4[3];
        }
        // pass 3: Ah.Bl — 16 independent MMAs
#pragma unroll
        for (int mt = 0; mt < 2; ++mt)
#pragma unroll
            for (int nt = 0; nt < 8; ++nt)
                mma16816(acc[mt][nt], ah[mt], bfr[nt]);
    }
}

__device__ __forceinline__ void gemm_mainloop(
    const __nv_bfloat16* __restrict__ Ah, const __nv_bfloat16* __restrict__ Al,
    const __nv_bfloat16* __restrict__ Bh, const __nv_bfloat16* __restrict__ Bl,
    float acc[2][8][4])
{
    const uint32_t sb = smem_u32(smraw);
    const int tid = threadIdx.x;
    const int lane = tid & 31, w = tid >> 5;
    const int wm = w >> 1, wn = w & 1;

#pragma unroll
    for (int mt = 0; mt < 2; ++mt)
#pragma unroll
        for (int nt = 0; nt < 8; ++nt)
#pragma unroll
            for (int j = 0; j < 4; ++j) acc[mt][nt][j] = 0.f;

    // prime 2 chunks
    issue_chunk(Ah, Al, Bh, Bl, sb + 0 * STAGEB, 0,  tid);
    CP_COMMIT();
    issue_chunk(Ah, Al, Bh, Bl, sb + 1 * STAGEB, 32, tid);
    CP_COMMIT();

    for (int c = 0; c < 64; ++c) {
        if (c + 2 < 64) CP_WAIT1(); else CP_WAIT0();
        __syncthreads();   // all warps done with stage (c-1)%3, stage c%3 data ready
        if (c + 2 < 64) {
            issue_chunk(Ah, Al, Bh, Bl, sb + (uint32_t)((c + 2) % NSTAGE) * STAGEB,
                        (c + 2) * 32, tid);
            CP_COMMIT();
        }
        compute_stage(sb + (uint32_t)(c % NSTAGE) * STAGEB, wm, wn, lane, acc);
    }
}

// ---------------------------------------------------------------------------
// Kernel 1: q = RoPE(x @ Wq^T) -> g_q [B,H,T,DH]
// ---------------------------------------------------------------------------
__global__ void __launch_bounds__(256, 1) qgemm_rope_kernel()
{
    const int bn = blockIdx.x, bm = blockIdx.y;
    float acc[2][8][4];
    gemm_mainloop(g_x_hi + (size_t)bm * 128 * DDIM, g_x_lo + (size_t)bm * 128 * DDIM,
                  g_wq_hi + (size_t)bn * 128 * DDIM, g_wq_lo + (size_t)bn * 128 * DDIM,
                  acc);

    const int tid = threadIdx.x, lane = tid & 31, w = tid >> 5;
    const int wm = w >> 1, wn = w & 1;
    const int h = bn * 2 + wn;
    const int fc = lane & 3;

#pragma unroll
    for (int mt = 0; mt < 2; ++mt) {
        const int m0 = bm * 128 + wm * 32 + mt * 16 + (lane >> 2);
#pragma unroll
        for (int rh = 0; rh < 2; ++rh) {
            const int m = m0 + rh * 8;
            const int b = m >> 12, t = m & 4095;
            float* qrow = g_q + ((size_t)(b * NH + h) * TT + t) * DHD;
#pragma unroll
            for (int nt = 0; nt < 8; ++nt) {
                float e = acc[mt][nt][rh * 2 + 0];
                float o = acc[mt][nt][rh * 2 + 1];
                float ph = (float)t * g_invfreq[nt * 4 + fc];
                float sn, cn;
                sincosf(ph, &sn, &cn);
                float2 v = make_float2(e * cn - o * sn, e * sn + o * cn);
                *(float2*)(qrow + nt * 8 + fc * 2) = v;
            }
        }
    }
}

// ---------------------------------------------------------------------------
// Kernel 3: out = ao @ Wo^T -> d_out fp32
// ---------------------------------------------------------------------------
__global__ void __launch_bounds__(256, 1) ogemm_kernel(float* __restrict__ out)
{
    const int bn = blockIdx.x, bm = blockIdx.y;
    float acc[2][8][4];
    gemm_mainloop(g_ao_hi + (size_t)bm * 128 * DDIM, g_ao_lo + (size_t)bm * 128 * DDIM,
                  g_wo_hi + (size_t)bn * 128 * DDIM, g_wo_lo + (size_t)bn * 128 * DDIM,
                  acc);

    const int tid = threadIdx.x, lane = tid & 31, w = tid >> 5;
    const int wm = w >> 1, wn = w & 1;
    const int col = bn * 128 + wn * 64 + (lane & 3) * 2;

#pragma unroll
    for (int mt = 0; mt < 2; ++mt) {
        const int m0 = bm * 128 + wm * 32 + mt * 16 + (lane >> 2);
#pragma unroll
        for (int rh = 0; rh < 2; ++rh) {
            float* crow = out + (size_t)(m0 + rh * 8) * DDIM + col;
#pragma unroll
            for (int nt = 0; nt < 8; ++nt) {
                float2 v = make_float2(acc[mt][nt][rh * 2 + 0], acc[mt][nt][rh * 2 + 1]);
                *(float2*)(crow + nt * 8) = v;
            }
        }
    }
}

// ---------------------------------------------------------------------------
// Kernel 2: windowed causal attention, online softmax (SIMT fp32).
// Epilogue writes bf16 hi/lo split for the Wo GEMM.
// ---------------------------------------------------------------------------
#define PAD 68
#define ATTN_SMEM (4 * 64 * PAD * (int)sizeof(float))
__global__ void __launch_bounds__(256) attn_kernel(
    const float* __restrict__ kc, const float* __restrict__ vc)
{
    float* smf = (float*)smraw;
    float (*Qs)[PAD] = (float(*)[PAD])(smf);
    float (*Ks)[PAD] = (float(*)[PAD])(smf + 64 * PAD);       // [d][s]
    float (*Vs)[PAD] = (float(*)[PAD])(smf + 2 * 64 * PAD);   // [s][d]
    float (*Ps)[PAD] = (float(*)[PAD])(smf + 3 * 64 * PAD);   // [r][s]

    const int qt = blockIdx.x;
    const int bh = blockIdx.y;
    const int b  = bh >> 5, h = bh & 31;
    const int kv = h >> 2;
    const int tid = threadIdx.x;
    const int r  = tid >> 2, sg = tid & 3;

    {
        const float* qp = g_q + ((size_t)bh * TT + (size_t)qt * 64) * DHD;
        int rr = tid >> 4;
        int c4 = (tid & 15) << 2;
#pragma unroll
        for (int p = 0; p < 4; ++p) {
            int row = rr + p * 16;
            *(float4*)&Qs[row][c4] = *(const float4*)(qp + (size_t)row * DHD + c4);
        }
    }

    const float* kbase = kc + ((size_t)(b * NKV + kv) * TCC + WSTART) * DHD;
    const float* vbase = vc + ((size_t)(b * NKV + kv) * TCC + WSTART) * DHD;

    float mrow = -INFINITY, lrow = 0.f;
    float o[16];
#pragma unroll
    for (int i = 0; i < 16; i++) o[i] = 0.f;

    const int kbmax = (qt < 16) ? qt : 15;
    for (int kb = 0; kb <= kbmax; ++kb) {
        __syncthreads();
        {
            int rr = tid >> 4, c4 = (tid & 15) << 2;
#pragma unroll
            for (int p = 0; p < 4; ++p) {
                int s = rr + p * 16;
                float4 kvv = *(const float4*)(kbase + (size_t)(kb * 64 + s) * DHD + c4);
                Ks[c4 + 0][s] = kvv.x;
                Ks[c4 + 1][s] = kvv.y;
                Ks[c4 + 2][s] = kvv.z;
                Ks[c4 + 3][s] = kvv.w;
                *(float4*)&Vs[s][c4] = *(const float4*)(vbase + (size_t)(kb * 64 + s) * DHD + c4);
            }
        }
        __syncthreads();

        float sreg[16];
#pragma unroll
        for (int i = 0; i < 16; i++) sreg[i] = 0.f;
#pragma unroll 4
        for (int d = 0; d < 64; ++d) {
            float qv = Qs[r][d];
            float kvr[16];
            const float* kr = &Ks[d][sg * 16];
            *(float4*)&kvr[0]  = *(const float4*)(kr);
            *(float4*)&kvr[4]  = *(const float4*)(kr + 4);
            *(float4*)&kvr[8]  = *(const float4*)(kr + 8);
            *(float4*)&kvr[12] = *(const float4*)(kr + 12);
#pragma unroll
            for (int i = 0; i < 16; i++) sreg[i] = fmaf(qv, kvr[i], sreg[i]);
        }

        const bool diag = (qt < 16) && (kb == qt);
#pragma unroll
        for (int i = 0; i < 16; i++) {
            float sv = sreg[i] * SCALE;
            if (diag && (sg * 16 + i) > r) sv = -INFINITY;
            sreg[i] = sv;
        }

        float mb = sreg[0];
#pragma unroll
        for (int i = 1; i < 16; i++) mb = fmaxf(mb, sreg[i]);
        mb = fmaxf(mb, __shfl_xor_sync(0xffffffffu, mb, 1));
        mb = fmaxf(mb, __shfl_xor_sync(0xffffffffu, mb, 2));

        float mnew = fmaxf(mrow, mb);
        float corr = __expf(mrow - mnew);
        float lsum = 0.f;
#pragma unroll
        for (int i = 0; i < 16; i++) {
            float p = __expf(sreg[i] - mnew);
            sreg[i] = p;
            lsum += p;
        }
        lsum += __shfl_xor_sync(0xffffffffu, lsum, 1);
        lsum += __shfl_xor_sync(0xffffffffu, lsum, 2);
        lrow = lrow * corr + lsum;
        mrow = mnew;
#pragma unroll
        for (int i = 0; i < 16; i++) o[i] *= corr;

        *(float4*)&Ps[r][sg * 16]      = *(float4*)&sreg[0];
        *(float4*)&Ps[r][sg * 16 + 4]  = *(float4*)&sreg[4];
        *(float4*)&Ps[r][sg * 16 + 8]  = *(float4*)&sreg[8];
        *(float4*)&Ps[r][sg * 16 + 12] = *(float4*)&sreg[12];
        __syncthreads();

#pragma unroll 4
        for (int s = 0; s < 64; ++s) {
            float p = Ps[r][s];
            float vv[16];
            const float* vr = &Vs[s][sg * 16];
            *(float4*)&vv[0]  = *(const float4*)(vr);
            *(float4*)&vv[4]  = *(const float4*)(vr + 4);
            *(float4*)&vv[8]  = *(const float4*)(vr + 8);
            *(float4*)&vv[12] = *(const float4*)(vr + 12);
#pragma unroll
            for (int i = 0; i < 16; i++) o[i] = fmaf(p, vv[i], o[i]);
        }
    }

    // finalize: bf16 hi/lo split store for the Wo GEMM
    float invl = 1.f / lrow;
    __nv_bfloat16 hv[16], lv[16];
#pragma unroll
    for (int i = 0; i < 16; i++) {
        float v = o[i] * invl;
        __nv_bfloat16 hx = __float2bfloat16(v);
        hv[i] = hx;
        lv[i] = __float2bfloat16(v - __bfloat162float(hx));
    }
    size_t base = ((size_t)(b * TT + qt * 64 + r)) * DDIM + h * DHD + sg * 16;
    *(uint4*)(g_ao_hi + base)     = *(const uint4*)&hv[0];
    *(uint4*)(g_ao_hi + base + 8) = *(const uint4*)&hv[8];
    *(uint4*)(g_ao_lo + base)     = *(const uint4*)&lv[0];
    *(uint4*)(g_ao_lo + base + 8) = *(const uint4*)&lv[8];
}

// ---------------------------------------------------------------------------
extern "C" void kernel_launch(void* const* d_in, const int* in_sizes, int n_in,
                              void* d_out, int out_size)
{
    const float* x  = (const float*)d_in[0];
    const float* kc = (const float*)d_in[1];
    const float* vc = (const float*)d_in[2];
    const float* Wq = (const float*)d_in[3];
    const float* Wo = (const float*)d_in[4];
    float* out = (float*)d_out;
    (void)in_sizes; (void)n_in; (void)out_size;

    cudaFuncSetAttribute(attn_kernel, cudaFuncAttributeMaxDynamicSharedMemorySize, ATTN_SMEM);
    cudaFuncSetAttribute(qgemm_rope_kernel, cudaFuncAttributeMaxDynamicSharedMemorySize, GEMM_SMEM);
    cudaFuncSetAttribute(ogemm_kernel, cudaFuncAttributeMaxDynamicSharedMemorySize, GEMM_SMEM);

    // resolve device-global addresses for the split kernels
    __nv_bfloat16 *xh, *xl, *wqh, *wql, *woh, *wol;
    cudaGetSymbolAddress((void**)&xh,  g_x_hi);
    cudaGetSymbolAddress((void**)&xl,  g_x_lo);
    cudaGetSymbolAddress((void**)&wqh, g_wq_hi);
    cudaGetSymbolAddress((void**)&wql, g_wq_lo);
    cudaGetSymbolAddress((void**)&woh, g_wo_hi);
    cudaGetSymbolAddress((void**)&wol, g_wo_lo);

    initfreq_kernel<<<1, 32>>>();

    const int nx4 = (BB * TT * DDIM) / 4;
    const int nw4 = (DDIM * DDIM) / 4;
    split_kernel<<<nx4 / 256, 256>>>((const float4*)x,  (uint2*)xh,  (uint2*)xl,  nx4);
    split_kernel<<<nw4 / 256, 256>>>((const float4*)Wq, (uint2*)wqh, (uint2*)wql, nw4);
    split_kernel<<<nw4 / 256, 256>>>((const float4*)Wo, (uint2*)woh, (uint2*)wol, nw4);

    dim3 ggrid(DDIM / 128, (BB * TT) / 128);   // (16, 64)
    qgemm_rope_kernel<<<ggrid, 256, GEMM_SMEM>>>();

    dim3 agrid(TT / 64, BB * NH);              // (64, 64)
    attn_kernel<<<agrid, 256, ATTN_SMEM>>>(kc, vc);

    ogemm_kernel<<<ggrid, 256, GEMM_SMEM>>>(out);
}

// round 6
// speedup vs baseline: 5.5134x; 4.4293x over previous
#include <cuda_runtime.h>
#include <cuda_bf16.h>
#include <math.h>
#include <stdint.h>

// Problem constants
#define BB    2
#define TT    4096
#define DDIM  2048
#define NH    32
#define NKV   8
#define DHD   64
#define TCC   4096
#define WIN   1024
#define WSTART 3072
#define SCALE 0.125f

// ---------------------------------------------------------------------------
// Scratch (device globals — allocation-free rule)
// ---------------------------------------------------------------------------
__device__ __nv_bfloat16 g_q_hi [(size_t)BB * NH * TT * DHD];  // RoPE'd, pre-scaled
__device__ __nv_bfloat16 g_q_lo [(size_t)BB * NH * TT * DHD];
__device__ __nv_bfloat16 g_k_hi [(size_t)BB * NKV * WIN * DHD];
__device__ __nv_bfloat16 g_k_lo [(size_t)BB * NKV * WIN * DHD];
__device__ __nv_bfloat16 g_v_hi [(size_t)BB * NKV * WIN * DHD];
__device__ __nv_bfloat16 g_v_lo [(size_t)BB * NKV * WIN * DHD];
__device__ __nv_bfloat16 g_x_hi [(size_t)BB * TT * DDIM];
__device__ __nv_bfloat16 g_x_lo [(size_t)BB * TT * DDIM];
__device__ __nv_bfloat16 g_wq_hi[(size_t)DDIM * DDIM];
__device__ __nv_bfloat16 g_wq_lo[(size_t)DDIM * DDIM];
__device__ __nv_bfloat16 g_wo_hi[(size_t)DDIM * DDIM];
__device__ __nv_bfloat16 g_wo_lo[(size_t)DDIM * DDIM];
__device__ __nv_bfloat16 g_ao_hi[(size_t)BB * TT * DDIM];
__device__ __nv_bfloat16 g_ao_lo[(size_t)BB * TT * DDIM];
__device__ float         g_invfreq[32];

extern __shared__ char smraw[];

// ---------------------------------------------------------------------------
// Helpers (baseline PTX only: ldmatrix / mma.sync / cp.async — all sm_80+)
// ---------------------------------------------------------------------------
__device__ __forceinline__ uint32_t smem_u32(const void* p) {
    uint32_t a;
    asm("{ .reg .u64 t; cvta.to.shared.u64 t, %1; cvt.u32.u64 %0, t; }"
        : "=r"(a) : "l"(p));
    return a;
}

__device__ __forceinline__ void ldsm4(uint32_t* r, uint32_t addr) {
    asm volatile("ldmatrix.sync.aligned.m8n8.x4.shared.b16 {%0,%1,%2,%3}, [%4];"
        : "=r"(r[0]), "=r"(r[1]), "=r"(r[2]), "=r"(r[3]) : "r"(addr));
}

__device__ __forceinline__ void ldsm4t(uint32_t* r, uint32_t addr) {
    asm volatile("ldmatrix.sync.aligned.m8n8.x4.trans.shared.b16 {%0,%1,%2,%3}, [%4];"
        : "=r"(r[0]), "=r"(r[1]), "=r"(r[2]), "=r"(r[3]) : "r"(addr));
}

__device__ __forceinline__ void mma16816(float* c, const uint32_t* a, const uint32_t* b) {
    asm("mma.sync.aligned.m16n8k16.row.col.f32.bf16.bf16.f32 "
        "{%0,%1,%2,%3}, {%4,%5,%6,%7}, {%8,%9}, {%0,%1,%2,%3};"
        : "+f"(c[0]), "+f"(c[1]), "+f"(c[2]), "+f"(c[3])
        : "r"(a[0]), "r"(a[1]), "r"(a[2]), "r"(a[3]), "r"(b[0]), "r"(b[1]));
}

#define CP_ASYNC16(dst, src) \
    asm volatile("cp.async.cg.shared.global [%0], [%1], 16;" \
                 :: "r"(dst), "l"(src) : "memory")
#define CP_COMMIT() asm volatile("cp.async.commit_group;" ::: "memory")
#define CP_WAIT1()  asm volatile("cp.async.wait_group 1;" ::: "memory")
#define CP_WAIT0()  asm volatile("cp.async.wait_group 0;" ::: "memory")

// split a pair of floats into bf16-hi pair and bf16-lo (residual) pair
__device__ __forceinline__ void split2(float a, float b, uint32_t& hi, uint32_t& lo) {
    __nv_bfloat16 ha = __float2bfloat16(a), hb = __float2bfloat16(b);
    __nv_bfloat162 hh = __halves2bfloat162(ha, hb);
    hi = *reinterpret_cast<uint32_t*>(&hh);
    __nv_bfloat16 la = __float2bfloat16(a - __bfloat162float(ha));
    __nv_bfloat16 lb = __float2bfloat16(b - __bfloat162float(hb));
    __nv_bfloat162 ll = __halves2bfloat162(la, lb);
    lo = *reinterpret_cast<uint32_t*>(&ll);
}

// ---------------------------------------------------------------------------
// Prep kernels
// ---------------------------------------------------------------------------
__global__ void __launch_bounds__(256) split_kernel(
    const float4* __restrict__ in, uint2* __restrict__ hi, uint2* __restrict__ lo, int n4)
{
    int i = blockIdx.x * 256 + threadIdx.x;
    if (i >= n4) return;
    float4 v = in[i];
    float vv[4] = {v.x, v.y, v.z, v.w};
    __nv_bfloat16 h[4], l[4];
#pragma unroll
    for (int j = 0; j < 4; ++j) {
        h[j] = __float2bfloat16(vv[j]);
        l[j] = __float2bfloat16(vv[j] - __bfloat162float(h[j]));
    }
    hi[i] = *(const uint2*)h;
    lo[i] = *(const uint2*)l;
}

// K/V window (last 1024 positions) -> bf16 hi/lo, layout [b][kv][1024][64]
__global__ void __launch_bounds__(256) kvsplit_kernel(
    const float4* __restrict__ kc, const float4* __restrict__ vc)
{
    int idx = blockIdx.x * 256 + threadIdx.x;          // 0..262143
    int within = idx & ((WIN * DHD / 4) - 1);          // 16383
    int bk = idx >> 14;                                // 0..15
    size_t src = (size_t)bk * (TCC * DHD / 4) + (WSTART * DHD / 4) + within;
    float4 k4 = kc[src];
    float4 v4 = vc[src];
    float kv_[4] = {k4.x, k4.y, k4.z, k4.w};
    float vv_[4] = {v4.x, v4.y, v4.z, v4.w};
    __nv_bfloat16 kh[4], kl[4], vh[4], vl[4];
#pragma unroll
    for (int j = 0; j < 4; ++j) {
        kh[j] = __float2bfloat16(kv_[j]);
        kl[j] = __float2bfloat16(kv_[j] - __bfloat162float(kh[j]));
        vh[j] = __float2bfloat16(vv_[j]);
        vl[j] = __float2bfloat16(vv_[j] - __bfloat162float(vh[j]));
    }
    ((uint2*)g_k_hi)[idx] = *(const uint2*)kh;
    ((uint2*)g_k_lo)[idx] = *(const uint2*)kl;
    ((uint2*)g_v_hi)[idx] = *(const uint2*)vh;
    ((uint2*)g_v_lo)[idx] = *(const uint2*)vl;
}

__global__ void initfreq_kernel() {
    int i = threadIdx.x;   // 32 threads
    g_invfreq[i] = (float)exp(-(double)i * (9.210340371976184 / 32.0));
}

// ---------------------------------------------------------------------------
// GEMM mainloop (unchanged from round 5)
// ---------------------------------------------------------------------------
#define TILEB      (128 * 80)
#define STAGEB     (4 * TILEB)
#define NSTAGE     3
#define GEMM_SMEM  (NSTAGE * STAGEB)

__device__ __forceinline__ void issue_chunk(
    const __nv_bfloat16* __restrict__ Ah, const __nv_bfloat16* __restrict__ Al,
    const __nv_bfloat16* __restrict__ Bh, const __nv_bfloat16* __restrict__ Bl,
    uint32_t stage, int k0, int tid)
{
    const __nv_bfloat16* srcs[4] = {Ah, Al, Bh, Bl};
#pragma unroll
    for (int t = 0; t < 4; ++t) {
#pragma unroll
        for (int i = 0; i < 2; ++i) {
            int idx = tid + i * 256;
            int r = idx >> 2, cc = idx & 3;
            uint64_t src = __cvta_generic_to_global(srcs[t] + (size_t)r * DDIM + k0 + cc * 8);
            uint32_t dst = stage + t * TILEB + r * 80 + cc * 16;
            CP_ASYNC16(dst, src);
        }
    }
}

__device__ __forceinline__ void compute_stage(
    uint32_t stage, int wm, int wn, int lane, float acc[2][8][4])
{
    const uint32_t a_off = (uint32_t)((lane & 15) * 80 + (lane >> 4) * 16);
    const uint32_t b_row = (uint32_t)((lane & 7) + ((lane & 16) >> 1));
    const uint32_t b_off = b_row * 80 + ((lane >> 3) & 1) * 16;

#pragma unroll
    for (int s2 = 0; s2 < 2; ++s2) {
        const uint32_t kb = s2 * 32;

        uint32_t ah[2][4], al[2][4];
#pragma unroll
        for (int mt = 0; mt < 2; ++mt) {
            uint32_t base = stage + (uint32_t)(wm * 32 + mt * 16) * 80 + a_off + kb;
            ldsm4(ah[mt], base);
            ldsm4(al[mt], base + TILEB);
        }

        uint32_t bfr[8][2];
#pragma unroll
        for (int ng = 0; ng < 4; ++ng) {
            uint32_t base = stage + 2 * TILEB + (uint32_t)(wn * 64 + ng * 16) * 80 + b_off + kb;
            uint32_t t4[4];
            ldsm4(t4, base);
            bfr[ng * 2][0] = t4[0]; bfr[ng * 2][1] = t4[1];
            bfr[ng * 2 + 1][0] = t4[2]; bfr[ng * 2 + 1][1] = t4[3];
        }
#pragma unroll
        for (int mt = 0; mt < 2; ++mt)
#pragma unroll
            for (int nt = 0; nt < 8; ++nt)
                mma16816(acc[mt][nt], ah[mt], bfr[nt]);
#pragma unroll
        for (int mt = 0; mt < 2; ++mt)
#pragma unroll
            for (int nt = 0; nt < 8; ++nt)
                mma16816(acc[mt][nt], al[mt], bfr[nt]);

#pragma unroll
        for (int ng = 0; ng < 4; ++ng) {
            uint32_t base = stage + 3 * TILEB + (uint32_t)(wn * 64 + ng * 16) * 80 + b_off + kb;
            uint32_t t4[4];
            ldsm4(t4, base);
            bfr[ng * 2][0] = t4[0]; bfr[ng * 2][1] = t4[1];
            bfr[ng * 2 + 1][0] = t4[2]; bfr[ng * 2 + 1][1] = t4[3];
        }
#pragma unroll
        for (int mt = 0; mt < 2; ++mt)
#pragma unroll
            for (int nt = 0; nt < 8; ++nt)
                mma16816(acc[mt][nt], ah[mt], bfr[nt]);
    }
}

__device__ __forceinline__ void gemm_mainloop(
    const __nv_bfloat16* __restrict__ Ah, const __nv_bfloat16* __restrict__ Al,
    const __nv_bfloat16* __restrict__ Bh, const __nv_bfloat16* __restrict__ Bl,
    float acc[2][8][4])
{
    const uint32_t sb = smem_u32(smraw);
    const int tid = threadIdx.x;
    const int lane = tid & 31, w = tid >> 5;
    const int wm = w >> 1, wn = w & 1;

#pragma unroll
    for (int mt = 0; mt < 2; ++mt)
#pragma unroll
        for (int nt = 0; nt < 8; ++nt)
#pragma unroll
            for (int j = 0; j < 4; ++j) acc[mt][nt][j] = 0.f;

    issue_chunk(Ah, Al, Bh, Bl, sb + 0 * STAGEB, 0,  tid);
    CP_COMMIT();
    issue_chunk(Ah, Al, Bh, Bl, sb + 1 * STAGEB, 32, tid);
    CP_COMMIT();

    for (int c = 0; c < 64; ++c) {
        if (c + 2 < 64) CP_WAIT1(); else CP_WAIT0();
        __syncthreads();
        if (c + 2 < 64) {
            issue_chunk(Ah, Al, Bh, Bl, sb + (uint32_t)((c + 2) % NSTAGE) * STAGEB,
                        (c + 2) * 32, tid);
            CP_COMMIT();
        }
        compute_stage(sb + (uint32_t)(c % NSTAGE) * STAGEB, wm, wn, lane, acc);
    }
}

// ---------------------------------------------------------------------------
// Kernel 1: q = RoPE(x @ Wq^T) * SCALE -> bf16 hi/lo [B*NH][T][64]
// ---------------------------------------------------------------------------
__global__ void __launch_bounds__(256, 1) qgemm_rope_kernel()
{
    const int bn = blockIdx.x, bm = blockIdx.y;
    float acc[2][8][4];
    gemm_mainloop(g_x_hi + (size_t)bm * 128 * DDIM, g_x_lo + (size_t)bm * 128 * DDIM,
                  g_wq_hi + (size_t)bn * 128 * DDIM, g_wq_lo + (size_t)bn * 128 * DDIM,
                  acc);

    const int tid = threadIdx.x, lane = tid & 31, w = tid >> 5;
    const int wm = w >> 1, wn = w & 1;
    const int h = bn * 2 + wn;
    const int fc = lane & 3;

#pragma unroll
    for (int mt = 0; mt < 2; ++mt) {
        const int m0 = bm * 128 + wm * 32 + mt * 16 + (lane >> 2);
#pragma unroll
        for (int rh = 0; rh < 2; ++rh) {
            const int m = m0 + rh * 8;
            const int b = m >> 12, t = m & 4095;
            size_t rbase = ((size_t)(b * NH + h) * TT + t) * DHD;
#pragma unroll
            for (int nt = 0; nt < 8; ++nt) {
                float e = acc[mt][nt][rh * 2 + 0];
                float o = acc[mt][nt][rh * 2 + 1];
                float ph = (float)t * g_invfreq[nt * 4 + fc];
                float sn, cn;
                sincosf(ph, &sn, &cn);
                float v0 = (e * cn - o * sn) * SCALE;
                float v1 = (e * sn + o * cn) * SCALE;
                uint32_t hi, lo;
                split2(v0, v1, hi, lo);
                *(uint32_t*)(g_q_hi + rbase + nt * 8 + fc * 2) = hi;
                *(uint32_t*)(g_q_lo + rbase + nt * 8 + fc * 2) = lo;
            }
        }
    }
}

// ---------------------------------------------------------------------------
// Kernel 3: out = ao @ Wo^T -> d_out fp32
// ---------------------------------------------------------------------------
__global__ void __launch_bounds__(256, 1) ogemm_kernel(float* __restrict__ out)
{
    const int bn = blockIdx.x, bm = blockIdx.y;
    float acc[2][8][4];
    gemm_mainloop(g_ao_hi + (size_t)bm * 128 * DDIM, g_ao_lo + (size_t)bm * 128 * DDIM,
                  g_wo_hi + (size_t)bn * 128 * DDIM, g_wo_lo + (size_t)bn * 128 * DDIM,
                  acc);

    const int tid = threadIdx.x, lane = tid & 31, w = tid >> 5;
    const int wm = w >> 1, wn = w & 1;
    const int col = bn * 128 + wn * 64 + (lane & 3) * 2;

#pragma unroll
    for (int mt = 0; mt < 2; ++mt) {
        const int m0 = bm * 128 + wm * 32 + mt * 16 + (lane >> 2);
#pragma unroll
        for (int rh = 0; rh < 2; ++rh) {
            float* crow = out + (size_t)(m0 + rh * 8) * DDIM + col;
#pragma unroll
            for (int nt = 0; nt < 8; ++nt) {
                float2 v = make_float2(acc[mt][nt][rh * 2 + 0], acc[mt][nt][rh * 2 + 1]);
                *(float2*)(crow + nt * 8) = v;
            }
        }
    }
}

// ---------------------------------------------------------------------------
// Kernel 2: tensor-core windowed causal attention (flash style, HMMA).
// CTA = 128 q rows x bh. Warp = 16 q rows x 64 keys. Double-buffered K/V.
// ---------------------------------------------------------------------------
#define AT_STRIDE 144
#define AT_TILE   (64 * AT_STRIDE)          // 9216
#define AT_STAGE  (4 * AT_TILE)             // 36864
#define AT_QOFF   (2 * AT_STAGE)            // 73728
#define AT_QTILE  (128 * AT_STRIDE)         // 18432
#define ATTN_SMEM (AT_QOFF + 2 * AT_QTILE)  // 110592

__device__ __forceinline__ void attn_issue(
    const __nv_bfloat16* __restrict__ Kh, const __nv_bfloat16* __restrict__ Kl,
    const __nv_bfloat16* __restrict__ Vh, const __nv_bfloat16* __restrict__ Vl,
    uint32_t stage, int kb, int tid)
{
    const __nv_bfloat16* srcs[4] = {Kh, Kl, Vh, Vl};
#pragma unroll
    for (int t = 0; t < 4; ++t) {
#pragma unroll
        for (int i = 0; i < 2; ++i) {
            int idx = tid + i * 256;               // 0..511
            int r = idx >> 3, c = idx & 7;
            uint64_t src = __cvta_generic_to_global(srcs[t] + (size_t)(kb * 64 + r) * DHD + c * 8);
            uint32_t dst = stage + t * AT_TILE + r * AT_STRIDE + c * 16;
            CP_ASYNC16(dst, src);
        }
    }
}

__global__ void __launch_bounds__(256, 1) attn_kernel()
{
    const int qt = blockIdx.x;                 // 0..31 (128 q rows)
    const int bh = blockIdx.y;                 // 0..63
    const int b = bh >> 5, h = bh & 31, kvh = h >> 2;
    const int tid = threadIdx.x, lane = tid & 31, w = tid >> 5;
    const uint32_t sb = smem_u32(smraw);
    const int nkb = min(16, 2 * qt + 2);

    const __nv_bfloat16* Kh = g_k_hi + (size_t)(b * NKV + kvh) * WIN * DHD;
    const __nv_bfloat16* Kl = g_k_lo + (size_t)(b * NKV + kvh) * WIN * DHD;
    const __nv_bfloat16* Vh = g_v_hi + (size_t)(b * NKV + kvh) * WIN * DHD;
    const __nv_bfloat16* Vl = g_v_lo + (size_t)(b * NKV + kvh) * WIN * DHD;

    // prime stage 0 while we stage Q
    attn_issue(Kh, Kl, Vh, Vl, sb, 0, tid);
    CP_COMMIT();

    // Q tile (128 x 64 hi/lo) -> smem, 144B row stride
    {
        const __nv_bfloat16* qh = g_q_hi + ((size_t)bh * TT + (size_t)qt * 128) * DHD;
        const __nv_bfloat16* ql = g_q_lo + ((size_t)bh * TT + (size_t)qt * 128) * DHD;
#pragma unroll
        for (int i = 0; i < 4; ++i) {
            int idx = tid + i * 256;               // 0..1023
            int r = idx >> 3, c = idx & 7;
            *(uint4*)(smraw + AT_QOFF + r * AT_STRIDE + c * 16) =
                *(const uint4*)(qh + (size_t)r * DHD + c * 8);
            *(uint4*)(smraw + AT_QOFF + AT_QTILE + r * AT_STRIDE + c * 16) =
                *(const uint4*)(ql + (size_t)r * DHD + c * 8);
        }
    }
    __syncthreads();

    uint32_t qhf[4][4], qlf[4][4];
    {
        uint32_t a_addr = sb + AT_QOFF + (uint32_t)(w * 16 + (lane & 15)) * AT_STRIDE
                        + (uint32_t)((lane >> 4) * 16);
#pragma unroll
        for (int kc = 0; kc < 4; ++kc) {
            ldsm4(qhf[kc], a_addr + kc * 32);
            ldsm4(qlf[kc], a_addr + AT_QTILE + kc * 32);
        }
    }

    float m0 = -INFINITY, m1 = -INFINITY, l0 = 0.f, l1 = 0.f;
    float oac[8][4];
#pragma unroll
    for (int nt = 0; nt < 8; ++nt)
#pragma unroll
        for (int j = 0; j < 4; ++j) oac[nt][j] = 0.f;

    const int trow0 = qt * 128 + w * 16 + (lane >> 2);
    const int scb = (lane & 3) * 2;
    const uint32_t b_off = (uint32_t)(((lane & 7) + ((lane & 16) >> 1)) * AT_STRIDE
                         + ((lane >> 3) & 1) * 16);
    const uint32_t v_off = (uint32_t)((((lane >> 3) & 1) * 8 + (lane & 7)) * AT_STRIDE
                         + (lane >> 4) * 16);

    for (int kb = 0; kb < nkb; ++kb) {
        uint32_t stage = sb + (uint32_t)(kb & 1) * AT_STAGE;
        if (kb + 1 < nkb) {
            attn_issue(Kh, Kl, Vh, Vl, sb + (uint32_t)((kb + 1) & 1) * AT_STAGE, kb + 1, tid);
            CP_COMMIT();
            CP_WAIT1();
        } else {
            CP_WAIT0();
        }
        __syncthreads();

        // ---- S = Q.K^T (pre-scaled), 3 split passes
        float sac[8][4];
#pragma unroll
        for (int nt = 0; nt < 8; ++nt)
#pragma unroll
            for (int j = 0; j < 4; ++j) sac[nt][j] = 0.f;

#pragma unroll
        for (int kc = 0; kc < 4; ++kc) {
            uint32_t kf[4][4];
#pragma unroll
            for (int ng = 0; ng < 4; ++ng)
                ldsm4(kf[ng], stage + (uint32_t)(ng * 16) * AT_STRIDE + b_off + kc * 32);
#pragma unroll
            for (int ng = 0; ng < 4; ++ng) {
                mma16816(sac[2 * ng],     qhf[kc], &kf[ng][0]);
                mma16816(sac[2 * ng + 1], qhf[kc], &kf[ng][2]);
            }
#pragma unroll
            for (int ng = 0; ng < 4; ++ng) {
                mma16816(sac[2 * ng],     qlf[kc], &kf[ng][0]);
                mma16816(sac[2 * ng + 1], qlf[kc], &kf[ng][2]);
            }
#pragma unroll
            for (int ng = 0; ng < 4; ++ng)
                ldsm4(kf[ng], stage + AT_TILE + (uint32_t)(ng * 16) * AT_STRIDE + b_off + kc * 32);
#pragma unroll
            for (int ng = 0; ng < 4; ++ng) {
                mma16816(sac[2 * ng],     qhf[kc], &kf[ng][0]);
                mma16816(sac[2 * ng + 1], qhf[kc], &kf[ng][2]);
            }
        }

        // ---- causal mask (s > t)
        if (kb * 64 + 63 > trow0) {
#pragma unroll
            for (int nt = 0; nt < 8; ++nt) {
                int s0 = kb * 64 + nt * 8 + scb;
                if (s0     > trow0)     sac[nt][0] = -INFINITY;
                if (s0 + 1 > trow0)     sac[nt][1] = -INFINITY;
                if (s0     > trow0 + 8) sac[nt][2] = -INFINITY;
                if (s0 + 1 > trow0 + 8) sac[nt][3] = -INFINITY;
            }
        }

        // ---- online softmax (rows r and r+8)
        float mx0 = -INFINITY, mx1 = -INFINITY;
#pragma unroll
        for (int nt = 0; nt < 8; ++nt) {
            mx0 = fmaxf(mx0, fmaxf(sac[nt][0], sac[nt][1]));
            mx1 = fmaxf(mx1, fmaxf(sac[nt][2], sac[nt][3]));
        }
        mx0 = fmaxf(mx0, __shfl_xor_sync(0xffffffffu, mx0, 1));
        mx0 = fmaxf(mx0, __shfl_xor_sync(0xffffffffu, mx0, 2));
        mx1 = fmaxf(mx1, __shfl_xor_sync(0xffffffffu, mx1, 1));
        mx1 = fmaxf(mx1, __shfl_xor_sync(0xffffffffu, mx1, 2));

        float mn0 = fmaxf(m0, mx0), mn1 = fmaxf(m1, mx1);
        float cr0 = __expf(m0 - mn0), cr1 = __expf(m1 - mn1);
        float s0 = 0.f, s1 = 0.f;
#pragma unroll
        for (int nt = 0; nt < 8; ++nt) {
            float p0 = __expf(sac[nt][0] - mn0);
            float p1 = __expf(sac[nt][1] - mn0);
            float p2 = __expf(sac[nt][2] - mn1);
            float p3 = __expf(sac[nt][3] - mn1);
            sac[nt][0] = p0; sac[nt][1] = p1; sac[nt][2] = p2; sac[nt][3] = p3;
            s0 += p0 + p1;
            s1 += p2 + p3;
        }
        s0 += __shfl_xor_sync(0xffffffffu, s0, 1);
        s0 += __shfl_xor_sync(0xffffffffu, s0, 2);
        s1 += __shfl_xor_sync(0xffffffffu, s1, 1);
        s1 += __shfl_xor_sync(0xffffffffu, s1, 2);
        l0 = l0 * cr0 + s0;
        l1 = l1 * cr1 + s1;
        m0 = mn0; m1 = mn1;
#pragma unroll
        for (int nt = 0; nt < 8; ++nt) {
            oac[nt][0] *= cr0; oac[nt][1] *= cr0;
            oac[nt][2] *= cr1; oac[nt][3] *= cr1;
        }

        // ---- O += P.V, P split hi/lo in registers (C-frag -> A-frag repack)
#pragma unroll
        for (int kc = 0; kc < 4; ++kc) {
            uint32_t ph[4], pl[4];
            split2(sac[2 * kc][0],     sac[2 * kc][1],     ph[0], pl[0]);
            split2(sac[2 * kc][2],     sac[2 * kc][3],     ph[1], pl[1]);
            split2(sac[2 * kc + 1][0], sac[2 * kc + 1][1], ph[2], pl[2]);
            split2(sac[2 * kc + 1][2], sac[2 * kc + 1][3], ph[3], pl[3]);

            uint32_t vaddr = stage + 2 * AT_TILE + (uint32_t)(kc * 16) * AT_STRIDE + v_off;
#pragma unroll
            for (int nt2 = 0; nt2 < 4; ++nt2) {
                uint32_t f[4];
                ldsm4t(f, vaddr + nt2 * 32);                 // Vh
                mma16816(oac[2 * nt2],     ph, &f[0]);
                mma16816(oac[2 * nt2 + 1], ph, &f[2]);
                mma16816(oac[2 * nt2],     pl, &f[0]);
                mma16816(oac[2 * nt2 + 1], pl, &f[2]);
                ldsm4t(f, vaddr + AT_TILE + nt2 * 32);       // Vl
                mma16816(oac[2 * nt2],     ph, &f[0]);
                mma16816(oac[2 * nt2 + 1], ph, &f[2]);
            }
        }
        __syncthreads();
    }

    // ---- epilogue: O /= l, bf16 hi/lo split store to g_ao
    float i0 = 1.f / l0, i1 = 1.f / l1;
    size_t base0 = ((size_t)(b * TT) + trow0) * DDIM + h * DHD + scb;
    size_t base1 = base0 + (size_t)8 * DDIM;
#pragma unroll
    for (int nt = 0; nt < 8; ++nt) {
        uint32_t hi, lo;
        split2(oac[nt][0] * i0, oac[nt][1] * i0, hi, lo);
        *(uint32_t*)(g_ao_hi + base0 + nt * 8) = hi;
        *(uint32_t*)(g_ao_lo + base0 + nt * 8) = lo;
        split2(oac[nt][2] * i1, oac[nt][3] * i1, hi, lo);
        *(uint32_t*)(g_ao_hi + base1 + nt * 8) = hi;
        *(uint32_t*)(g_ao_lo + base1 + nt * 8) = lo;
    }
}

// ---------------------------------------------------------------------------
extern "C" void kernel_launch(void* const* d_in, const int* in_sizes, int n_in,
                              void* d_out, int out_size)
{
    const float* x  = (const float*)d_in[0];
    const float* kc = (const float*)d_in[1];
    const float* vc = (const float*)d_in[2];
    const float* Wq = (const float*)d_in[3];
    const float* Wo = (const float*)d_in[4];
    float* out = (float*)d_out;
    (void)in_sizes; (void)n_in; (void)out_size;

    cudaFuncSetAttribute(attn_kernel, cudaFuncAttributeMaxDynamicSharedMemorySize, ATTN_SMEM);
    cudaFuncSetAttribute(qgemm_rope_kernel, cudaFuncAttributeMaxDynamicSharedMemorySize, GEMM_SMEM);
    cudaFuncSetAttribute(ogemm_kernel, cudaFuncAttributeMaxDynamicSharedMemorySize, GEMM_SMEM);

    __nv_bfloat16 *xh, *xl, *wqh, *wql, *woh, *wol;
    cudaGetSymbolAddress((void**)&xh,  g_x_hi);
    cudaGetSymbolAddress((void**)&xl,  g_x_lo);
    cudaGetSymbolAddress((void**)&wqh, g_wq_hi);
    cudaGetSymbolAddress((void**)&wql, g_wq_lo);
    cudaGetSymbolAddress((void**)&woh, g_wo_hi);
    cudaGetSymbolAddress((void**)&wol, g_wo_lo);

    initfreq_kernel<<<1, 32>>>();

    const int nx4 = (BB * TT * DDIM) / 4;
    const int nw4 = (DDIM * DDIM) / 4;
    split_kernel<<<nx4 / 256, 256>>>((const float4*)x,  (uint2*)xh,  (uint2*)xl,  nx4);
    split_kernel<<<nw4 / 256, 256>>>((const float4*)Wq, (uint2*)wqh, (uint2*)wql, nw4);
    split_kernel<<<nw4 / 256, 256>>>((const float4*)Wo, (uint2*)woh, (uint2*)wol, nw4);

    const int nkv4 = (BB * NKV * WIN * DHD) / 4;   // 262144
    kvsplit_kernel<<<nkv4 / 256, 256>>>((const float4*)kc, (const float4*)vc);

    dim3 ggrid(DDIM / 128, (BB * TT) / 128);   // (16, 64)
    qgemm_rope_kernel<<<ggrid, 256, GEMM_SMEM>>>();

    dim3 agrid(TT / 128, BB * NH);             // (32, 64)
    attn_kernel<<<agrid, 256, ATTN_SMEM>>>();

    ogemm_kernel<<<ggrid, 256, GEMM_SMEM>>>(out);
}

// round 7
// speedup vs baseline: 6.2142x; 1.1271x over previous
#include <cuda_runtime.h>
#include <cuda_bf16.h>
#include <math.h>
#include <stdint.h>

// Problem constants
#define BB    2
#define TT    4096
#define DDIM  2048
#define NH    32
#define NKV   8
#define DHD   64
#define TCC   4096
#define WIN   1024
#define WSTART 3072
#define SCALE 0.125f

// ---------------------------------------------------------------------------
// Scratch (device globals — allocation-free rule)
// ---------------------------------------------------------------------------
__device__ __nv_bfloat16 g_q_hi [(size_t)BB * NH * TT * DHD];  // RoPE'd, pre-scaled
__device__ __nv_bfloat16 g_q_lo [(size_t)BB * NH * TT * DHD];
__device__ __nv_bfloat16 g_k_hi [(size_t)BB * NKV * WIN * DHD];
__device__ __nv_bfloat16 g_k_lo [(size_t)BB * NKV * WIN * DHD];
__device__ __nv_bfloat16 g_v_hi [(size_t)BB * NKV * WIN * DHD];
__device__ __nv_bfloat16 g_v_lo [(size_t)BB * NKV * WIN * DHD];
__device__ __nv_bfloat16 g_x_hi [(size_t)BB * TT * DDIM];
__device__ __nv_bfloat16 g_x_lo [(size_t)BB * TT * DDIM];
__device__ __nv_bfloat16 g_wq_hi[(size_t)DDIM * DDIM];
__device__ __nv_bfloat16 g_wq_lo[(size_t)DDIM * DDIM];
__device__ __nv_bfloat16 g_wo_hi[(size_t)DDIM * DDIM];
__device__ __nv_bfloat16 g_wo_lo[(size_t)DDIM * DDIM];
__device__ __nv_bfloat16 g_ao_hi[(size_t)BB * TT * DDIM];
__device__ __nv_bfloat16 g_ao_lo[(size_t)BB * TT * DDIM];
__device__ float         g_invfreq[32];

extern __shared__ char smraw[];

// ---------------------------------------------------------------------------
// Helpers (baseline PTX only: ldmatrix / mma.sync / cp.async — all sm_80+)
// ---------------------------------------------------------------------------
__device__ __forceinline__ uint32_t smem_u32(const void* p) {
    uint32_t a;
    asm("{ .reg .u64 t; cvta.to.shared.u64 t, %1; cvt.u32.u64 %0, t; }"
        : "=r"(a) : "l"(p));
    return a;
}

__device__ __forceinline__ void ldsm4(uint32_t* r, uint32_t addr) {
    asm volatile("ldmatrix.sync.aligned.m8n8.x4.shared.b16 {%0,%1,%2,%3}, [%4];"
        : "=r"(r[0]), "=r"(r[1]), "=r"(r[2]), "=r"(r[3]) : "r"(addr));
}

__device__ __forceinline__ void ldsm4t(uint32_t* r, uint32_t addr) {
    asm volatile("ldmatrix.sync.aligned.m8n8.x4.trans.shared.b16 {%0,%1,%2,%3}, [%4];"
        : "=r"(r[0]), "=r"(r[1]), "=r"(r[2]), "=r"(r[3]) : "r"(addr));
}

__device__ __forceinline__ void mma16816(float* c, const uint32_t* a, const uint32_t* b) {
    asm("mma.sync.aligned.m16n8k16.row.col.f32.bf16.bf16.f32 "
        "{%0,%1,%2,%3}, {%4,%5,%6,%7}, {%8,%9}, {%0,%1,%2,%3};"
        : "+f"(c[0]), "+f"(c[1]), "+f"(c[2]), "+f"(c[3])
        : "r"(a[0]), "r"(a[1]), "r"(a[2]), "r"(a[3]), "r"(b[0]), "r"(b[1]));
}

#define CP_ASYNC16(dst, src) \
    asm volatile("cp.async.cg.shared.global [%0], [%1], 16;" \
                 :: "r"(dst), "l"(src) : "memory")
#define CP_COMMIT() asm volatile("cp.async.commit_group;" ::: "memory")
#define CP_WAIT1()  asm volatile("cp.async.wait_group 1;" ::: "memory")
#define CP_WAIT0()  asm volatile("cp.async.wait_group 0;" ::: "memory")

// split a pair of floats into bf16-hi pair and bf16-lo (residual) pair
__device__ __forceinline__ void split2(float a, float b, uint32_t& hi, uint32_t& lo) {
    __nv_bfloat16 ha = __float2bfloat16(a), hb = __float2bfloat16(b);
    __nv_bfloat162 hh = __halves2bfloat162(ha, hb);
    hi = *reinterpret_cast<uint32_t*>(&hh);
    __nv_bfloat16 la = __float2bfloat16(a - __bfloat162float(ha));
    __nv_bfloat16 lb = __float2bfloat16(b - __bfloat162float(hb));
    __nv_bfloat162 ll = __halves2bfloat162(la, lb);
    lo = *reinterpret_cast<uint32_t*>(&ll);
}

// ---------------------------------------------------------------------------
// Prep kernels
// ---------------------------------------------------------------------------
__global__ void __launch_bounds__(256) split_kernel(
    const float4* __restrict__ in, uint2* __restrict__ hi, uint2* __restrict__ lo, int n4)
{
    int i = blockIdx.x * 256 + threadIdx.x;
    if (i >= n4) return;
    float4 v = in[i];
    float vv[4] = {v.x, v.y, v.z, v.w};
    __nv_bfloat16 h[4], l[4];
#pragma unroll
    for (int j = 0; j < 4; ++j) {
        h[j] = __float2bfloat16(vv[j]);
        l[j] = __float2bfloat16(vv[j] - __bfloat162float(h[j]));
    }
    hi[i] = *(const uint2*)h;
    lo[i] = *(const uint2*)l;
}

// K/V window (last 1024 positions) -> bf16 hi/lo, layout [b][kv][1024][64]
__global__ void __launch_bounds__(256) kvsplit_kernel(
    const float4* __restrict__ kc, const float4* __restrict__ vc)
{
    int idx = blockIdx.x * 256 + threadIdx.x;          // 0..262143
    int within = idx & ((WIN * DHD / 4) - 1);          // 16383
    int bk = idx >> 14;                                // 0..15
    size_t src = (size_t)bk * (TCC * DHD / 4) + (WSTART * DHD / 4) + within;
    float4 k4 = kc[src];
    float4 v4 = vc[src];
    float kv_[4] = {k4.x, k4.y, k4.z, k4.w};
    float vv_[4] = {v4.x, v4.y, v4.z, v4.w};
    __nv_bfloat16 kh[4], kl[4], vh[4], vl[4];
#pragma unroll
    for (int j = 0; j < 4; ++j) {
        kh[j] = __float2bfloat16(kv_[j]);
        kl[j] = __float2bfloat16(kv_[j] - __bfloat162float(kh[j]));
        vh[j] = __float2bfloat16(vv_[j]);
        vl[j] = __float2bfloat16(vv_[j] - __bfloat162float(vh[j]));
    }
    ((uint2*)g_k_hi)[idx] = *(const uint2*)kh;
    ((uint2*)g_k_lo)[idx] = *(const uint2*)kl;
    ((uint2*)g_v_hi)[idx] = *(const uint2*)vh;
    ((uint2*)g_v_lo)[idx] = *(const uint2*)vl;
}

__global__ void initfreq_kernel() {
    int i = threadIdx.x;   // 32 threads
    g_invfreq[i] = (float)exp(-(double)i * (9.210340371976184 / 32.0));
}

// ---------------------------------------------------------------------------
// GEMM mainloop: 2-stage pipeline, 80KB smem -> 2 CTAs/SM (4 warps/SMSP)
// ---------------------------------------------------------------------------
#define TILEB      (128 * 80)
#define STAGEB     (4 * TILEB)
#define NSTAGE     2
#define GEMM_SMEM  (NSTAGE * STAGEB)   // 81920

__device__ __forceinline__ void issue_chunk(
    const __nv_bfloat16* __restrict__ Ah, const __nv_bfloat16* __restrict__ Al,
    const __nv_bfloat16* __restrict__ Bh, const __nv_bfloat16* __restrict__ Bl,
    uint32_t stage, int k0, int tid)
{
    const __nv_bfloat16* srcs[4] = {Ah, Al, Bh, Bl};
#pragma unroll
    for (int t = 0; t < 4; ++t) {
#pragma unroll
        for (int i = 0; i < 2; ++i) {
            int idx = tid + i * 256;
            int r = idx >> 2, cc = idx & 3;
            uint64_t src = __cvta_generic_to_global(srcs[t] + (size_t)r * DDIM + k0 + cc * 8);
            uint32_t dst = stage + t * TILEB + r * 80 + cc * 16;
            CP_ASYNC16(dst, src);
        }
    }
}

__device__ __forceinline__ void compute_stage(
    uint32_t stage, int wm, int wn, int lane, float acc[2][8][4])
{
    const uint32_t a_off = (uint32_t)((lane & 15) * 80 + (lane >> 4) * 16);
    const uint32_t b_row = (uint32_t)((lane & 7) + ((lane & 16) >> 1));
    const uint32_t b_off = b_row * 80 + ((lane >> 3) & 1) * 16;

#pragma unroll
    for (int s2 = 0; s2 < 2; ++s2) {
        const uint32_t kb = s2 * 32;

        uint32_t ah[2][4], al[2][4];
#pragma unroll
        for (int mt = 0; mt < 2; ++mt) {
            uint32_t base = stage + (uint32_t)(wm * 32 + mt * 16) * 80 + a_off + kb;
            ldsm4(ah[mt], base);
            ldsm4(al[mt], base + TILEB);
        }

        uint32_t bfr[8][2];
#pragma unroll
        for (int ng = 0; ng < 4; ++ng) {
            uint32_t base = stage + 2 * TILEB + (uint32_t)(wn * 64 + ng * 16) * 80 + b_off + kb;
            uint32_t t4[4];
            ldsm4(t4, base);
            bfr[ng * 2][0] = t4[0]; bfr[ng * 2][1] = t4[1];
            bfr[ng * 2 + 1][0] = t4[2]; bfr[ng * 2 + 1][1] = t4[3];
        }
#pragma unroll
        for (int mt = 0; mt < 2; ++mt)
#pragma unroll
            for (int nt = 0; nt < 8; ++nt)
                mma16816(acc[mt][nt], ah[mt], bfr[nt]);
#pragma unroll
        for (int mt = 0; mt < 2; ++mt)
#pragma unroll
            for (int nt = 0; nt < 8; ++nt)
                mma16816(acc[mt][nt], al[mt], bfr[nt]);

#pragma unroll
        for (int ng = 0; ng < 4; ++ng) {
            uint32_t base = stage + 3 * TILEB + (uint32_t)(wn * 64 + ng * 16) * 80 + b_off + kb;
            uint32_t t4[4];
            ldsm4(t4, base);
            bfr[ng * 2][0] = t4[0]; bfr[ng * 2][1] = t4[1];
            bfr[ng * 2 + 1][0] = t4[2]; bfr[ng * 2 + 1][1] = t4[3];
        }
#pragma unroll
        for (int mt = 0; mt < 2; ++mt)
#pragma unroll
            for (int nt = 0; nt < 8; ++nt)
                mma16816(acc[mt][nt], ah[mt], bfr[nt]);
    }
}

__device__ __forceinline__ void gemm_mainloop(
    const __nv_bfloat16* __restrict__ Ah, const __nv_bfloat16* __restrict__ Al,
    const __nv_bfloat16* __restrict__ Bh, const __nv_bfloat16* __restrict__ Bl,
    float acc[2][8][4])
{
    const uint32_t sb = smem_u32(smraw);
    const int tid = threadIdx.x;
    const int lane = tid & 31, w = tid >> 5;
    const int wm = w >> 1, wn = w & 1;

#pragma unroll
    for (int mt = 0; mt < 2; ++mt)
#pragma unroll
        for (int nt = 0; nt < 8; ++nt)
#pragma unroll
            for (int j = 0; j < 4; ++j) acc[mt][nt][j] = 0.f;

    issue_chunk(Ah, Al, Bh, Bl, sb, 0, tid);
    CP_COMMIT();

    for (int c = 0; c < 64; ++c) {
        CP_WAIT0();          // chunk c landed
        __syncthreads();     // everyone done computing chunk c-1 (other stage)
        if (c + 1 < 64) {    // prefetch c+1 into the other stage, overlaps compute
            issue_chunk(Ah, Al, Bh, Bl, sb + (uint32_t)((c + 1) & 1) * STAGEB,
                        (c + 1) * 32, tid);
            CP_COMMIT();
        }
        compute_stage(sb + (uint32_t)(c & 1) * STAGEB, wm, wn, lane, acc);
    }
}

// ---------------------------------------------------------------------------
// Kernel 1: q = RoPE(x @ Wq^T) * SCALE -> bf16 hi/lo [B*NH][T][64]
// ---------------------------------------------------------------------------
__global__ void __launch_bounds__(256, 2) qgemm_rope_kernel()
{
    const int bn = blockIdx.x, bm = blockIdx.y;
    float acc[2][8][4];
    gemm_mainloop(g_x_hi + (size_t)bm * 128 * DDIM, g_x_lo + (size_t)bm * 128 * DDIM,
                  g_wq_hi + (size_t)bn * 128 * DDIM, g_wq_lo + (size_t)bn * 128 * DDIM,
                  acc);

    const int tid = threadIdx.x, lane = tid & 31, w = tid >> 5;
    const int wm = w >> 1, wn = w & 1;
    const int h = bn * 2 + wn;
    const int fc = lane & 3;

#pragma unroll
    for (int mt = 0; mt < 2; ++mt) {
        const int m0 = bm * 128 + wm * 32 + mt * 16 + (lane >> 2);
#pragma unroll
        for (int rh = 0; rh < 2; ++rh) {
            const int m = m0 + rh * 8;
            const int b = m >> 12, t = m & 4095;
            size_t rbase = ((size_t)(b * NH + h) * TT + t) * DHD;
#pragma unroll
            for (int nt = 0; nt < 8; ++nt) {
                float e = acc[mt][nt][rh * 2 + 0];
                float o = acc[mt][nt][rh * 2 + 1];
                float ph = (float)t * g_invfreq[nt * 4 + fc];
                float sn, cn;
                sincosf(ph, &sn, &cn);
                float v0 = (e * cn - o * sn) * SCALE;
                float v1 = (e * sn + o * cn) * SCALE;
                uint32_t hi, lo;
                split2(v0, v1, hi, lo);
                *(uint32_t*)(g_q_hi + rbase + nt * 8 + fc * 2) = hi;
                *(uint32_t*)(g_q_lo + rbase + nt * 8 + fc * 2) = lo;
            }
        }
    }
}

// ---------------------------------------------------------------------------
// Kernel 3: out = ao @ Wo^T -> d_out fp32
// ---------------------------------------------------------------------------
__global__ void __launch_bounds__(256, 2) ogemm_kernel(float* __restrict__ out)
{
    const int bn = blockIdx.x, bm = blockIdx.y;
    float acc[2][8][4];
    gemm_mainloop(g_ao_hi + (size_t)bm * 128 * DDIM, g_ao_lo + (size_t)bm * 128 * DDIM,
                  g_wo_hi + (size_t)bn * 128 * DDIM, g_wo_lo + (size_t)bn * 128 * DDIM,
                  acc);

    const int tid = threadIdx.x, lane = tid & 31, w = tid >> 5;
    const int wm = w >> 1, wn = w & 1;
    const int col = bn * 128 + wn * 64 + (lane & 3) * 2;

#pragma unroll
    for (int mt = 0; mt < 2; ++mt) {
        const int m0 = bm * 128 + wm * 32 + mt * 16 + (lane >> 2);
#pragma unroll
        for (int rh = 0; rh < 2; ++rh) {
            float* crow = out + (size_t)(m0 + rh * 8) * DDIM + col;
#pragma unroll
            for (int nt = 0; nt < 8; ++nt) {
                float2 v = make_float2(acc[mt][nt][rh * 2 + 0], acc[mt][nt][rh * 2 + 1]);
                *(float2*)(crow + nt * 8) = v;
            }
        }
    }
}

// ---------------------------------------------------------------------------
// Kernel 2: tensor-core windowed causal attention (flash style, HMMA).
// CTA = 128 q rows x bh. Warp = 16 q rows x 64 keys. Double-buffered K/V.
// ---------------------------------------------------------------------------
#define AT_STRIDE 144
#define AT_TILE   (64 * AT_STRIDE)          // 9216
#define AT_STAGE  (4 * AT_TILE)             // 36864
#define AT_QOFF   (2 * AT_STAGE)            // 73728
#define AT_QTILE  (128 * AT_STRIDE)         // 18432
#define ATTN_SMEM (AT_QOFF + 2 * AT_QTILE)  // 110592

__device__ __forceinline__ void attn_issue(
    const __nv_bfloat16* __restrict__ Kh, const __nv_bfloat16* __restrict__ Kl,
    const __nv_bfloat16* __restrict__ Vh, const __nv_bfloat16* __restrict__ Vl,
    uint32_t stage, int kb, int tid)
{
    const __nv_bfloat16* srcs[4] = {Kh, Kl, Vh, Vl};
#pragma unroll
    for (int t = 0; t < 4; ++t) {
#pragma unroll
        for (int i = 0; i < 2; ++i) {
            int idx = tid + i * 256;               // 0..511
            int r = idx >> 3, c = idx & 7;
            uint64_t src = __cvta_generic_to_global(srcs[t] + (size_t)(kb * 64 + r) * DHD + c * 8);
            uint32_t dst = stage + t * AT_TILE + r * AT_STRIDE + c * 16;
            CP_ASYNC16(dst, src);
        }
    }
}

__global__ void __launch_bounds__(256, 1) attn_kernel()
{
    const int qt = blockIdx.x;                 // 0..31 (128 q rows)
    const int bh = blockIdx.y;                 // 0..63
    const int b = bh >> 5, h = bh & 31, kvh = h >> 2;
    const int tid = threadIdx.x, lane = tid & 31, w = tid >> 5;
    const uint32_t sb = smem_u32(smraw);
    const int nkb = min(16, 2 * qt + 2);

    const __nv_bfloat16* Kh = g_k_hi + (size_t)(b * NKV + kvh) * WIN * DHD;
    const __nv_bfloat16* Kl = g_k_lo + (size_t)(b * NKV + kvh) * WIN * DHD;
    const __nv_bfloat16* Vh = g_v_hi + (size_t)(b * NKV + kvh) * WIN * DHD;
    const __nv_bfloat16* Vl = g_v_lo + (size_t)(b * NKV + kvh) * WIN * DHD;

    attn_issue(Kh, Kl, Vh, Vl, sb, 0, tid);
    CP_COMMIT();

    {
        const __nv_bfloat16* qh = g_q_hi + ((size_t)bh * TT + (size_t)qt * 128) * DHD;
        const __nv_bfloat16* ql = g_q_lo + ((size_t)bh * TT + (size_t)qt * 128) * DHD;
#pragma unroll
        for (int i = 0; i < 4; ++i) {
            int idx = tid + i * 256;
            int r = idx >> 3, c = idx & 7;
            *(uint4*)(smraw + AT_QOFF + r * AT_STRIDE + c * 16) =
                *(const uint4*)(qh + (size_t)r * DHD + c * 8);
            *(uint4*)(smraw + AT_QOFF + AT_QTILE + r * AT_STRIDE + c * 16) =
                *(const uint4*)(ql + (size_t)r * DHD + c * 8);
        }
    }
    __syncthreads();

    uint32_t qhf[4][4], qlf[4][4];
    {
        uint32_t a_addr = sb + AT_QOFF + (uint32_t)(w * 16 + (lane & 15)) * AT_STRIDE
                        + (uint32_t)((lane >> 4) * 16);
#pragma unroll
        for (int kc = 0; kc < 4; ++kc) {
            ldsm4(qhf[kc], a_addr + kc * 32);
            ldsm4(qlf[kc], a_addr + AT_QTILE + kc * 32);
        }
    }

    float m0 = -INFINITY, m1 = -INFINITY, l0 = 0.f, l1 = 0.f;
    float oac[8][4];
#pragma unroll
    for (int nt = 0; nt < 8; ++nt)
#pragma unroll
        for (int j = 0; j < 4; ++j) oac[nt][j] = 0.f;

    const int trow0 = qt * 128 + w * 16 + (lane >> 2);
    const int scb = (lane & 3) * 2;
    const uint32_t b_off = (uint32_t)(((lane & 7) + ((lane & 16) >> 1)) * AT_STRIDE
                         + ((lane >> 3) & 1) * 16);
    const uint32_t v_off = (uint32_t)((((lane >> 3) & 1) * 8 + (lane & 7)) * AT_STRIDE
                         + (lane >> 4) * 16);

    for (int kb = 0; kb < nkb; ++kb) {
        uint32_t stage = sb + (uint32_t)(kb & 1) * AT_STAGE;
        if (kb + 1 < nkb) {
            attn_issue(Kh, Kl, Vh, Vl, sb + (uint32_t)((kb + 1) & 1) * AT_STAGE, kb + 1, tid);
            CP_COMMIT();
            CP_WAIT1();
        } else {
            CP_WAIT0();
        }
        __syncthreads();

        float sac[8][4];
#pragma unroll
        for (int nt = 0; nt < 8; ++nt)
#pragma unroll
            for (int j = 0; j < 4; ++j) sac[nt][j] = 0.f;

#pragma unroll
        for (int kc = 0; kc < 4; ++kc) {
            uint32_t kf[4][4];
#pragma unroll
            for (int ng = 0; ng < 4; ++ng)
                ldsm4(kf[ng], stage + (uint32_t)(ng * 16) * AT_STRIDE + b_off + kc * 32);
#pragma unroll
            for (int ng = 0; ng < 4; ++ng) {
                mma16816(sac[2 * ng],     qhf[kc], &kf[ng][0]);
                mma16816(sac[2 * ng + 1], qhf[kc], &kf[ng][2]);
            }
#pragma unroll
            for (int ng = 0; ng < 4; ++ng) {
                mma16816(sac[2 * ng],     qlf[kc], &kf[ng][0]);
                mma16816(sac[2 * ng + 1], qlf[kc], &kf[ng][2]);
            }
#pragma unroll
            for (int ng = 0; ng < 4; ++ng)
                ldsm4(kf[ng], stage + AT_TILE + (uint32_t)(ng * 16) * AT_STRIDE + b_off + kc * 32);
#pragma unroll
            for (int ng = 0; ng < 4; ++ng) {
                mma16816(sac[2 * ng],     qhf[kc], &kf[ng][0]);
                mma16816(sac[2 * ng + 1], qhf[kc], &kf[ng][2]);
            }
        }

        if (kb * 64 + 63 > trow0) {
#pragma unroll
            for (int nt = 0; nt < 8; ++nt) {
                int s0 = kb * 64 + nt * 8 + scb;
                if (s0     > trow0)     sac[nt][0] = -INFINITY;
                if (s0 + 1 > trow0)     sac[nt][1] = -INFINITY;
                if (s0     > trow0 + 8) sac[nt][2] = -INFINITY;
                if (s0 + 1 > trow0 + 8) sac[nt][3] = -INFINITY;
            }
        }

        float mx0 = -INFINITY, mx1 = -INFINITY;
#pragma unroll
        for (int nt = 0; nt < 8; ++nt) {
            mx0 = fmaxf(mx0, fmaxf(sac[nt][0], sac[nt][1]));
            mx1 = fmaxf(mx1, fmaxf(sac[nt][2], sac[nt][3]));
        }
        mx0 = fmaxf(mx0, __shfl_xor_sync(0xffffffffu, mx0, 1));
        mx0 = fmaxf(mx0, __shfl_xor_sync(0xffffffffu, mx0, 2));
        mx1 = fmaxf(mx1, __shfl_xor_sync(0xffffffffu, mx1, 1));
        mx1 = fmaxf(mx1, __shfl_xor_sync(0xffffffffu, mx1, 2));

        float mn0 = fmaxf(m0, mx0), mn1 = fmaxf(m1, mx1);
        float cr0 = __expf(m0 - mn0), cr1 = __expf(m1 - mn1);
        float s0 = 0.f, s1 = 0.f;
#pragma unroll
        for (int nt = 0; nt < 8; ++nt) {
            float p0 = __expf(sac[nt][0] - mn0);
            float p1 = __expf(sac[nt][1] - mn0);
            float p2 = __expf(sac[nt][2] - mn1);
            float p3 = __expf(sac[nt][3] - mn1);
            sac[nt][0] = p0; sac[nt][1] = p1; sac[nt][2] = p2; sac[nt][3] = p3;
            s0 += p0 + p1;
            s1 += p2 + p3;
        }
        s0 += __shfl_xor_sync(0xffffffffu, s0, 1);
        s0 += __shfl_xor_sync(0xffffffffu, s0, 2);
        s1 += __shfl_xor_sync(0xffffffffu, s1, 1);
        s1 += __shfl_xor_sync(0xffffffffu, s1, 2);
        l0 = l0 * cr0 + s0;
        l1 = l1 * cr1 + s1;
        m0 = mn0; m1 = mn1;
#pragma unroll
        for (int nt = 0; nt < 8; ++nt) {
            oac[nt][0] *= cr0; oac[nt][1] *= cr0;
            oac[nt][2] *= cr1; oac[nt][3] *= cr1;
        }

#pragma unroll
        for (int kc = 0; kc < 4; ++kc) {
            uint32_t ph[4], pl[4];
            split2(sac[2 * kc][0],     sac[2 * kc][1],     ph[0], pl[0]);
            split2(sac[2 * kc][2],     sac[2 * kc][3],     ph[1], pl[1]);
            split2(sac[2 * kc + 1][0], sac[2 * kc + 1][1], ph[2], pl[2]);
            split2(sac[2 * kc + 1][2], sac[2 * kc + 1][3], ph[3], pl[3]);

            uint32_t vaddr = stage + 2 * AT_TILE + (uint32_t)(kc * 16) * AT_STRIDE + v_off;
#pragma unroll
            for (int nt2 = 0; nt2 < 4; ++nt2) {
                uint32_t f[4];
                ldsm4t(f, vaddr + nt2 * 32);                 // Vh
                mma16816(oac[2 * nt2],     ph, &f[0]);
                mma16816(oac[2 * nt2 + 1], ph, &f[2]);
                mma16816(oac[2 * nt2],     pl, &f[0]);
                mma16816(oac[2 * nt2 + 1], pl, &f[2]);
                ldsm4t(f, vaddr + AT_TILE + nt2 * 32);       // Vl
                mma16816(oac[2 * nt2],     ph, &f[0]);
                mma16816(oac[2 * nt2 + 1], ph, &f[2]);
            }
        }
        __syncthreads();
    }

    float i0 = 1.f / l0, i1 = 1.f / l1;
    size_t base0 = ((size_t)(b * TT) + trow0) * DDIM + h * DHD + scb;
    size_t base1 = base0 + (size_t)8 * DDIM;
#pragma unroll
    for (int nt = 0; nt < 8; ++nt) {
        uint32_t hi, lo;
        split2(oac[nt][0] * i0, oac[nt][1] * i0, hi, lo);
        *(uint32_t*)(g_ao_hi + base0 + nt * 8) = hi;
        *(uint32_t*)(g_ao_lo + base0 + nt * 8) = lo;
        split2(oac[nt][2] * i1, oac[nt][3] * i1, hi, lo);
        *(uint32_t*)(g_ao_hi + base1 + nt * 8) = hi;
        *(uint32_t*)(g_ao_lo + base1 + nt * 8) = lo;
    }
}

// ---------------------------------------------------------------------------
extern "C" void kernel_launch(void* const* d_in, const int* in_sizes, int n_in,
                              void* d_out, int out_size)
{
    const float* x  = (const float*)d_in[0];
    const float* kc = (const float*)d_in[1];
    const float* vc = (const float*)d_in[2];
    const float* Wq = (const float*)d_in[3];
    const float* Wo = (const float*)d_in[4];
    float* out = (float*)d_out;
    (void)in_sizes; (void)n_in; (void)out_size;

    cudaFuncSetAttribute(attn_kernel, cudaFuncAttributeMaxDynamicSharedMemorySize, ATTN_SMEM);
    cudaFuncSetAttribute(qgemm_rope_kernel, cudaFuncAttributeMaxDynamicSharedMemorySize, GEMM_SMEM);
    cudaFuncSetAttribute(ogemm_kernel, cudaFuncAttributeMaxDynamicSharedMemorySize, GEMM_SMEM);

    __nv_bfloat16 *xh, *xl, *wqh, *wql, *woh, *wol;
    cudaGetSymbolAddress((void**)&xh,  g_x_hi);
    cudaGetSymbolAddress((void**)&xl,  g_x_lo);
    cudaGetSymbolAddress((void**)&wqh, g_wq_hi);
    cudaGetSymbolAddress((void**)&wql, g_wq_lo);
    cudaGetSymbolAddress((void**)&woh, g_wo_hi);
    cudaGetSymbolAddress((void**)&wol, g_wo_lo);

    initfreq_kernel<<<1, 32>>>();

    const int nx4 = (BB * TT * DDIM) / 4;
    const int nw4 = (DDIM * DDIM) / 4;
    split_kernel<<<nx4 / 256, 256>>>((const float4*)x,  (uint2*)xh,  (uint2*)xl,  nx4);
    split_kernel<<<nw4 / 256, 256>>>((const float4*)Wq, (uint2*)wqh, (uint2*)wql, nw4);
    split_kernel<<<nw4 / 256, 256>>>((const float4*)Wo, (uint2*)woh, (uint2*)wol, nw4);

    const int nkv4 = (BB * NKV * WIN * DHD) / 4;   // 262144
    kvsplit_kernel<<<nkv4 / 256, 256>>>((const float4*)kc, (const float4*)vc);

    dim3 ggrid(DDIM / 128, (BB * TT) / 128);   // (16, 64)
    qgemm_rope_kernel<<<ggrid, 256, GEMM_SMEM>>>();

    dim3 agrid(TT / 128, BB * NH);             // (32, 64)
    attn_kernel<<<agrid, 256, ATTN_SMEM>>>();

    ogemm_kernel<<<ggrid, 256, GEMM_SMEM>>>(out);
}

// round 8
// speedup vs baseline: 7.8013x; 1.2554x over previous
#include <cuda_runtime.h>
#include <cuda_bf16.h>
#include <cuda_fp16.h>
#include <math.h>
#include <stdint.h>

// Problem constants
#define BB    2
#define TT    4096
#define DDIM  2048
#define NH    32
#define NKV   8
#define DHD   64
#define TCC   4096
#define WIN   1024
#define WSTART 3072
#define SCALE 0.125f

// ---------------------------------------------------------------------------
// Scratch (device globals — allocation-free rule)
// ---------------------------------------------------------------------------
__device__ __nv_bfloat16 g_q_hi [(size_t)BB * NH * TT * DHD];  // RoPE'd, pre-scaled
__device__ __nv_bfloat16 g_q_lo [(size_t)BB * NH * TT * DHD];
__device__ __nv_bfloat16 g_k_hi [(size_t)BB * NKV * WIN * DHD];
__device__ __nv_bfloat16 g_k_lo [(size_t)BB * NKV * WIN * DHD];
__device__ __nv_bfloat16 g_v_hi [(size_t)BB * NKV * WIN * DHD];
__device__ __nv_bfloat16 g_v_lo [(size_t)BB * NKV * WIN * DHD];
__device__ __half        g_x_h  [(size_t)BB * TT * DDIM];      // fp16 hi
__device__ __half        g_x_l  [(size_t)BB * TT * DDIM];      // fp16 lo (residual)
__device__ __half        g_wq_h [(size_t)DDIM * DDIM];         // fp16 (rounded)
__device__ __half        g_wo_h [(size_t)DDIM * DDIM];
__device__ __half        g_ao_h [(size_t)BB * TT * DDIM];
__device__ __half        g_ao_l [(size_t)BB * TT * DDIM];
__device__ float         g_invfreq[32];

extern __shared__ char smraw[];

// ---------------------------------------------------------------------------
// Helpers (baseline PTX only: ldmatrix / mma.sync / cp.async — all sm_80+)
// ---------------------------------------------------------------------------
__device__ __forceinline__ uint32_t smem_u32(const void* p) {
    uint32_t a;
    asm("{ .reg .u64 t; cvta.to.shared.u64 t, %1; cvt.u32.u64 %0, t; }"
        : "=r"(a) : "l"(p));
    return a;
}

__device__ __forceinline__ void ldsm4(uint32_t* r, uint32_t addr) {
    asm volatile("ldmatrix.sync.aligned.m8n8.x4.shared.b16 {%0,%1,%2,%3}, [%4];"
        : "=r"(r[0]), "=r"(r[1]), "=r"(r[2]), "=r"(r[3]) : "r"(addr));
}

__device__ __forceinline__ void ldsm4t(uint32_t* r, uint32_t addr) {
    asm volatile("ldmatrix.sync.aligned.m8n8.x4.trans.shared.b16 {%0,%1,%2,%3}, [%4];"
        : "=r"(r[0]), "=r"(r[1]), "=r"(r[2]), "=r"(r[3]) : "r"(addr));
}

// bf16 HMMA (attention)
__device__ __forceinline__ void mma16816(float* c, const uint32_t* a, const uint32_t* b) {
    asm("mma.sync.aligned.m16n8k16.row.col.f32.bf16.bf16.f32 "
        "{%0,%1,%2,%3}, {%4,%5,%6,%7}, {%8,%9}, {%0,%1,%2,%3};"
        : "+f"(c[0]), "+f"(c[1]), "+f"(c[2]), "+f"(c[3])
        : "r"(a[0]), "r"(a[1]), "r"(a[2]), "r"(a[3]), "r"(b[0]), "r"(b[1]));
}

// fp16 HMMA (projection GEMMs)
__device__ __forceinline__ void mma16816h(float* c, const uint32_t* a, const uint32_t* b) {
    asm("mma.sync.aligned.m16n8k16.row.col.f32.f16.f16.f32 "
        "{%0,%1,%2,%3}, {%4,%5,%6,%7}, {%8,%9}, {%0,%1,%2,%3};"
        : "+f"(c[0]), "+f"(c[1]), "+f"(c[2]), "+f"(c[3])
        : "r"(a[0]), "r"(a[1]), "r"(a[2]), "r"(a[3]), "r"(b[0]), "r"(b[1]));
}

#define CP_ASYNC16(dst, src) \
    asm volatile("cp.async.cg.shared.global [%0], [%1], 16;" \
                 :: "r"(dst), "l"(src) : "memory")
#define CP_COMMIT() asm volatile("cp.async.commit_group;" ::: "memory")
#define CP_WAIT1()  asm volatile("cp.async.wait_group 1;" ::: "memory")
#define CP_WAIT0()  asm volatile("cp.async.wait_group 0;" ::: "memory")

// bf16 split (attention inputs)
__device__ __forceinline__ void split2(float a, float b, uint32_t& hi, uint32_t& lo) {
    __nv_bfloat16 ha = __float2bfloat16(a), hb = __float2bfloat16(b);
    __nv_bfloat162 hh = __halves2bfloat162(ha, hb);
    hi = *reinterpret_cast<uint32_t*>(&hh);
    __nv_bfloat16 la = __float2bfloat16(a - __bfloat162float(ha));
    __nv_bfloat16 lb = __float2bfloat16(b - __bfloat162float(hb));
    __nv_bfloat162 ll = __halves2bfloat162(la, lb);
    lo = *reinterpret_cast<uint32_t*>(&ll);
}

// fp16 split (GEMM A operands)
__device__ __forceinline__ void split2h(float a, float b, uint32_t& hi, uint32_t& lo) {
    __half ha = __float2half_rn(a), hb = __float2half_rn(b);
    __half2 hh = __halves2half2(ha, hb);
    hi = *reinterpret_cast<uint32_t*>(&hh);
    __half la = __float2half_rn(a - __half2float(ha));
    __half lb = __float2half_rn(b - __half2float(hb));
    __half2 ll = __halves2half2(la, lb);
    lo = *reinterpret_cast<uint32_t*>(&ll);
}

// ---------------------------------------------------------------------------
// Prep kernels
// ---------------------------------------------------------------------------
// fp32 -> fp16 hi + fp16 lo
__global__ void __launch_bounds__(256) split16_kernel(
    const float4* __restrict__ in, uint2* __restrict__ hi, uint2* __restrict__ lo, int n4)
{
    int i = blockIdx.x * 256 + threadIdx.x;
    if (i >= n4) return;
    float4 v = in[i];
    uint2 h, l;
    split2h(v.x, v.y, h.x, l.x);
    split2h(v.z, v.w, h.y, l.y);
    hi[i] = h;
    lo[i] = l;
}

// fp32 -> fp16 (round only, for weights)
__global__ void __launch_bounds__(256) round16_kernel(
    const float4* __restrict__ in, uint2* __restrict__ hi, int n4)
{
    int i = blockIdx.x * 256 + threadIdx.x;
    if (i >= n4) return;
    float4 v = in[i];
    __half h[4] = {__float2half_rn(v.x), __float2half_rn(v.y),
                   __float2half_rn(v.z), __float2half_rn(v.w)};
    hi[i] = *(const uint2*)h;
}

// K/V window (last 1024 positions) -> bf16 hi/lo, layout [b][kv][1024][64]
__global__ void __launch_bounds__(256) kvsplit_kernel(
    const float4* __restrict__ kc, const float4* __restrict__ vc)
{
    int idx = blockIdx.x * 256 + threadIdx.x;          // 0..262143
    int within = idx & ((WIN * DHD / 4) - 1);
    int bk = idx >> 14;
    size_t src = (size_t)bk * (TCC * DHD / 4) + (WSTART * DHD / 4) + within;
    float4 k4 = kc[src];
    float4 v4 = vc[src];
    float kv_[4] = {k4.x, k4.y, k4.z, k4.w};
    float vv_[4] = {v4.x, v4.y, v4.z, v4.w};
    __nv_bfloat16 kh[4], kl[4], vh[4], vl[4];
#pragma unroll
    for (int j = 0; j < 4; ++j) {
        kh[j] = __float2bfloat16(kv_[j]);
        kl[j] = __float2bfloat16(kv_[j] - __bfloat162float(kh[j]));
        vh[j] = __float2bfloat16(vv_[j]);
        vl[j] = __float2bfloat16(vv_[j] - __bfloat162float(vh[j]));
    }
    ((uint2*)g_k_hi)[idx] = *(const uint2*)kh;
    ((uint2*)g_k_lo)[idx] = *(const uint2*)kl;
    ((uint2*)g_v_hi)[idx] = *(const uint2*)vh;
    ((uint2*)g_v_lo)[idx] = *(const uint2*)vl;
}

__global__ void initfreq_kernel() {
    int i = threadIdx.x;   // 32 threads
    g_invfreq[i] = (float)exp(-(double)i * (9.210340371976184 / 32.0));
}

// ---------------------------------------------------------------------------
// GEMM mainloop (fp16 2-pass): acc = Ah.Bh^T + Al.Bh^T
// CTA tile 128x128, 8 warps. Per stage: 3 tiles (Ah, Al, Bh), 128 x 32 fp16,
// 80B row stride. 3-stage cp.async pipeline, 2 CTAs/SM.
// ---------------------------------------------------------------------------
#define TILEB      (128 * 80)          // 10240
#define STAGEB     (3 * TILEB)         // 30720
#define NSTAGE     3
#define GEMM_SMEM  (NSTAGE * STAGEB)   // 92160

__device__ __forceinline__ void issue_chunk(
    const __half* __restrict__ Ah, const __half* __restrict__ Al,
    const __half* __restrict__ Bh,
    uint32_t stage, int k0, int tid)
{
    const __half* srcs[3] = {Ah, Al, Bh};
#pragma unroll
    for (int t = 0; t < 3; ++t) {
#pragma unroll
        for (int i = 0; i < 2; ++i) {
            int idx = tid + i * 256;
            int r = idx >> 2, cc = idx & 3;
            uint64_t src = __cvta_generic_to_global(srcs[t] + (size_t)r * DDIM + k0 + cc * 8);
            uint32_t dst = stage + t * TILEB + r * 80 + cc * 16;
            CP_ASYNC16(dst, src);
        }
    }
}

__device__ __forceinline__ void compute_stage(
    uint32_t stage, int wm, int wn, int lane, float acc[2][8][4])
{
    const uint32_t a_off = (uint32_t)((lane & 15) * 80 + (lane >> 4) * 16);
    const uint32_t b_row = (uint32_t)((lane & 7) + ((lane & 16) >> 1));
    const uint32_t b_off = b_row * 80 + ((lane >> 3) & 1) * 16;

#pragma unroll
    for (int s2 = 0; s2 < 2; ++s2) {
        const uint32_t kb = s2 * 32;

        uint32_t ah[2][4], al[2][4];
#pragma unroll
        for (int mt = 0; mt < 2; ++mt) {
            uint32_t base = stage + (uint32_t)(wm * 32 + mt * 16) * 80 + a_off + kb;
            ldsm4(ah[mt], base);
            ldsm4(al[mt], base + TILEB);
        }

        uint32_t bfr[8][2];
#pragma unroll
        for (int ng = 0; ng < 4; ++ng) {
            uint32_t base = stage + 2 * TILEB + (uint32_t)(wn * 64 + ng * 16) * 80 + b_off + kb;
            uint32_t t4[4];
            ldsm4(t4, base);
            bfr[ng * 2][0] = t4[0]; bfr[ng * 2][1] = t4[1];
            bfr[ng * 2 + 1][0] = t4[2]; bfr[ng * 2 + 1][1] = t4[3];
        }
        // pass 1: Ah.Bh — 16 independent MMAs
#pragma unroll
        for (int mt = 0; mt < 2; ++mt)
#pragma unroll
            for (int nt = 0; nt < 8; ++nt)
                mma16816h(acc[mt][nt], ah[mt], bfr[nt]);
        // pass 2: Al.Bh — 16 independent MMAs
#pragma unroll
        for (int mt = 0; mt < 2; ++mt)
#pragma unroll
            for (int nt = 0; nt < 8; ++nt)
                mma16816h(acc[mt][nt], al[mt], bfr[nt]);
    }
}

__device__ __forceinline__ void gemm_mainloop(
    const __half* __restrict__ Ah, const __half* __restrict__ Al,
    const __half* __restrict__ Bh,
    float acc[2][8][4])
{
    const uint32_t sb = smem_u32(smraw);
    const int tid = threadIdx.x;
    const int lane = tid & 31, w = tid >> 5;
    const int wm = w >> 1, wn = w & 1;

#pragma unroll
    for (int mt = 0; mt < 2; ++mt)
#pragma unroll
        for (int nt = 0; nt < 8; ++nt)
#pragma unroll
            for (int j = 0; j < 4; ++j) acc[mt][nt][j] = 0.f;

    issue_chunk(Ah, Al, Bh, sb + 0 * STAGEB, 0,  tid);
    CP_COMMIT();
    issue_chunk(Ah, Al, Bh, sb + 1 * STAGEB, 32, tid);
    CP_COMMIT();

    for (int c = 0; c < 64; ++c) {
        if (c + 2 < 64) CP_WAIT1(); else CP_WAIT0();
        __syncthreads();
        if (c + 2 < 64) {
            issue_chunk(Ah, Al, Bh, sb + (uint32_t)((c + 2) % NSTAGE) * STAGEB,
                        (c + 2) * 32, tid);
            CP_COMMIT();
        }
        compute_stage(sb + (uint32_t)(c % NSTAGE) * STAGEB, wm, wn, lane, acc);
    }
}

// ---------------------------------------------------------------------------
// Kernel 1: q = RoPE(x @ Wq^T) * SCALE -> bf16 hi/lo [B*NH][T][64]
// ---------------------------------------------------------------------------
__global__ void __launch_bounds__(256, 2) qgemm_rope_kernel()
{
    const int bn = blockIdx.x, bm = blockIdx.y;
    float acc[2][8][4];
    gemm_mainloop(g_x_h + (size_t)bm * 128 * DDIM, g_x_l + (size_t)bm * 128 * DDIM,
                  g_wq_h + (size_t)bn * 128 * DDIM, acc);

    const int tid = threadIdx.x, lane = tid & 31, w = tid >> 5;
    const int wm = w >> 1, wn = w & 1;
    const int h = bn * 2 + wn;
    const int fc = lane & 3;

#pragma unroll
    for (int mt = 0; mt < 2; ++mt) {
        const int m0 = bm * 128 + wm * 32 + mt * 16 + (lane >> 2);
#pragma unroll
        for (int rh = 0; rh < 2; ++rh) {
            const int m = m0 + rh * 8;
            const int b = m >> 12, t = m & 4095;
            size_t rbase = ((size_t)(b * NH + h) * TT + t) * DHD;
#pragma unroll
            for (int nt = 0; nt < 8; ++nt) {
                float e = acc[mt][nt][rh * 2 + 0];
                float o = acc[mt][nt][rh * 2 + 1];
                float ph = (float)t * g_invfreq[nt * 4 + fc];
                float sn, cn;
                sincosf(ph, &sn, &cn);
                float v0 = (e * cn - o * sn) * SCALE;
                float v1 = (e * sn + o * cn) * SCALE;
                uint32_t hi, lo;
                split2(v0, v1, hi, lo);
                *(uint32_t*)(g_q_hi + rbase + nt * 8 + fc * 2) = hi;
                *(uint32_t*)(g_q_lo + rbase + nt * 8 + fc * 2) = lo;
            }
        }
    }
}

// ---------------------------------------------------------------------------
// Kernel 3: out = ao @ Wo^T -> d_out fp32
// ---------------------------------------------------------------------------
__global__ void __launch_bounds__(256, 2) ogemm_kernel(float* __restrict__ out)
{
    const int bn = blockIdx.x, bm = blockIdx.y;
    float acc[2][8][4];
    gemm_mainloop(g_ao_h + (size_t)bm * 128 * DDIM, g_ao_l + (size_t)bm * 128 * DDIM,
                  g_wo_h + (size_t)bn * 128 * DDIM, acc);

    const int tid = threadIdx.x, lane = tid & 31, w = tid >> 5;
    const int wm = w >> 1, wn = w & 1;
    const int col = bn * 128 + wn * 64 + (lane & 3) * 2;

#pragma unroll
    for (int mt = 0; mt < 2; ++mt) {
        const int m0 = bm * 128 + wm * 32 + mt * 16 + (lane >> 2);
#pragma unroll
        for (int rh = 0; rh < 2; ++rh) {
            float* crow = out + (size_t)(m0 + rh * 8) * DDIM + col;
#pragma unroll
            for (int nt = 0; nt < 8; ++nt) {
                float2 v = make_float2(acc[mt][nt][rh * 2 + 0], acc[mt][nt][rh * 2 + 1]);
                *(float2*)(crow + nt * 8) = v;
            }
        }
    }
}

// ---------------------------------------------------------------------------
// Kernel 2: tensor-core windowed causal attention (flash style, bf16 HMMA).
// CTA = 128 q rows x bh. Warp = 16 q rows x 64 keys. Double-buffered K/V.
// ---------------------------------------------------------------------------
#define AT_STRIDE 144
#define AT_TILE   (64 * AT_STRIDE)          // 9216
#define AT_STAGE  (4 * AT_TILE)             // 36864
#define AT_QOFF   (2 * AT_STAGE)            // 73728
#define AT_QTILE  (128 * AT_STRIDE)         // 18432
#define ATTN_SMEM (AT_QOFF + 2 * AT_QTILE)  // 110592

__device__ __forceinline__ void attn_issue(
    const __nv_bfloat16* __restrict__ Kh, const __nv_bfloat16* __restrict__ Kl,
    const __nv_bfloat16* __restrict__ Vh, const __nv_bfloat16* __restrict__ Vl,
    uint32_t stage, int kb, int tid)
{
    const __nv_bfloat16* srcs[4] = {Kh, Kl, Vh, Vl};
#pragma unroll
    for (int t = 0; t < 4; ++t) {
#pragma unroll
        for (int i = 0; i < 2; ++i) {
            int idx = tid + i * 256;               // 0..511
            int r = idx >> 3, c = idx & 7;
            uint64_t src = __cvta_generic_to_global(srcs[t] + (size_t)(kb * 64 + r) * DHD + c * 8);
            uint32_t dst = stage + t * AT_TILE + r * AT_STRIDE + c * 16;
            CP_ASYNC16(dst, src);
        }
    }
}

__global__ void __launch_bounds__(256, 1) attn_kernel()
{
    const int qt = blockIdx.x;                 // 0..31
    const int bh = blockIdx.y;                 // 0..63
    const int b = bh >> 5, h = bh & 31, kvh = h >> 2;
    const int tid = threadIdx.x, lane = tid & 31, w = tid >> 5;
    const uint32_t sb = smem_u32(smraw);
    const int nkb = min(16, 2 * qt + 2);

    const __nv_bfloat16* Kh = g_k_hi + (size_t)(b * NKV + kvh) * WIN * DHD;
    const __nv_bfloat16* Kl = g_k_lo + (size_t)(b * NKV + kvh) * WIN * DHD;
    const __nv_bfloat16* Vh = g_v_hi + (size_t)(b * NKV + kvh) * WIN * DHD;
    const __nv_bfloat16* Vl = g_v_lo + (size_t)(b * NKV + kvh) * WIN * DHD;

    attn_issue(Kh, Kl, Vh, Vl, sb, 0, tid);
    CP_COMMIT();

    {
        const __nv_bfloat16* qh = g_q_hi + ((size_t)bh * TT + (size_t)qt * 128) * DHD;
        const __nv_bfloat16* ql = g_q_lo + ((size_t)bh * TT + (size_t)qt * 128) * DHD;
#pragma unroll
        for (int i = 0; i < 4; ++i) {
            int idx = tid + i * 256;
            int r = idx >> 3, c = idx & 7;
            *(uint4*)(smraw + AT_QOFF + r * AT_STRIDE + c * 16) =
                *(const uint4*)(qh + (size_t)r * DHD + c * 8);
            *(uint4*)(smraw + AT_QOFF + AT_QTILE + r * AT_STRIDE + c * 16) =
                *(const uint4*)(ql + (size_t)r * DHD + c * 8);
        }
    }
    __syncthreads();

    uint32_t qhf[4][4], qlf[4][4];
    {
        uint32_t a_addr = sb + AT_QOFF + (uint32_t)(w * 16 + (lane & 15)) * AT_STRIDE
                        + (uint32_t)((lane >> 4) * 16);
#pragma unroll
        for (int kc = 0; kc < 4; ++kc) {
            ldsm4(qhf[kc], a_addr + kc * 32);
            ldsm4(qlf[kc], a_addr + AT_QTILE + kc * 32);
        }
    }

    float m0 = -INFINITY, m1 = -INFINITY, l0 = 0.f, l1 = 0.f;
    float oac[8][4];
#pragma unroll
    for (int nt = 0; nt < 8; ++nt)
#pragma unroll
        for (int j = 0; j < 4; ++j) oac[nt][j] = 0.f;

    const int trow0 = qt * 128 + w * 16 + (lane >> 2);
    const int scb = (lane & 3) * 2;
    const uint32_t b_off = (uint32_t)(((lane & 7) + ((lane & 16) >> 1)) * AT_STRIDE
                         + ((lane >> 3) & 1) * 16);
    const uint32_t v_off = (uint32_t)((((lane >> 3) & 1) * 8 + (lane & 7)) * AT_STRIDE
                         + (lane >> 4) * 16);

    for (int kb = 0; kb < nkb; ++kb) {
        uint32_t stage = sb + (uint32_t)(kb & 1) * AT_STAGE;
        if (kb + 1 < nkb) {
            attn_issue(Kh, Kl, Vh, Vl, sb + (uint32_t)((kb + 1) & 1) * AT_STAGE, kb + 1, tid);
            CP_COMMIT();
            CP_WAIT1();
        } else {
            CP_WAIT0();
        }
        __syncthreads();

        float sac[8][4];
#pragma unroll
        for (int nt = 0; nt < 8; ++nt)
#pragma unroll
            for (int j = 0; j < 4; ++j) sac[nt][j] = 0.f;

#pragma unroll
        for (int kc = 0; kc < 4; ++kc) {
            uint32_t kf[4][4];
#pragma unroll
            for (int ng = 0; ng < 4; ++ng)
                ldsm4(kf[ng], stage + (uint32_t)(ng * 16) * AT_STRIDE + b_off + kc * 32);
#pragma unroll
            for (int ng = 0; ng < 4; ++ng) {
                mma16816(sac[2 * ng],     qhf[kc], &kf[ng][0]);
                mma16816(sac[2 * ng + 1], qhf[kc], &kf[ng][2]);
            }
#pragma unroll
            for (int ng = 0; ng < 4; ++ng) {
                mma16816(sac[2 * ng],     qlf[kc], &kf[ng][0]);
                mma16816(sac[2 * ng + 1], qlf[kc], &kf[ng][2]);
            }
#pragma unroll
            for (int ng = 0; ng < 4; ++ng)
                ldsm4(kf[ng], stage + AT_TILE + (uint32_t)(ng * 16) * AT_STRIDE + b_off + kc * 32);
#pragma unroll
            for (int ng = 0; ng < 4; ++ng) {
                mma16816(sac[2 * ng],     qhf[kc], &kf[ng][0]);
                mma16816(sac[2 * ng + 1], qhf[kc], &kf[ng][2]);
            }
        }

        if (kb * 64 + 63 > trow0) {
#pragma unroll
            for (int nt = 0; nt < 8; ++nt) {
                int s0 = kb * 64 + nt * 8 + scb;
                if (s0     > trow0)     sac[nt][0] = -INFINITY;
                if (s0 + 1 > trow0)     sac[nt][1] = -INFINITY;
                if (s0     > trow0 + 8) sac[nt][2] = -INFINITY;
                if (s0 + 1 > trow0 + 8) sac[nt][3] = -INFINITY;
            }
        }

        float mx0 = -INFINITY, mx1 = -INFINITY;
#pragma unroll
        for (int nt = 0; nt < 8; ++nt) {
            mx0 = fmaxf(mx0, fmaxf(sac[nt][0], sac[nt][1]));
            mx1 = fmaxf(mx1, fmaxf(sac[nt][2], sac[nt][3]));
        }
        mx0 = fmaxf(mx0, __shfl_xor_sync(0xffffffffu, mx0, 1));
        mx0 = fmaxf(mx0, __shfl_xor_sync(0xffffffffu, mx0, 2));
        mx1 = fmaxf(mx1, __shfl_xor_sync(0xffffffffu, mx1, 1));
        mx1 = fmaxf(mx1, __shfl_xor_sync(0xffffffffu, mx1, 2));

        float mn0 = fmaxf(m0, mx0), mn1 = fmaxf(m1, mx1);
        float cr0 = __expf(m0 - mn0), cr1 = __expf(m1 - mn1);
        float s0 = 0.f, s1 = 0.f;
#pragma unroll
        for (int nt = 0; nt < 8; ++nt) {
            float p0 = __expf(sac[nt][0] - mn0);
            float p1 = __expf(sac[nt][1] - mn0);
            float p2 = __expf(sac[nt][2] - mn1);
            float p3 = __expf(sac[nt][3] - mn1);
            sac[nt][0] = p0; sac[nt][1] = p1; sac[nt][2] = p2; sac[nt][3] = p3;
            s0 += p0 + p1;
            s1 += p2 + p3;
        }
        s0 += __shfl_xor_sync(0xffffffffu, s0, 1);
        s0 += __shfl_xor_sync(0xffffffffu, s0, 2);
        s1 += __shfl_xor_sync(0xffffffffu, s1, 1);
        s1 += __shfl_xor_sync(0xffffffffu, s1, 2);
        l0 = l0 * cr0 + s0;
        l1 = l1 * cr1 + s1;
        m0 = mn0; m1 = mn1;
#pragma unroll
        for (int nt = 0; nt < 8; ++nt) {
            oac[nt][0] *= cr0; oac[nt][1] *= cr0;
            oac[nt][2] *= cr1; oac[nt][3] *= cr1;
        }

#pragma unroll
        for (int kc = 0; kc < 4; ++kc) {
            uint32_t ph[4], pl[4];
            split2(sac[2 * kc][0],     sac[2 * kc][1],     ph[0], pl[0]);
            split2(sac[2 * kc][2],     sac[2 * kc][3],     ph[1], pl[1]);
            split2(sac[2 * kc + 1][0], sac[2 * kc + 1][1], ph[2], pl[2]);
            split2(sac[2 * kc + 1][2], sac[2 * kc + 1][3], ph[3], pl[3]);

            uint32_t vaddr = stage + 2 * AT_TILE + (uint32_t)(kc * 16) * AT_STRIDE + v_off;
#pragma unroll
            for (int nt2 = 0; nt2 < 4; ++nt2) {
                uint32_t f[4];
                ldsm4t(f, vaddr + nt2 * 32);                 // Vh
                mma16816(oac[2 * nt2],     ph, &f[0]);
                mma16816(oac[2 * nt2 + 1], ph, &f[2]);
                mma16816(oac[2 * nt2],     pl, &f[0]);
                mma16816(oac[2 * nt2 + 1], pl, &f[2]);
                ldsm4t(f, vaddr + AT_TILE + nt2 * 32);       // Vl
                mma16816(oac[2 * nt2],     ph, &f[0]);
                mma16816(oac[2 * nt2 + 1], ph, &f[2]);
            }
        }
        __syncthreads();
    }

    // epilogue: O /= l, fp16 hi/lo split store for the Wo GEMM
    float i0 = 1.f / l0, i1 = 1.f / l1;
    size_t base0 = ((size_t)(b * TT) + trow0) * DDIM + h * DHD + scb;
    size_t base1 = base0 + (size_t)8 * DDIM;
#pragma unroll
    for (int nt = 0; nt < 8; ++nt) {
        uint32_t hi, lo;
        split2h(oac[nt][0] * i0, oac[nt][1] * i0, hi, lo);
        *(uint32_t*)(g_ao_h + base0 + nt * 8) = hi;
        *(uint32_t*)(g_ao_l + base0 + nt * 8) = lo;
        split2h(oac[nt][2] * i1, oac[nt][3] * i1, hi, lo);
        *(uint32_t*)(g_ao_h + base1 + nt * 8) = hi;
        *(uint32_t*)(g_ao_l + base1 + nt * 8) = lo;
    }
}

// ---------------------------------------------------------------------------
extern "C" void kernel_launch(void* const* d_in, const int* in_sizes, int n_in,
                              void* d_out, int out_size)
{
    const float* x  = (const float*)d_in[0];
    const float* kc = (const float*)d_in[1];
    const float* vc = (const float*)d_in[2];
    const float* Wq = (const float*)d_in[3];
    const float* Wo = (const float*)d_in[4];
    float* out = (float*)d_out;
    (void)in_sizes; (void)n_in; (void)out_size;

    cudaFuncSetAttribute(attn_kernel, cudaFuncAttributeMaxDynamicSharedMemorySize, ATTN_SMEM);
    cudaFuncSetAttribute(qgemm_rope_kernel, cudaFuncAttributeMaxDynamicSharedMemorySize, GEMM_SMEM);
    cudaFuncSetAttribute(ogemm_kernel, cudaFuncAttributeMaxDynamicSharedMemorySize, GEMM_SMEM);

    __half *xh, *xl, *wqh, *woh;
    cudaGetSymbolAddress((void**)&xh,  g_x_h);
    cudaGetSymbolAddress((void**)&xl,  g_x_l);
    cudaGetSymbolAddress((void**)&wqh, g_wq_h);
    cudaGetSymbolAddress((void**)&woh, g_wo_h);

    initfreq_kernel<<<1, 32>>>();

    const int nx4 = (BB * TT * DDIM) / 4;
    const int nw4 = (DDIM * DDIM) / 4;
    split16_kernel<<<nx4 / 256, 256>>>((const float4*)x,  (uint2*)xh, (uint2*)xl, nx4);
    round16_kernel<<<nw4 / 256, 256>>>((const float4*)Wq, (uint2*)wqh, nw4);
    round16_kernel<<<nw4 / 256, 256>>>((const float4*)Wo, (uint2*)woh, nw4);

    const int nkv4 = (BB * NKV * WIN * DHD) / 4;
    kvsplit_kernel<<<nkv4 / 256, 256>>>((const float4*)kc, (const float4*)vc);

    dim3 ggrid(DDIM / 128, (BB * TT) / 128);   // (16, 64)
    qgemm_rope_kernel<<<ggrid, 256, GEMM_SMEM>>>();

    dim3 agrid(TT / 128, BB * NH);             // (32, 64)
    attn_kernel<<<agrid, 256, ATTN_SMEM>>>();

    ogemm_kernel<<<ggrid, 256, GEMM_SMEM>>>(out);
}

// round 9
// speedup vs baseline: 8.4952x; 1.0889x over previous
#include <cuda_runtime.h>
#include <cuda_bf16.h>
#include <cuda_fp16.h>
#include <math.h>
#include <stdint.h>

// Problem constants
#define BB    2
#define TT    4096
#define DDIM  2048
#define NH    32
#define NKV   8
#define DHD   64
#define TCC   4096
#define WIN   1024
#define WSTART 3072
#define SCALE 0.125f

// ---------------------------------------------------------------------------
// Scratch (device globals — allocation-free rule)
// ---------------------------------------------------------------------------
__device__ __nv_bfloat16 g_q_hi [(size_t)BB * NH * TT * DHD];  // RoPE'd, pre-scaled
__device__ __nv_bfloat16 g_q_lo [(size_t)BB * NH * TT * DHD];
__device__ __nv_bfloat16 g_k_hi [(size_t)BB * NKV * WIN * DHD];
__device__ __nv_bfloat16 g_k_lo [(size_t)BB * NKV * WIN * DHD];
__device__ __nv_bfloat16 g_v_hi [(size_t)BB * NKV * WIN * DHD];
__device__ __nv_bfloat16 g_v_lo [(size_t)BB * NKV * WIN * DHD];
__device__ __half        g_x_h  [(size_t)BB * TT * DDIM];      // fp16 hi
__device__ __half        g_x_l  [(size_t)BB * TT * DDIM];      // fp16 lo (residual)
__device__ __half        g_wq_h [(size_t)DDIM * DDIM];         // fp16 (rounded)
__device__ __half        g_wo_h [(size_t)DDIM * DDIM];
__device__ __half        g_ao_h [(size_t)BB * TT * DDIM];
__device__ __half        g_ao_l [(size_t)BB * TT * DDIM];
__device__ float         g_invfreq[32];

extern __shared__ char smraw[];

// ---------------------------------------------------------------------------
// Helpers (baseline PTX only: ldmatrix / mma.sync / cp.async — all sm_80+)
// ---------------------------------------------------------------------------
__device__ __forceinline__ uint32_t smem_u32(const void* p) {
    uint32_t a;
    asm("{ .reg .u64 t; cvta.to.shared.u64 t, %1; cvt.u32.u64 %0, t; }"
        : "=r"(a) : "l"(p));
    return a;
}

__device__ __forceinline__ void ldsm4(uint32_t* r, uint32_t addr) {
    asm volatile("ldmatrix.sync.aligned.m8n8.x4.shared.b16 {%0,%1,%2,%3}, [%4];"
        : "=r"(r[0]), "=r"(r[1]), "=r"(r[2]), "=r"(r[3]) : "r"(addr));
}

__device__ __forceinline__ void ldsm4t(uint32_t* r, uint32_t addr) {
    asm volatile("ldmatrix.sync.aligned.m8n8.x4.trans.shared.b16 {%0,%1,%2,%3}, [%4];"
        : "=r"(r[0]), "=r"(r[1]), "=r"(r[2]), "=r"(r[3]) : "r"(addr));
}

// bf16 HMMA (attention)
__device__ __forceinline__ void mma16816(float* c, const uint32_t* a, const uint32_t* b) {
    asm("mma.sync.aligned.m16n8k16.row.col.f32.bf16.bf16.f32 "
        "{%0,%1,%2,%3}, {%4,%5,%6,%7}, {%8,%9}, {%0,%1,%2,%3};"
        : "+f"(c[0]), "+f"(c[1]), "+f"(c[2]), "+f"(c[3])
        : "r"(a[0]), "r"(a[1]), "r"(a[2]), "r"(a[3]), "r"(b[0]), "r"(b[1]));
}

// fp16 HMMA (projection GEMMs)
__device__ __forceinline__ void mma16816h(float* c, const uint32_t* a, const uint32_t* b) {
    asm("mma.sync.aligned.m16n8k16.row.col.f32.f16.f16.f32 "
        "{%0,%1,%2,%3}, {%4,%5,%6,%7}, {%8,%9}, {%0,%1,%2,%3};"
        : "+f"(c[0]), "+f"(c[1]), "+f"(c[2]), "+f"(c[3])
        : "r"(a[0]), "r"(a[1]), "r"(a[2]), "r"(a[3]), "r"(b[0]), "r"(b[1]));
}

#define CP_ASYNC16(dst, src) \
    asm volatile("cp.async.cg.shared.global [%0], [%1], 16;" \
                 :: "r"(dst), "l"(src) : "memory")
#define CP_COMMIT() asm volatile("cp.async.commit_group;" ::: "memory")
#define CP_WAIT1()  asm volatile("cp.async.wait_group 1;" ::: "memory")
#define CP_WAIT0()  asm volatile("cp.async.wait_group 0;" ::: "memory")

// bf16 split (attention inputs)
__device__ __forceinline__ void split2(float a, float b, uint32_t& hi, uint32_t& lo) {
    __nv_bfloat16 ha = __float2bfloat16(a), hb = __float2bfloat16(b);
    __nv_bfloat162 hh = __halves2bfloat162(ha, hb);
    hi = *reinterpret_cast<uint32_t*>(&hh);
    __nv_bfloat16 la = __float2bfloat16(a - __bfloat162float(ha));
    __nv_bfloat16 lb = __float2bfloat16(b - __bfloat162float(hb));
    __nv_bfloat162 ll = __halves2bfloat162(la, lb);
    lo = *reinterpret_cast<uint32_t*>(&ll);
}

// fp16 split (GEMM A operands)
__device__ __forceinline__ void split2h(float a, float b, uint32_t& hi, uint32_t& lo) {
    __half ha = __float2half_rn(a), hb = __float2half_rn(b);
    __half2 hh = __halves2half2(ha, hb);
    hi = *reinterpret_cast<uint32_t*>(&hh);
    __half la = __float2half_rn(a - __half2float(ha));
    __half lb = __float2half_rn(b - __half2float(hb));
    __half2 ll = __halves2half2(la, lb);
    lo = *reinterpret_cast<uint32_t*>(&ll);
}

// ---------------------------------------------------------------------------
// Prep kernels
// ---------------------------------------------------------------------------
__global__ void __launch_bounds__(256) split16_kernel(
    const float4* __restrict__ in, uint2* __restrict__ hi, uint2* __restrict__ lo, int n4)
{
    int i = blockIdx.x * 256 + threadIdx.x;
    if (i >= n4) return;
    float4 v = in[i];
    uint2 h, l;
    split2h(v.x, v.y, h.x, l.x);
    split2h(v.z, v.w, h.y, l.y);
    hi[i] = h;
    lo[i] = l;
}

// both weights in one launch: fp32 -> fp16 round
__global__ void __launch_bounds__(256) roundw_kernel(
    const float4* __restrict__ wq, const float4* __restrict__ wo,
    uint2* __restrict__ wqh, uint2* __restrict__ woh, int n4)
{
    int i = blockIdx.x * 256 + threadIdx.x;
    const float4* src = (i < n4) ? wq : wo;
    uint2* dst = (i < n4) ? wqh : woh;
    int j = (i < n4) ? i : i - n4;
    float4 v = src[j];
    __half h[4] = {__float2half_rn(v.x), __float2half_rn(v.y),
                   __float2half_rn(v.z), __float2half_rn(v.w)};
    dst[j] = *(const uint2*)h;
}

// K/V window (last 1024 positions) -> bf16 hi/lo, layout [b][kv][1024][64]
__global__ void __launch_bounds__(256) kvsplit_kernel(
    const float4* __restrict__ kc, const float4* __restrict__ vc)
{
    int idx = blockIdx.x * 256 + threadIdx.x;
    int within = idx & ((WIN * DHD / 4) - 1);
    int bk = idx >> 14;
    size_t src = (size_t)bk * (TCC * DHD / 4) + (WSTART * DHD / 4) + within;
    float4 k4 = kc[src];
    float4 v4 = vc[src];
    float kv_[4] = {k4.x, k4.y, k4.z, k4.w};
    float vv_[4] = {v4.x, v4.y, v4.z, v4.w};
    __nv_bfloat16 kh[4], kl[4], vh[4], vl[4];
#pragma unroll
    for (int j = 0; j < 4; ++j) {
        kh[j] = __float2bfloat16(kv_[j]);
        kl[j] = __float2bfloat16(kv_[j] - __bfloat162float(kh[j]));
        vh[j] = __float2bfloat16(vv_[j]);
        vl[j] = __float2bfloat16(vv_[j] - __bfloat162float(vh[j]));
    }
    ((uint2*)g_k_hi)[idx] = *(const uint2*)kh;
    ((uint2*)g_k_lo)[idx] = *(const uint2*)kl;
    ((uint2*)g_v_hi)[idx] = *(const uint2*)vh;
    ((uint2*)g_v_lo)[idx] = *(const uint2*)vl;
}

__global__ void initfreq_kernel() {
    int i = threadIdx.x;
    g_invfreq[i] = (float)exp(-(double)i * (9.210340371976184 / 32.0));
}

// ---------------------------------------------------------------------------
// GEMM mainloop (fp16 2-pass): acc = Ah.Bh^T + Al.Bh^T
// CTA tile 128x128, 8 warps. K-chunk = 64 fp16 (128B rows + 16B pad = 144B
// stride, LDSM phase-conflict-free). 2-stage cp.async pipeline, 2 CTAs/SM,
// 32 chunks (barriers halved vs 32-wide chunks).
// ---------------------------------------------------------------------------
#define GTILE      (128 * 144)         // 18432
#define GSTAGE     (3 * GTILE)         // 55296 (Ah, Al, Bh)
#define GEMM_SMEM  (2 * GSTAGE)        // 110592

__device__ __forceinline__ void issue_chunk(
    const __half* __restrict__ Ah, const __half* __restrict__ Al,
    const __half* __restrict__ Bh,
    uint32_t stage, int k0, int tid)
{
    const __half* srcs[3] = {Ah, Al, Bh};
#pragma unroll
    for (int t = 0; t < 3; ++t) {
#pragma unroll
        for (int i = 0; i < 4; ++i) {
            int idx = tid + i * 256;            // 0..1023
            int r = idx >> 3, cc = idx & 7;
            uint64_t src = __cvta_generic_to_global(srcs[t] + (size_t)r * DDIM + k0 + cc * 8);
            uint32_t dst = stage + t * GTILE + r * 144 + cc * 16;
            CP_ASYNC16(dst, src);
        }
    }
}

__device__ __forceinline__ void compute_stage(
    uint32_t stage, int wm, int wn, int lane, float acc[2][8][4])
{
    const uint32_t a_off = (uint32_t)((lane & 15) * 144 + (lane >> 4) * 16);
    const uint32_t b_off = (uint32_t)(((lane & 7) + ((lane & 16) >> 1)) * 144
                         + ((lane >> 3) & 1) * 16);

#pragma unroll
    for (int s2 = 0; s2 < 4; ++s2) {
        const uint32_t kb = s2 * 32;           // 16 fp16 = 32 B per sub-step

        uint32_t ah[2][4], al[2][4];
#pragma unroll
        for (int mt = 0; mt < 2; ++mt) {
            uint32_t base = stage + (uint32_t)(wm * 32 + mt * 16) * 144 + a_off + kb;
            ldsm4(ah[mt], base);
            ldsm4(al[mt], base + GTILE);
        }

        uint32_t bfr[8][2];
#pragma unroll
        for (int ng = 0; ng < 4; ++ng) {
            uint32_t base = stage + 2 * GTILE + (uint32_t)(wn * 64 + ng * 16) * 144 + b_off + kb;
            uint32_t t4[4];
            ldsm4(t4, base);
            bfr[ng * 2][0] = t4[0]; bfr[ng * 2][1] = t4[1];
            bfr[ng * 2 + 1][0] = t4[2]; bfr[ng * 2 + 1][1] = t4[3];
        }
        // pass 1: Ah.Bh — 16 independent MMAs
#pragma unroll
        for (int mt = 0; mt < 2; ++mt)
#pragma unroll
            for (int nt = 0; nt < 8; ++nt)
                mma16816h(acc[mt][nt], ah[mt], bfr[nt]);
        // pass 2: Al.Bh — 16 independent MMAs
#pragma unroll
        for (int mt = 0; mt < 2; ++mt)
#pragma unroll
            for (int nt = 0; nt < 8; ++nt)
                mma16816h(acc[mt][nt], al[mt], bfr[nt]);
    }
}

__device__ __forceinline__ void gemm_mainloop(
    const __half* __restrict__ Ah, const __half* __restrict__ Al,
    const __half* __restrict__ Bh,
    float acc[2][8][4])
{
    const uint32_t sb = smem_u32(smraw);
    const int tid = threadIdx.x;
    const int lane = tid & 31, w = tid >> 5;
    const int wm = w >> 1, wn = w & 1;

#pragma unroll
    for (int mt = 0; mt < 2; ++mt)
#pragma unroll
        for (int nt = 0; nt < 8; ++nt)
#pragma unroll
            for (int j = 0; j < 4; ++j) acc[mt][nt][j] = 0.f;

    issue_chunk(Ah, Al, Bh, sb, 0, tid);
    CP_COMMIT();

    for (int c = 0; c < 32; ++c) {
        CP_WAIT0();          // chunk c landed
        __syncthreads();     // all warps done with the other stage
        if (c + 1 < 32) {    // prefetch c+1, overlaps compute of c
            issue_chunk(Ah, Al, Bh, sb + (uint32_t)((c + 1) & 1) * GSTAGE,
                        (c + 1) * 64, tid);
            CP_COMMIT();
        }
        compute_stage(sb + (uint32_t)(c & 1) * GSTAGE, wm, wn, lane, acc);
    }
}

// ---------------------------------------------------------------------------
// Kernel 1: q = RoPE(x @ Wq^T) * SCALE -> bf16 hi/lo [B*NH][T][64]
// ---------------------------------------------------------------------------
__global__ void __launch_bounds__(256, 2) qgemm_rope_kernel()
{
    const int bn = blockIdx.x, bm = blockIdx.y;
    float acc[2][8][4];
    gemm_mainloop(g_x_h + (size_t)bm * 128 * DDIM, g_x_l + (size_t)bm * 128 * DDIM,
                  g_wq_h + (size_t)bn * 128 * DDIM, acc);

    const int tid = threadIdx.x, lane = tid & 31, w = tid >> 5;
    const int wm = w >> 1, wn = w & 1;
    const int h = bn * 2 + wn;
    const int fc = lane & 3;

#pragma unroll
    for (int mt = 0; mt < 2; ++mt) {
        const int m0 = bm * 128 + wm * 32 + mt * 16 + (lane >> 2);
#pragma unroll
        for (int rh = 0; rh < 2; ++rh) {
            const int m = m0 + rh * 8;
            const int b = m >> 12, t = m & 4095;
            size_t rbase = ((size_t)(b * NH + h) * TT + t) * DHD;
#pragma unroll
            for (int nt = 0; nt < 8; ++nt) {
                float e = acc[mt][nt][rh * 2 + 0];
                float o = acc[mt][nt][rh * 2 + 1];
                float ph = (float)t * g_invfreq[nt * 4 + fc];
                float sn, cn;
                sincosf(ph, &sn, &cn);
                float v0 = (e * cn - o * sn) * SCALE;
                float v1 = (e * sn + o * cn) * SCALE;
                uint32_t hi, lo;
                split2(v0, v1, hi, lo);
                *(uint32_t*)(g_q_hi + rbase + nt * 8 + fc * 2) = hi;
                *(uint32_t*)(g_q_lo + rbase + nt * 8 + fc * 2) = lo;
            }
        }
    }
}

// ---------------------------------------------------------------------------
// Kernel 3: out = ao @ Wo^T -> d_out fp32
// ---------------------------------------------------------------------------
__global__ void __launch_bounds__(256, 2) ogemm_kernel(float* __restrict__ out)
{
    const int bn = blockIdx.x, bm = blockIdx.y;
    float acc[2][8][4];
    gemm_mainloop(g_ao_h + (size_t)bm * 128 * DDIM, g_ao_l + (size_t)bm * 128 * DDIM,
                  g_wo_h + (size_t)bn * 128 * DDIM, acc);

    const int tid = threadIdx.x, lane = tid & 31, w = tid >> 5;
    const int wm = w >> 1, wn = w & 1;
    const int col = bn * 128 + wn * 64 + (lane & 3) * 2;

#pragma unroll
    for (int mt = 0; mt < 2; ++mt) {
        const int m0 = bm * 128 + wm * 32 + mt * 16 + (lane >> 2);
#pragma unroll
        for (int rh = 0; rh < 2; ++rh) {
            float* crow = out + (size_t)(m0 + rh * 8) * DDIM + col;
#pragma unroll
            for (int nt = 0; nt < 8; ++nt) {
                float2 v = make_float2(acc[mt][nt][rh * 2 + 0], acc[mt][nt][rh * 2 + 1]);
                *(float2*)(crow + nt * 8) = v;
            }
        }
    }
}

// ---------------------------------------------------------------------------
// Kernel 2: tensor-core windowed causal attention (flash style, bf16 HMMA).
// CTA = 128 q rows x bh. Q staged through stage-0 buffer (no dedicated Q
// area) -> smem 73.7KB -> 2 CTAs/SM with __launch_bounds__(256, 2).
// ---------------------------------------------------------------------------
#define AT_STRIDE 144
#define AT_TILE   (64 * AT_STRIDE)          // 9216
#define AT_STAGE  (4 * AT_TILE)             // 36864
#define ATTN_SMEM (2 * AT_STAGE)            // 73728

__device__ __forceinline__ void attn_issue(
    const __nv_bfloat16* __restrict__ Kh, const __nv_bfloat16* __restrict__ Kl,
    const __nv_bfloat16* __restrict__ Vh, const __nv_bfloat16* __restrict__ Vl,
    uint32_t stage, int kb, int tid)
{
    const __nv_bfloat16* srcs[4] = {Kh, Kl, Vh, Vl};
#pragma unroll
    for (int t = 0; t < 4; ++t) {
#pragma unroll
        for (int i = 0; i < 2; ++i) {
            int idx = tid + i * 256;
            int r = idx >> 3, c = idx & 7;
            uint64_t src = __cvta_generic_to_global(srcs[t] + (size_t)(kb * 64 + r) * DHD + c * 8);
            uint32_t dst = stage + t * AT_TILE + r * AT_STRIDE + c * 16;
            CP_ASYNC16(dst, src);
        }
    }
}

__global__ void __launch_bounds__(256, 2) attn_kernel()
{
    const int qt = blockIdx.x;                 // 0..31
    const int bh = blockIdx.y;                 // 0..63
    const int b = bh >> 5, h = bh & 31, kvh = h >> 2;
    const int tid = threadIdx.x, lane = tid & 31, w = tid >> 5;
    const uint32_t sb = smem_u32(smraw);
    const int nkb = min(16, 2 * qt + 2);

    const __nv_bfloat16* Kh = g_k_hi + (size_t)(b * NKV + kvh) * WIN * DHD;
    const __nv_bfloat16* Kl = g_k_lo + (size_t)(b * NKV + kvh) * WIN * DHD;
    const __nv_bfloat16* Vh = g_v_hi + (size_t)(b * NKV + kvh) * WIN * DHD;
    const __nv_bfloat16* Vl = g_v_lo + (size_t)(b * NKV + kvh) * WIN * DHD;

    // Stage Q (128 x 64 hi/lo = 36864 B) through stage-0 buffer
    {
        const __nv_bfloat16* qh = g_q_hi + ((size_t)bh * TT + (size_t)qt * 128) * DHD;
        const __nv_bfloat16* ql = g_q_lo + ((size_t)bh * TT + (size_t)qt * 128) * DHD;
#pragma unroll
        for (int i = 0; i < 4; ++i) {
            int idx = tid + i * 256;
            int r = idx >> 3, c = idx & 7;
            *(uint4*)(smraw + r * AT_STRIDE + c * 16) =
                *(const uint4*)(qh + (size_t)r * DHD + c * 8);
            *(uint4*)(smraw + 2 * AT_TILE + r * AT_STRIDE + c * 16) =
                *(const uint4*)(ql + (size_t)r * DHD + c * 8);
        }
    }
    __syncthreads();

    uint32_t qhf[4][4], qlf[4][4];
    {
        uint32_t a_addr = sb + (uint32_t)(w * 16 + (lane & 15)) * AT_STRIDE
                        + (uint32_t)((lane >> 4) * 16);
#pragma unroll
        for (int kc = 0; kc < 4; ++kc) {
            ldsm4(qhf[kc], a_addr + kc * 32);
            ldsm4(qlf[kc], a_addr + 2 * AT_TILE + kc * 32);
        }
    }
    __syncthreads();   // all warps hold Q fragments; stage-0 can be overwritten

    // now start the K/V pipeline in stage 0
    attn_issue(Kh, Kl, Vh, Vl, sb, 0, tid);
    CP_COMMIT();

    float m0 = -INFINITY, m1 = -INFINITY, l0 = 0.f, l1 = 0.f;
    float oac[8][4];
#pragma unroll
    for (int nt = 0; nt < 8; ++nt)
#pragma unroll
        for (int j = 0; j < 4; ++j) oac[nt][j] = 0.f;

    const int trow0 = qt * 128 + w * 16 + (lane >> 2);
    const int scb = (lane & 3) * 2;
    const uint32_t b_off = (uint32_t)(((lane & 7) + ((lane & 16) >> 1)) * AT_STRIDE
                         + ((lane >> 3) & 1) * 16);
    const uint32_t v_off = (uint32_t)((((lane >> 3) & 1) * 8 + (lane & 7)) * AT_STRIDE
                         + (lane >> 4) * 16);

    for (int kb = 0; kb < nkb; ++kb) {
        uint32_t stage = sb + (uint32_t)(kb & 1) * AT_STAGE;
        if (kb + 1 < nkb) {
            attn_issue(Kh, Kl, Vh, Vl, sb + (uint32_t)((kb + 1) & 1) * AT_STAGE, kb + 1, tid);
            CP_COMMIT();
            CP_WAIT1();
        } else {
            CP_WAIT0();
        }
        __syncthreads();

        float sac[8][4];
#pragma unroll
        for (int nt = 0; nt < 8; ++nt)
#pragma unroll
            for (int j = 0; j < 4; ++j) sac[nt][j] = 0.f;

#pragma unroll
        for (int kc = 0; kc < 4; ++kc) {
            uint32_t kf[4][4];
#pragma unroll
            for (int ng = 0; ng < 4; ++ng)
                ldsm4(kf[ng], stage + (uint32_t)(ng * 16) * AT_STRIDE + b_off + kc * 32);
#pragma unroll
            for (int ng = 0; ng < 4; ++ng) {
                mma16816(sac[2 * ng],     qhf[kc], &kf[ng][0]);
                mma16816(sac[2 * ng + 1], qhf[kc], &kf[ng][2]);
            }
#pragma unroll
            for (int ng = 0; ng < 4; ++ng) {
                mma16816(sac[2 * ng],     qlf[kc], &kf[ng][0]);
                mma16816(sac[2 * ng + 1], qlf[kc], &kf[ng][2]);
            }
#pragma unroll
            for (int ng = 0; ng < 4; ++ng)
                ldsm4(kf[ng], stage + AT_TILE + (uint32_t)(ng * 16) * AT_STRIDE + b_off + kc * 32);
#pragma unroll
            for (int ng = 0; ng < 4; ++ng) {
                mma16816(sac[2 * ng],     qhf[kc], &kf[ng][0]);
                mma16816(sac[2 * ng + 1], qhf[kc], &kf[ng][2]);
            }
        }

        if (kb * 64 + 63 > trow0) {
#pragma unroll
            for (int nt = 0; nt < 8; ++nt) {
                int s0 = kb * 64 + nt * 8 + scb;
                if (s0     > trow0)     sac[nt][0] = -INFINITY;
                if (s0 + 1 > trow0)     sac[nt][1] = -INFINITY;
                if (s0     > trow0 + 8) sac[nt][2] = -INFINITY;
                if (s0 + 1 > trow0 + 8) sac[nt][3] = -INFINITY;
            }
        }

        float mx0 = -INFINITY, mx1 = -INFINITY;
#pragma unroll
        for (int nt = 0; nt < 8; ++nt) {
            mx0 = fmaxf(mx0, fmaxf(sac[nt][0], sac[nt][1]));
            mx1 = fmaxf(mx1, fmaxf(sac[nt][2], sac[nt][3]));
        }
        mx0 = fmaxf(mx0, __shfl_xor_sync(0xffffffffu, mx0, 1));
        mx0 = fmaxf(mx0, __shfl_xor_sync(0xffffffffu, mx0, 2));
        mx1 = fmaxf(mx1, __shfl_xor_sync(0xffffffffu, mx1, 1));
        mx1 = fmaxf(mx1, __shfl_xor_sync(0xffffffffu, mx1, 2));

        float mn0 = fmaxf(m0, mx0), mn1 = fmaxf(m1, mx1);
        float cr0 = __expf(m0 - mn0), cr1 = __expf(m1 - mn1);
        float s0 = 0.f, s1 = 0.f;
#pragma unroll
        for (int nt = 0; nt < 8; ++nt) {
            float p0 = __expf(sac[nt][0] - mn0);
            float p1 = __expf(sac[nt][1] - mn0);
            float p2 = __expf(sac[nt][2] - mn1);
            float p3 = __expf(sac[nt][3] - mn1);
            sac[nt][0] = p0; sac[nt][1] = p1; sac[nt][2] = p2; sac[nt][3] = p3;
            s0 += p0 + p1;
            s1 += p2 + p3;
        }
        s0 += __shfl_xor_sync(0xffffffffu, s0, 1);
        s0 += __shfl_xor_sync(0xffffffffu, s0, 2);
        s1 += __shfl_xor_sync(0xffffffffu, s1, 1);
        s1 += __shfl_xor_sync(0xffffffffu, s1, 2);
        l0 = l0 * cr0 + s0;
        l1 = l1 * cr1 + s1;
        m0 = mn0; m1 = mn1;
#pragma unroll
        for (int nt = 0; nt < 8; ++nt) {
            oac[nt][0] *= cr0; oac[nt][1] *= cr0;
            oac[nt][2] *= cr1; oac[nt][3] *= cr1;
        }

#pragma unroll
        for (int kc = 0; kc < 4; ++kc) {
            uint32_t ph[4], pl[4];
            split2(sac[2 * kc][0],     sac[2 * kc][1],     ph[0], pl[0]);
            split2(sac[2 * kc][2],     sac[2 * kc][3],     ph[1], pl[1]);
            split2(sac[2 * kc + 1][0], sac[2 * kc + 1][1], ph[2], pl[2]);
            split2(sac[2 * kc + 1][2], sac[2 * kc + 1][3], ph[3], pl[3]);

            uint32_t vaddr = stage + 2 * AT_TILE + (uint32_t)(kc * 16) * AT_STRIDE + v_off;
#pragma unroll
            for (int nt2 = 0; nt2 < 4; ++nt2) {
                uint32_t f[4];
                ldsm4t(f, vaddr + nt2 * 32);                 // Vh
                mma16816(oac[2 * nt2],     ph, &f[0]);
                mma16816(oac[2 * nt2 + 1], ph, &f[2]);
                mma16816(oac[2 * nt2],     pl, &f[0]);
                mma16816(oac[2 * nt2 + 1], pl, &f[2]);
                ldsm4t(f, vaddr + AT_TILE + nt2 * 32);       // Vl
                mma16816(oac[2 * nt2],     ph, &f[0]);
                mma16816(oac[2 * nt2 + 1], ph, &f[2]);
            }
        }
        __syncthreads();
    }

    // epilogue: O /= l, fp16 hi/lo split store for the Wo GEMM
    float i0 = 1.f / l0, i1 = 1.f / l1;
    size_t base0 = ((size_t)(b * TT) + trow0) * DDIM + h * DHD + scb;
    size_t base1 = base0 + (size_t)8 * DDIM;
#pragma unroll
    for (int nt = 0; nt < 8; ++nt) {
        uint32_t hi, lo;
        split2h(oac[nt][0] * i0, oac[nt][1] * i0, hi, lo);
        *(uint32_t*)(g_ao_h + base0 + nt * 8) = hi;
        *(uint32_t*)(g_ao_l + base0 + nt * 8) = lo;
        split2h(oac[nt][2] * i1, oac[nt][3] * i1, hi, lo);
        *(uint32_t*)(g_ao_h + base1 + nt * 8) = hi;
        *(uint32_t*)(g_ao_l + base1 + nt * 8) = lo;
    }
}

// ---------------------------------------------------------------------------
extern "C" void kernel_launch(void* const* d_in, const int* in_sizes, int n_in,
                              void* d_out, int out_size)
{
    const float* x  = (const float*)d_in[0];
    const float* kc = (const float*)d_in[1];
    const float* vc = (const float*)d_in[2];
    const float* Wq = (const float*)d_in[3];
    const float* Wo = (const float*)d_in[4];
    float* out = (float*)d_out;
    (void)in_sizes; (void)n_in; (void)out_size;

    cudaFuncSetAttribute(attn_kernel, cudaFuncAttributeMaxDynamicSharedMemorySize, ATTN_SMEM);
    cudaFuncSetAttribute(qgemm_rope_kernel, cudaFuncAttributeMaxDynamicSharedMemorySize, GEMM_SMEM);
    cudaFuncSetAttribute(ogemm_kernel, cudaFuncAttributeMaxDynamicSharedMemorySize, GEMM_SMEM);

    __half *xh, *xl, *wqh, *woh;
    cudaGetSymbolAddress((void**)&xh,  g_x_h);
    cudaGetSymbolAddress((void**)&xl,  g_x_l);
    cudaGetSymbolAddress((void**)&wqh, g_wq_h);
    cudaGetSymbolAddress((void**)&woh, g_wo_h);

    initfreq_kernel<<<1, 32>>>();

    const int nx4 = (BB * TT * DDIM) / 4;
    const int nw4 = (DDIM * DDIM) / 4;
    split16_kernel<<<nx4 / 256, 256>>>((const float4*)x,  (uint2*)xh, (uint2*)xl, nx4);
    roundw_kernel<<<(2 * nw4) / 256, 256>>>((const float4*)Wq, (const float4*)Wo,
                                            (uint2*)wqh, (uint2*)woh, nw4);

    const int nkv4 = (BB * NKV * WIN * DHD) / 4;
    kvsplit_kernel<<<nkv4 / 256, 256>>>((const float4*)kc, (const float4*)vc);

    dim3 ggrid(DDIM / 128, (BB * TT) / 128);   // (16, 64)
    qgemm_rope_kernel<<<ggrid, 256, GEMM_SMEM>>>();

    dim3 agrid(TT / 128, BB * NH);             // (32, 64)
    attn_kernel<<<agrid, 256, ATTN_SMEM>>>();

    ogemm_kernel<<<ggrid, 256, GEMM_SMEM>>>(out);
}

// round 10
// speedup vs baseline: 11.1853x; 1.3167x over previous
#include <cuda_runtime.h>
#include <cuda_bf16.h>
#include <cuda_fp16.h>
#include <math.h>
#include <stdint.h>

// Problem constants
#define BB    2
#define TT    4096
#define DDIM  2048
#define NH    32
#define NKV   8
#define DHD   64
#define TCC   4096
#define WIN   1024
#define WSTART 3072
#define SCALE 0.125f

// ---------------------------------------------------------------------------
// Scratch (device globals — allocation-free rule)
// ---------------------------------------------------------------------------
__device__ __nv_bfloat16 g_q_hi [(size_t)BB * NH * TT * DHD];  // RoPE'd, pre-scaled
__device__ __nv_bfloat16 g_q_lo [(size_t)BB * NH * TT * DHD];
__device__ __nv_bfloat16 g_k_hi [(size_t)BB * NKV * WIN * DHD];
__device__ __nv_bfloat16 g_k_lo [(size_t)BB * NKV * WIN * DHD];
__device__ __nv_bfloat16 g_v_hi [(size_t)BB * NKV * WIN * DHD];
__device__ __nv_bfloat16 g_v_lo [(size_t)BB * NKV * WIN * DHD];
__device__ __half        g_x_h  [(size_t)BB * TT * DDIM];      // fp16 (rounded)
__device__ __half        g_wq_h [(size_t)DDIM * DDIM];
__device__ __half        g_wo_h [(size_t)DDIM * DDIM];
__device__ __half        g_ao_h [(size_t)BB * TT * DDIM];
__device__ float         g_invfreq[32];

extern __shared__ char smraw[];

// ---------------------------------------------------------------------------
// Helpers (baseline PTX only: ldmatrix / mma.sync / cp.async — all sm_80+)
// ---------------------------------------------------------------------------
__device__ __forceinline__ uint32_t smem_u32(const void* p) {
    uint32_t a;
    asm("{ .reg .u64 t; cvta.to.shared.u64 t, %1; cvt.u32.u64 %0, t; }"
        : "=r"(a) : "l"(p));
    return a;
}

__device__ __forceinline__ void ldsm4(uint32_t* r, uint32_t addr) {
    asm volatile("ldmatrix.sync.aligned.m8n8.x4.shared.b16 {%0,%1,%2,%3}, [%4];"
        : "=r"(r[0]), "=r"(r[1]), "=r"(r[2]), "=r"(r[3]) : "r"(addr));
}

__device__ __forceinline__ void ldsm4t(uint32_t* r, uint32_t addr) {
    asm volatile("ldmatrix.sync.aligned.m8n8.x4.trans.shared.b16 {%0,%1,%2,%3}, [%4];"
        : "=r"(r[0]), "=r"(r[1]), "=r"(r[2]), "=r"(r[3]) : "r"(addr));
}

// bf16 HMMA (attention)
__device__ __forceinline__ void mma16816(float* c, const uint32_t* a, const uint32_t* b) {
    asm("mma.sync.aligned.m16n8k16.row.col.f32.bf16.bf16.f32 "
        "{%0,%1,%2,%3}, {%4,%5,%6,%7}, {%8,%9}, {%0,%1,%2,%3};"
        : "+f"(c[0]), "+f"(c[1]), "+f"(c[2]), "+f"(c[3])
        : "r"(a[0]), "r"(a[1]), "r"(a[2]), "r"(a[3]), "r"(b[0]), "r"(b[1]));
}

// fp16 HMMA (projection GEMMs)
__device__ __forceinline__ void mma16816h(float* c, const uint32_t* a, const uint32_t* b) {
    asm("mma.sync.aligned.m16n8k16.row.col.f32.f16.f16.f32 "
        "{%0,%1,%2,%3}, {%4,%5,%6,%7}, {%8,%9}, {%0,%1,%2,%3};"
        : "+f"(c[0]), "+f"(c[1]), "+f"(c[2]), "+f"(c[3])
        : "r"(a[0]), "r"(a[1]), "r"(a[2]), "r"(a[3]), "r"(b[0]), "r"(b[1]));
}

#define CP_ASYNC16(dst, src) \
    asm volatile("cp.async.cg.shared.global [%0], [%1], 16;" \
                 :: "r"(dst), "l"(src) : "memory")
#define CP_COMMIT() asm volatile("cp.async.commit_group;" ::: "memory")
#define CP_WAIT1()  asm volatile("cp.async.wait_group 1;" ::: "memory")
#define CP_WAIT0()  asm volatile("cp.async.wait_group 0;" ::: "memory")

// bf16 split (attention inputs)
__device__ __forceinline__ void split2(float a, float b, uint32_t& hi, uint32_t& lo) {
    __nv_bfloat16 ha = __float2bfloat16(a), hb = __float2bfloat16(b);
    __nv_bfloat162 hh = __halves2bfloat162(ha, hb);
    hi = *reinterpret_cast<uint32_t*>(&hh);
    __nv_bfloat16 la = __float2bfloat16(a - __bfloat162float(ha));
    __nv_bfloat16 lb = __float2bfloat16(b - __bfloat162float(hb));
    __nv_bfloat162 ll = __halves2bfloat162(la, lb);
    lo = *reinterpret_cast<uint32_t*>(&ll);
}

// ---------------------------------------------------------------------------
// Prep kernels
// ---------------------------------------------------------------------------
// fp32 -> fp16 round
__global__ void __launch_bounds__(256) round16_kernel(
    const float4* __restrict__ in, uint2* __restrict__ out, int n4)
{
    int i = blockIdx.x * 256 + threadIdx.x;
    if (i >= n4) return;
    float4 v = in[i];
    __half h[4] = {__float2half_rn(v.x), __float2half_rn(v.y),
                   __float2half_rn(v.z), __float2half_rn(v.w)};
    out[i] = *(const uint2*)h;
}

// K/V window (last 1024 positions) -> bf16 hi/lo, layout [b][kv][1024][64]
__global__ void __launch_bounds__(256) kvsplit_kernel(
    const float4* __restrict__ kc, const float4* __restrict__ vc)
{
    int idx = blockIdx.x * 256 + threadIdx.x;
    int within = idx & ((WIN * DHD / 4) - 1);
    int bk = idx >> 14;
    size_t src = (size_t)bk * (TCC * DHD / 4) + (WSTART * DHD / 4) + within;
    float4 k4 = kc[src];
    float4 v4 = vc[src];
    float kv_[4] = {k4.x, k4.y, k4.z, k4.w};
    float vv_[4] = {v4.x, v4.y, v4.z, v4.w};
    __nv_bfloat16 kh[4], kl[4], vh[4], vl[4];
#pragma unroll
    for (int j = 0; j < 4; ++j) {
        kh[j] = __float2bfloat16(kv_[j]);
        kl[j] = __float2bfloat16(kv_[j] - __bfloat162float(kh[j]));
        vh[j] = __float2bfloat16(vv_[j]);
        vl[j] = __float2bfloat16(vv_[j] - __bfloat162float(vh[j]));
    }
    ((uint2*)g_k_hi)[idx] = *(const uint2*)kh;
    ((uint2*)g_k_lo)[idx] = *(const uint2*)kl;
    ((uint2*)g_v_hi)[idx] = *(const uint2*)vh;
    ((uint2*)g_v_lo)[idx] = *(const uint2*)vl;
}

__global__ void initfreq_kernel() {
    int i = threadIdx.x;
    g_invfreq[i] = (float)exp(-(double)i * (9.210340371976184 / 32.0));
}

// ---------------------------------------------------------------------------
// GEMM mainloop (single-pass fp16): acc = A.B^T, fp32 accum.
// CTA tile 128x128, 8 warps. K-chunk = 64 fp16 (144B stride, LDSM
// conflict-free). 3-stage cp.async pipeline, 2 CTAs/SM, 32 chunks.
// ---------------------------------------------------------------------------
#define GTILE      (128 * 144)         // 18432
#define GSTAGE     (2 * GTILE)         // 36864 (A, B)
#define NSTAGE     3
#define GEMM_SMEM  (NSTAGE * GSTAGE)   // 110592

__device__ __forceinline__ void issue_chunk(
    const __half* __restrict__ A, const __half* __restrict__ B,
    uint32_t stage, int k0, int tid)
{
    const __half* srcs[2] = {A, B};
#pragma unroll
    for (int t = 0; t < 2; ++t) {
#pragma unroll
        for (int i = 0; i < 4; ++i) {
            int idx = tid + i * 256;            // 0..1023
            int r = idx >> 3, cc = idx & 7;
            uint64_t src = __cvta_generic_to_global(srcs[t] + (size_t)r * DDIM + k0 + cc * 8);
            uint32_t dst = stage + t * GTILE + r * 144 + cc * 16;
            CP_ASYNC16(dst, src);
        }
    }
}

__device__ __forceinline__ void compute_stage(
    uint32_t stage, int wm, int wn, int lane, float acc[2][8][4])
{
    const uint32_t a_off = (uint32_t)((lane & 15) * 144 + (lane >> 4) * 16);
    const uint32_t b_off = (uint32_t)(((lane & 7) + ((lane & 16) >> 1)) * 144
                         + ((lane >> 3) & 1) * 16);

#pragma unroll
    for (int s2 = 0; s2 < 4; ++s2) {
        const uint32_t kb = s2 * 32;           // 16 fp16 = 32 B per sub-step

        uint32_t af[2][4];
#pragma unroll
        for (int mt = 0; mt < 2; ++mt)
            ldsm4(af[mt], stage + (uint32_t)(wm * 32 + mt * 16) * 144 + a_off + kb);

        uint32_t bfr[8][2];
#pragma unroll
        for (int ng = 0; ng < 4; ++ng) {
            uint32_t base = stage + GTILE + (uint32_t)(wn * 64 + ng * 16) * 144 + b_off + kb;
            uint32_t t4[4];
            ldsm4(t4, base);
            bfr[ng * 2][0] = t4[0]; bfr[ng * 2][1] = t4[1];
            bfr[ng * 2 + 1][0] = t4[2]; bfr[ng * 2 + 1][1] = t4[3];
        }
        // 16 independent MMAs
#pragma unroll
        for (int mt = 0; mt < 2; ++mt)
#pragma unroll
            for (int nt = 0; nt < 8; ++nt)
                mma16816h(acc[mt][nt], af[mt], bfr[nt]);
    }
}

__device__ __forceinline__ void gemm_mainloop(
    const __half* __restrict__ A, const __half* __restrict__ B,
    float acc[2][8][4])
{
    const uint32_t sb = smem_u32(smraw);
    const int tid = threadIdx.x;
    const int lane = tid & 31, w = tid >> 5;
    const int wm = w >> 1, wn = w & 1;

#pragma unroll
    for (int mt = 0; mt < 2; ++mt)
#pragma unroll
        for (int nt = 0; nt < 8; ++nt)
#pragma unroll
            for (int j = 0; j < 4; ++j) acc[mt][nt][j] = 0.f;

    issue_chunk(A, B, sb + 0 * GSTAGE, 0,  tid);
    CP_COMMIT();
    issue_chunk(A, B, sb + 1 * GSTAGE, 64, tid);
    CP_COMMIT();

    for (int c = 0; c < 32; ++c) {
        if (c + 2 < 32) CP_WAIT1(); else CP_WAIT0();
        __syncthreads();
        if (c + 2 < 32) {
            issue_chunk(A, B, sb + (uint32_t)((c + 2) % NSTAGE) * GSTAGE,
                        (c + 2) * 64, tid);
            CP_COMMIT();
        }
        compute_stage(sb + (uint32_t)(c % NSTAGE) * GSTAGE, wm, wn, lane, acc);
    }
}

// ---------------------------------------------------------------------------
// Kernel 1: q = RoPE(x @ Wq^T) * SCALE -> bf16 hi/lo [B*NH][T][64]
// ---------------------------------------------------------------------------
__global__ void __launch_bounds__(256, 2) qgemm_rope_kernel()
{
    const int bn = blockIdx.x, bm = blockIdx.y;
    float acc[2][8][4];
    gemm_mainloop(g_x_h + (size_t)bm * 128 * DDIM,
                  g_wq_h + (size_t)bn * 128 * DDIM, acc);

    const int tid = threadIdx.x, lane = tid & 31, w = tid >> 5;
    const int wm = w >> 1, wn = w & 1;
    const int h = bn * 2 + wn;
    const int fc = lane & 3;

#pragma unroll
    for (int mt = 0; mt < 2; ++mt) {
        const int m0 = bm * 128 + wm * 32 + mt * 16 + (lane >> 2);
#pragma unroll
        for (int rh = 0; rh < 2; ++rh) {
            const int m = m0 + rh * 8;
            const int b = m >> 12, t = m & 4095;
            size_t rbase = ((size_t)(b * NH + h) * TT + t) * DHD;
#pragma unroll
            for (int nt = 0; nt < 8; ++nt) {
                float e = acc[mt][nt][rh * 2 + 0];
                float o = acc[mt][nt][rh * 2 + 1];
                float ph = (float)t * g_invfreq[nt * 4 + fc];
                float sn, cn;
                sincosf(ph, &sn, &cn);
                float v0 = (e * cn - o * sn) * SCALE;
                float v1 = (e * sn + o * cn) * SCALE;
                uint32_t hi, lo;
                split2(v0, v1, hi, lo);
                *(uint32_t*)(g_q_hi + rbase + nt * 8 + fc * 2) = hi;
                *(uint32_t*)(g_q_lo + rbase + nt * 8 + fc * 2) = lo;
            }
        }
    }
}

// ---------------------------------------------------------------------------
// Kernel 3: out = ao @ Wo^T -> d_out fp32
// ---------------------------------------------------------------------------
__global__ void __launch_bounds__(256, 2) ogemm_kernel(float* __restrict__ out)
{
    const int bn = blockIdx.x, bm = blockIdx.y;
    float acc[2][8][4];
    gemm_mainloop(g_ao_h + (size_t)bm * 128 * DDIM,
                  g_wo_h + (size_t)bn * 128 * DDIM, acc);

    const int tid = threadIdx.x, lane = tid & 31, w = tid >> 5;
    const int wm = w >> 1, wn = w & 1;
    const int col = bn * 128 + wn * 64 + (lane & 3) * 2;

#pragma unroll
    for (int mt = 0; mt < 2; ++mt) {
        const int m0 = bm * 128 + wm * 32 + mt * 16 + (lane >> 2);
#pragma unroll
        for (int rh = 0; rh < 2; ++rh) {
            float* crow = out + (size_t)(m0 + rh * 8) * DDIM + col;
#pragma unroll
            for (int nt = 0; nt < 8; ++nt) {
                float2 v = make_float2(acc[mt][nt][rh * 2 + 0], acc[mt][nt][rh * 2 + 1]);
                *(float2*)(crow + nt * 8) = v;
            }
        }
    }
}

// ---------------------------------------------------------------------------
// Kernel 2: tensor-core windowed causal attention (flash style, bf16 HMMA).
// CTA = 128 q rows x bh. Q staged through stage-0 buffer. 2 CTAs/SM.
// ---------------------------------------------------------------------------
#define AT_STRIDE 144
#define AT_TILE   (64 * AT_STRIDE)          // 9216
#define AT_STAGE  (4 * AT_TILE)             // 36864
#define ATTN_SMEM (2 * AT_STAGE)            // 73728

__device__ __forceinline__ void attn_issue(
    const __nv_bfloat16* __restrict__ Kh, const __nv_bfloat16* __restrict__ Kl,
    const __nv_bfloat16* __restrict__ Vh, const __nv_bfloat16* __restrict__ Vl,
    uint32_t stage, int kb, int tid)
{
    const __nv_bfloat16* srcs[4] = {Kh, Kl, Vh, Vl};
#pragma unroll
    for (int t = 0; t < 4; ++t) {
#pragma unroll
        for (int i = 0; i < 2; ++i) {
            int idx = tid + i * 256;
            int r = idx >> 3, c = idx & 7;
            uint64_t src = __cvta_generic_to_global(srcs[t] + (size_t)(kb * 64 + r) * DHD + c * 8);
            uint32_t dst = stage + t * AT_TILE + r * AT_STRIDE + c * 16;
            CP_ASYNC16(dst, src);
        }
    }
}

__global__ void __launch_bounds__(256, 2) attn_kernel()
{
    const int qt = blockIdx.x;                 // 0..31
    const int bh = blockIdx.y;                 // 0..63
    const int b = bh >> 5, h = bh & 31, kvh = h >> 2;
    const int tid = threadIdx.x, lane = tid & 31, w = tid >> 5;
    const uint32_t sb = smem_u32(smraw);
    const int nkb = min(16, 2 * qt + 2);

    const __nv_bfloat16* Kh = g_k_hi + (size_t)(b * NKV + kvh) * WIN * DHD;
    const __nv_bfloat16* Kl = g_k_lo + (size_t)(b * NKV + kvh) * WIN * DHD;
    const __nv_bfloat16* Vh = g_v_hi + (size_t)(b * NKV + kvh) * WIN * DHD;
    const __nv_bfloat16* Vl = g_v_lo + (size_t)(b * NKV + kvh) * WIN * DHD;

    // Stage Q (128 x 64 hi/lo = 36864 B) through stage-0 buffer
    {
        const __nv_bfloat16* qh = g_q_hi + ((size_t)bh * TT + (size_t)qt * 128) * DHD;
        const __nv_bfloat16* ql = g_q_lo + ((size_t)bh * TT + (size_t)qt * 128) * DHD;
#pragma unroll
        for (int i = 0; i < 4; ++i) {
            int idx = tid + i * 256;
            int r = idx >> 3, c = idx & 7;
            *(uint4*)(smraw + r * AT_STRIDE + c * 16) =
                *(const uint4*)(qh + (size_t)r * DHD + c * 8);
            *(uint4*)(smraw + 2 * AT_TILE + r * AT_STRIDE + c * 16) =
                *(const uint4*)(ql + (size_t)r * DHD + c * 8);
        }
    }
    __syncthreads();

    uint32_t qhf[4][4], qlf[4][4];
    {
        uint32_t a_addr = sb + (uint32_t)(w * 16 + (lane & 15)) * AT_STRIDE
                        + (uint32_t)((lane >> 4) * 16);
#pragma unroll
        for (int kc = 0; kc < 4; ++kc) {
            ldsm4(qhf[kc], a_addr + kc * 32);
            ldsm4(qlf[kc], a_addr + 2 * AT_TILE + kc * 32);
        }
    }
    __syncthreads();   // all warps hold Q fragments; stage-0 can be overwritten

    attn_issue(Kh, Kl, Vh, Vl, sb, 0, tid);
    CP_COMMIT();

    float m0 = -INFINITY, m1 = -INFINITY, l0 = 0.f, l1 = 0.f;
    float oac[8][4];
#pragma unroll
    for (int nt = 0; nt < 8; ++nt)
#pragma unroll
        for (int j = 0; j < 4; ++j) oac[nt][j] = 0.f;

    const int trow0 = qt * 128 + w * 16 + (lane >> 2);
    const int scb = (lane & 3) * 2;
    const uint32_t b_off = (uint32_t)(((lane & 7) + ((lane & 16) >> 1)) * AT_STRIDE
                         + ((lane >> 3) & 1) * 16);
    const uint32_t v_off = (uint32_t)((((lane >> 3) & 1) * 8 + (lane & 7)) * AT_STRIDE
                         + (lane >> 4) * 16);

    for (int kb = 0; kb < nkb; ++kb) {
        uint32_t stage = sb + (uint32_t)(kb & 1) * AT_STAGE;
        if (kb + 1 < nkb) {
            attn_issue(Kh, Kl, Vh, Vl, sb + (uint32_t)((kb + 1) & 1) * AT_STAGE, kb + 1, tid);
            CP_COMMIT();
            CP_WAIT1();
        } else {
            CP_WAIT0();
        }
        __syncthreads();

        float sac[8][4];
#pragma unroll
        for (int nt = 0; nt < 8; ++nt)
#pragma unroll
            for (int j = 0; j < 4; ++j) sac[nt][j] = 0.f;

#pragma unroll
        for (int kc = 0; kc < 4; ++kc) {
            uint32_t kf[4][4];
#pragma unroll
            for (int ng = 0; ng < 4; ++ng)
                ldsm4(kf[ng], stage + (uint32_t)(ng * 16) * AT_STRIDE + b_off + kc * 32);
#pragma unroll
            for (int ng = 0; ng < 4; ++ng) {
                mma16816(sac[2 * ng],     qhf[kc], &kf[ng][0]);
                mma16816(sac[2 * ng + 1], qhf[kc], &kf[ng][2]);
            }
#pragma unroll
            for (int ng = 0; ng < 4; ++ng) {
                mma16816(sac[2 * ng],     qlf[kc], &kf[ng][0]);
                mma16816(sac[2 * ng + 1], qlf[kc], &kf[ng][2]);
            }
#pragma unroll
            for (int ng = 0; ng < 4; ++ng)
                ldsm4(kf[ng], stage + AT_TILE + (uint32_t)(ng * 16) * AT_STRIDE + b_off + kc * 32);
#pragma unroll
            for (int ng = 0; ng < 4; ++ng) {
                mma16816(sac[2 * ng],     qhf[kc], &kf[ng][0]);
                mma16816(sac[2 * ng + 1], qhf[kc], &kf[ng][2]);
            }
        }

        if (kb * 64 + 63 > trow0) {
#pragma unroll
            for (int nt = 0; nt < 8; ++nt) {
                int s0 = kb * 64 + nt * 8 + scb;
                if (s0     > trow0)     sac[nt][0] = -INFINITY;
                if (s0 + 1 > trow0)     sac[nt][1] = -INFINITY;
                if (s0     > trow0 + 8) sac[nt][2] = -INFINITY;
                if (s0 + 1 > trow0 + 8) sac[nt][3] = -INFINITY;
            }
        }

        float mx0 = -INFINITY, mx1 = -INFINITY;
#pragma unroll
        for (int nt = 0; nt < 8; ++nt) {
            mx0 = fmaxf(mx0, fmaxf(sac[nt][0], sac[nt][1]));
            mx1 = fmaxf(mx1, fmaxf(sac[nt][2], sac[nt][3]));
        }
        mx0 = fmaxf(mx0, __shfl_xor_sync(0xffffffffu, mx0, 1));
        mx0 = fmaxf(mx0, __shfl_xor_sync(0xffffffffu, mx0, 2));
        mx1 = fmaxf(mx1, __shfl_xor_sync(0xffffffffu, mx1, 1));
        mx1 = fmaxf(mx1, __shfl_xor_sync(0xffffffffu, mx1, 2));

        float mn0 = fmaxf(m0, mx0), mn1 = fmaxf(m1, mx1);
        float cr0 = __expf(m0 - mn0), cr1 = __expf(m1 - mn1);
        float s0 = 0.f, s1 = 0.f;
#pragma unroll
        for (int nt = 0; nt < 8; ++nt) {
            float p0 = __expf(sac[nt][0] - mn0);
            float p1 = __expf(sac[nt][1] - mn0);
            float p2 = __expf(sac[nt][2] - mn1);
            float p3 = __expf(sac[nt][3] - mn1);
            sac[nt][0] = p0; sac[nt][1] = p1; sac[nt][2] = p2; sac[nt][3] = p3;
            s0 += p0 + p1;
            s1 += p2 + p3;
        }
        s0 += __shfl_xor_sync(0xffffffffu, s0, 1);
        s0 += __shfl_xor_sync(0xffffffffu, s0, 2);
        s1 += __shfl_xor_sync(0xffffffffu, s1, 1);
        s1 += __shfl_xor_sync(0xffffffffu, s1, 2);
        l0 = l0 * cr0 + s0;
        l1 = l1 * cr1 + s1;
        m0 = mn0; m1 = mn1;
#pragma unroll
        for (int nt = 0; nt < 8; ++nt) {
            oac[nt][0] *= cr0; oac[nt][1] *= cr0;
            oac[nt][2] *= cr1; oac[nt][3] *= cr1;
        }

#pragma unroll
        for (int kc = 0; kc < 4; ++kc) {
            uint32_t ph[4], pl[4];
            split2(sac[2 * kc][0],     sac[2 * kc][1],     ph[0], pl[0]);
            split2(sac[2 * kc][2],     sac[2 * kc][3],     ph[1], pl[1]);
            split2(sac[2 * kc + 1][0], sac[2 * kc + 1][1], ph[2], pl[2]);
            split2(sac[2 * kc + 1][2], sac[2 * kc + 1][3], ph[3], pl[3]);

            uint32_t vaddr = stage + 2 * AT_TILE + (uint32_t)(kc * 16) * AT_STRIDE + v_off;
#pragma unroll
            for (int nt2 = 0; nt2 < 4; ++nt2) {
                uint32_t f[4];
                ldsm4t(f, vaddr + nt2 * 32);                 // Vh
                mma16816(oac[2 * nt2],     ph, &f[0]);
                mma16816(oac[2 * nt2 + 1], ph, &f[2]);
                mma16816(oac[2 * nt2],     pl, &f[0]);
                mma16816(oac[2 * nt2 + 1], pl, &f[2]);
                ldsm4t(f, vaddr + AT_TILE + nt2 * 32);       // Vl
                mma16816(oac[2 * nt2],     ph, &f[0]);
                mma16816(oac[2 * nt2 + 1], ph, &f[2]);
            }
        }
        __syncthreads();
    }

    // epilogue: O /= l, fp16 round store for the Wo GEMM
    float i0 = 1.f / l0, i1 = 1.f / l1;
    size_t base0 = ((size_t)(b * TT) + trow0) * DDIM + h * DHD + scb;
    size_t base1 = base0 + (size_t)8 * DDIM;
#pragma unroll
    for (int nt = 0; nt < 8; ++nt) {
        __half2 h0 = __halves2half2(__float2half_rn(oac[nt][0] * i0),
                                    __float2half_rn(oac[nt][1] * i0));
        __half2 h1 = __halves2half2(__float2half_rn(oac[nt][2] * i1),
                                    __float2half_rn(oac[nt][3] * i1));
        *(uint32_t*)(g_ao_h + base0 + nt * 8) = *reinterpret_cast<uint32_t*>(&h0);
        *(uint32_t*)(g_ao_h + base1 + nt * 8) = *reinterpret_cast<uint32_t*>(&h1);
    }
}

// ---------------------------------------------------------------------------
extern "C" void kernel_launch(void* const* d_in, const int* in_sizes, int n_in,
                              void* d_out, int out_size)
{
    const float* x  = (const float*)d_in[0];
    const float* kc = (const float*)d_in[1];
    const float* vc = (const float*)d_in[2];
    const float* Wq = (const float*)d_in[3];
    const float* Wo = (const float*)d_in[4];
    float* out = (float*)d_out;
    (void)in_sizes; (void)n_in; (void)out_size;

    cudaFuncSetAttribute(attn_kernel, cudaFuncAttributeMaxDynamicSharedMemorySize, ATTN_SMEM);
    cudaFuncSetAttribute(qgemm_rope_kernel, cudaFuncAttributeMaxDynamicSharedMemorySize, GEMM_SMEM);
    cudaFuncSetAttribute(ogemm_kernel, cudaFuncAttributeMaxDynamicSharedMemorySize, GEMM_SMEM);

    __half *xh, *wqh, *woh;
    cudaGetSymbolAddress((void**)&xh,  g_x_h);
    cudaGetSymbolAddress((void**)&wqh, g_wq_h);
    cudaGetSymbolAddress((void**)&woh, g_wo_h);

    initfreq_kernel<<<1, 32>>>();

    const int nx4 = (BB * TT * DDIM) / 4;
    const int nw4 = (DDIM * DDIM) / 4;
    round16_kernel<<<nx4 / 256, 256>>>((const float4*)x,  (uint2*)xh,  nx4);
    round16_kernel<<<nw4 / 256, 256>>>((const float4*)Wq, (uint2*)wqh, nw4);
    round16_kernel<<<nw4 / 256, 256>>>((const float4*)Wo, (uint2*)woh, nw4);

    const int nkv4 = (BB * NKV * WIN * DHD) / 4;
    kvsplit_kernel<<<nkv4 / 256, 256>>>((const float4*)kc, (const float4*)vc);

    dim3 ggrid(DDIM / 128, (BB * TT) / 128);   // (16, 64)
    qgemm_rope_kernel<<<ggrid, 256, GEMM_SMEM>>>();

    dim3 agrid(TT / 128, BB * NH);             // (32, 64)
    attn_kernel<<<agrid, 256, ATTN_SMEM>>>();

    ogemm_kernel<<<ggrid, 256, GEMM_SMEM>>>(out);
}

// round 11
// speedup vs baseline: 16.0257x; 1.4327x over previous
#include <cuda_runtime.h>
#include <cuda_bf16.h>
#include <cuda_fp16.h>
#include <math.h>
#include <stdint.h>

// Problem constants
#define BB    2
#define TT    4096
#define DDIM  2048
#define NH    32
#define NKV   8
#define DHD   64
#define TCC   4096
#define WIN   1024
#define WSTART 3072
#define SCALE 0.125f

// ---------------------------------------------------------------------------
// Scratch (device globals — allocation-free rule)
// ---------------------------------------------------------------------------
__device__ __half g_q_h  [(size_t)BB * NH * TT * DHD];   // RoPE'd, pre-scaled, fp16
__device__ __half g_k_h  [(size_t)BB * NKV * WIN * DHD];
__device__ __half g_v_h  [(size_t)BB * NKV * WIN * DHD];
__device__ __half g_x_h  [(size_t)BB * TT * DDIM];
__device__ __half g_wq_h [(size_t)DDIM * DDIM];
__device__ __half g_wo_h [(size_t)DDIM * DDIM];
__device__ __half g_ao_h [(size_t)BB * TT * DDIM];
__device__ float  g_invfreq[32];

extern __shared__ char smraw[];

// ---------------------------------------------------------------------------
// Helpers (baseline PTX only: ldmatrix / mma.sync / cp.async — all sm_80+)
// ---------------------------------------------------------------------------
__device__ __forceinline__ uint32_t smem_u32(const void* p) {
    uint32_t a;
    asm("{ .reg .u64 t; cvta.to.shared.u64 t, %1; cvt.u32.u64 %0, t; }"
        : "=r"(a) : "l"(p));
    return a;
}

__device__ __forceinline__ void ldsm4(uint32_t* r, uint32_t addr) {
    asm volatile("ldmatrix.sync.aligned.m8n8.x4.shared.b16 {%0,%1,%2,%3}, [%4];"
        : "=r"(r[0]), "=r"(r[1]), "=r"(r[2]), "=r"(r[3]) : "r"(addr));
}

__device__ __forceinline__ void ldsm4t(uint32_t* r, uint32_t addr) {
    asm volatile("ldmatrix.sync.aligned.m8n8.x4.trans.shared.b16 {%0,%1,%2,%3}, [%4];"
        : "=r"(r[0]), "=r"(r[1]), "=r"(r[2]), "=r"(r[3]) : "r"(addr));
}

// fp16 HMMA (fp32 accumulate)
__device__ __forceinline__ void mma16816h(float* c, const uint32_t* a, const uint32_t* b) {
    asm("mma.sync.aligned.m16n8k16.row.col.f32.f16.f16.f32 "
        "{%0,%1,%2,%3}, {%4,%5,%6,%7}, {%8,%9}, {%0,%1,%2,%3};"
        : "+f"(c[0]), "+f"(c[1]), "+f"(c[2]), "+f"(c[3])
        : "r"(a[0]), "r"(a[1]), "r"(a[2]), "r"(a[3]), "r"(b[0]), "r"(b[1]));
}

#define CP_ASYNC16(dst, src) \
    asm volatile("cp.async.cg.shared.global [%0], [%1], 16;" \
                 :: "r"(dst), "l"(src) : "memory")
#define CP_COMMIT() asm volatile("cp.async.commit_group;" ::: "memory")
#define CP_WAIT1()  asm volatile("cp.async.wait_group 1;" ::: "memory")
#define CP_WAIT0()  asm volatile("cp.async.wait_group 0;" ::: "memory")

__device__ __forceinline__ uint32_t pack2h(float a, float b) {
    __half2 h = __halves2half2(__float2half_rn(a), __float2half_rn(b));
    return *reinterpret_cast<uint32_t*>(&h);
}

// ---------------------------------------------------------------------------
// Prep kernels
// ---------------------------------------------------------------------------
// fp32 -> fp16 round
__global__ void __launch_bounds__(256) round16_kernel(
    const float4* __restrict__ in, uint2* __restrict__ out, int n4)
{
    int i = blockIdx.x * 256 + threadIdx.x;
    if (i >= n4) return;
    float4 v = in[i];
    uint2 o;
    o.x = pack2h(v.x, v.y);
    o.y = pack2h(v.z, v.w);
    out[i] = o;
}

// K/V window (last 1024 positions) -> fp16, layout [b][kv][1024][64]
__global__ void __launch_bounds__(256) kvround_kernel(
    const float4* __restrict__ kc, const float4* __restrict__ vc)
{
    int idx = blockIdx.x * 256 + threadIdx.x;
    int within = idx & ((WIN * DHD / 4) - 1);
    int bk = idx >> 14;
    size_t src = (size_t)bk * (TCC * DHD / 4) + (WSTART * DHD / 4) + within;
    float4 k4 = kc[src];
    float4 v4 = vc[src];
    uint2 ko, vo;
    ko.x = pack2h(k4.x, k4.y);  ko.y = pack2h(k4.z, k4.w);
    vo.x = pack2h(v4.x, v4.y);  vo.y = pack2h(v4.z, v4.w);
    ((uint2*)g_k_h)[idx] = ko;
    ((uint2*)g_v_h)[idx] = vo;
}

__global__ void initfreq_kernel() {
    int i = threadIdx.x;
    g_invfreq[i] = (float)exp(-(double)i * (9.210340371976184 / 32.0));
}

// ---------------------------------------------------------------------------
// GEMM mainloop (single-pass fp16): acc = A.B^T, fp32 accum.
// CTA tile 128x128, 8 warps. K-chunk = 64 fp16 (144B stride, LDSM
// conflict-free). 3-stage cp.async pipeline, 2 CTAs/SM, 32 chunks.
// ---------------------------------------------------------------------------
#define GTILE      (128 * 144)         // 18432
#define GSTAGE     (2 * GTILE)         // 36864 (A, B)
#define NSTAGE     3
#define GEMM_SMEM  (NSTAGE * GSTAGE)   // 110592

__device__ __forceinline__ void issue_chunk(
    const __half* __restrict__ A, const __half* __restrict__ B,
    uint32_t stage, int k0, int tid)
{
    const __half* srcs[2] = {A, B};
#pragma unroll
    for (int t = 0; t < 2; ++t) {
#pragma unroll
        for (int i = 0; i < 4; ++i) {
            int idx = tid + i * 256;            // 0..1023
            int r = idx >> 3, cc = idx & 7;
            uint64_t src = __cvta_generic_to_global(srcs[t] + (size_t)r * DDIM + k0 + cc * 8);
            uint32_t dst = stage + t * GTILE + r * 144 + cc * 16;
            CP_ASYNC16(dst, src);
        }
    }
}

__device__ __forceinline__ void compute_stage(
    uint32_t stage, int wm, int wn, int lane, float acc[2][8][4])
{
    const uint32_t a_off = (uint32_t)((lane & 15) * 144 + (lane >> 4) * 16);
    const uint32_t b_off = (uint32_t)(((lane & 7) + ((lane & 16) >> 1)) * 144
                         + ((lane >> 3) & 1) * 16);

#pragma unroll
    for (int s2 = 0; s2 < 4; ++s2) {
        const uint32_t kb = s2 * 32;

        uint32_t af[2][4];
#pragma unroll
        for (int mt = 0; mt < 2; ++mt)
            ldsm4(af[mt], stage + (uint32_t)(wm * 32 + mt * 16) * 144 + a_off + kb);

        uint32_t bfr[8][2];
#pragma unroll
        for (int ng = 0; ng < 4; ++ng) {
            uint32_t base = stage + GTILE + (uint32_t)(wn * 64 + ng * 16) * 144 + b_off + kb;
            uint32_t t4[4];
            ldsm4(t4, base);
            bfr[ng * 2][0] = t4[0]; bfr[ng * 2][1] = t4[1];
            bfr[ng * 2 + 1][0] = t4[2]; bfr[ng * 2 + 1][1] = t4[3];
        }
#pragma unroll
        for (int mt = 0; mt < 2; ++mt)
#pragma unroll
            for (int nt = 0; nt < 8; ++nt)
                mma16816h(acc[mt][nt], af[mt], bfr[nt]);
    }
}

__device__ __forceinline__ void gemm_mainloop(
    const __half* __restrict__ A, const __half* __restrict__ B,
    float acc[2][8][4])
{
    const uint32_t sb = smem_u32(smraw);
    const int tid = threadIdx.x;
    const int lane = tid & 31, w = tid >> 5;
    const int wm = w >> 1, wn = w & 1;

#pragma unroll
    for (int mt = 0; mt < 2; ++mt)
#pragma unroll
        for (int nt = 0; nt < 8; ++nt)
#pragma unroll
            for (int j = 0; j < 4; ++j) acc[mt][nt][j] = 0.f;

    issue_chunk(A, B, sb + 0 * GSTAGE, 0,  tid);
    CP_COMMIT();
    issue_chunk(A, B, sb + 1 * GSTAGE, 64, tid);
    CP_COMMIT();

    for (int c = 0; c < 32; ++c) {
        if (c + 2 < 32) CP_WAIT1(); else CP_WAIT0();
        __syncthreads();
        if (c + 2 < 32) {
            issue_chunk(A, B, sb + (uint32_t)((c + 2) % NSTAGE) * GSTAGE,
                        (c + 2) * 64, tid);
            CP_COMMIT();
        }
        compute_stage(sb + (uint32_t)(c % NSTAGE) * GSTAGE, wm, wn, lane, acc);
    }
}

// ---------------------------------------------------------------------------
// Kernel 1: q = RoPE(x @ Wq^T) * SCALE -> fp16 [B*NH][T][64]
// ---------------------------------------------------------------------------
__global__ void __launch_bounds__(256, 2) qgemm_rope_kernel()
{
    const int bn = blockIdx.x, bm = blockIdx.y;
    float acc[2][8][4];
    gemm_mainloop(g_x_h + (size_t)bm * 128 * DDIM,
                  g_wq_h + (size_t)bn * 128 * DDIM, acc);

    const int tid = threadIdx.x, lane = tid & 31, w = tid >> 5;
    const int wm = w >> 1, wn = w & 1;
    const int h = bn * 2 + wn;
    const int fc = lane & 3;

#pragma unroll
    for (int mt = 0; mt < 2; ++mt) {
        const int m0 = bm * 128 + wm * 32 + mt * 16 + (lane >> 2);
#pragma unroll
        for (int rh = 0; rh < 2; ++rh) {
            const int m = m0 + rh * 8;
            const int b = m >> 12, t = m & 4095;
            size_t rbase = ((size_t)(b * NH + h) * TT + t) * DHD;
#pragma unroll
            for (int nt = 0; nt < 8; ++nt) {
                float e = acc[mt][nt][rh * 2 + 0];
                float o = acc[mt][nt][rh * 2 + 1];
                float ph = (float)t * g_invfreq[nt * 4 + fc];
                float sn, cn;
                sincosf(ph, &sn, &cn);
                float v0 = (e * cn - o * sn) * SCALE;
                float v1 = (e * sn + o * cn) * SCALE;
                *(uint32_t*)(g_q_h + rbase + nt * 8 + fc * 2) = pack2h(v0, v1);
            }
        }
    }
}

// ---------------------------------------------------------------------------
// Kernel 3: out = ao @ Wo^T -> d_out fp32
// ---------------------------------------------------------------------------
__global__ void __launch_bounds__(256, 2) ogemm_kernel(float* __restrict__ out)
{
    const int bn = blockIdx.x, bm = blockIdx.y;
    float acc[2][8][4];
    gemm_mainloop(g_ao_h + (size_t)bm * 128 * DDIM,
                  g_wo_h + (size_t)bn * 128 * DDIM, acc);

    const int tid = threadIdx.x, lane = tid & 31, w = tid >> 5;
    const int wm = w >> 1, wn = w & 1;
    const int col = bn * 128 + wn * 64 + (lane & 3) * 2;

#pragma unroll
    for (int mt = 0; mt < 2; ++mt) {
        const int m0 = bm * 128 + wm * 32 + mt * 16 + (lane >> 2);
#pragma unroll
        for (int rh = 0; rh < 2; ++rh) {
            float* crow = out + (size_t)(m0 + rh * 8) * DDIM + col;
#pragma unroll
            for (int nt = 0; nt < 8; ++nt) {
                float2 v = make_float2(acc[mt][nt][rh * 2 + 0], acc[mt][nt][rh * 2 + 1]);
                *(float2*)(crow + nt * 8) = v;
            }
        }
    }
}

// ---------------------------------------------------------------------------
// Kernel 2: tensor-core windowed causal attention (flash style, fp16 HMMA,
// single pass per GEMM). CTA = 128 q rows x bh. K/V single fp16,
// double-buffered; Q staged through stage-0. smem 36.9KB, 2 CTAs/SM.
// ---------------------------------------------------------------------------
#define AT_STRIDE 144
#define AT_TILE   (64 * AT_STRIDE)          // 9216
#define AT_STAGE  (2 * AT_TILE)             // 18432 (K, V)
#define ATTN_SMEM (2 * AT_STAGE)            // 36864

__device__ __forceinline__ void attn_issue(
    const __half* __restrict__ K, const __half* __restrict__ V,
    uint32_t stage, int kb, int tid)
{
    const __half* srcs[2] = {K, V};
#pragma unroll
    for (int t = 0; t < 2; ++t) {
#pragma unroll
        for (int i = 0; i < 2; ++i) {
            int idx = tid + i * 256;               // 0..511
            int r = idx >> 3, c = idx & 7;
            uint64_t src = __cvta_generic_to_global(srcs[t] + (size_t)(kb * 64 + r) * DHD + c * 8);
            uint32_t dst = stage + t * AT_TILE + r * AT_STRIDE + c * 16;
            CP_ASYNC16(dst, src);
        }
    }
}

__global__ void __launch_bounds__(256, 2) attn_kernel()
{
    const int qt = blockIdx.x;                 // 0..31
    const int bh = blockIdx.y;                 // 0..63
    const int b = bh >> 5, h = bh & 31, kvh = h >> 2;
    const int tid = threadIdx.x, lane = tid & 31, w = tid >> 5;
    const uint32_t sb = smem_u32(smraw);
    const int nkb = min(16, 2 * qt + 2);

    const __half* K = g_k_h + (size_t)(b * NKV + kvh) * WIN * DHD;
    const __half* V = g_v_h + (size_t)(b * NKV + kvh) * WIN * DHD;

    // Stage Q (128 x 64 fp16 = 18432 B) through stage-0 buffer
    {
        const __half* qp = g_q_h + ((size_t)bh * TT + (size_t)qt * 128) * DHD;
#pragma unroll
        for (int i = 0; i < 4; ++i) {
            int idx = tid + i * 256;               // 0..1023
            int r = idx >> 3, c = idx & 7;
            *(uint4*)(smraw + r * AT_STRIDE + c * 16) =
                *(const uint4*)(qp + (size_t)r * DHD + c * 8);
        }
    }
    __syncthreads();

    uint32_t qf[4][4];
    {
        uint32_t a_addr = sb + (uint32_t)(w * 16 + (lane & 15)) * AT_STRIDE
                        + (uint32_t)((lane >> 4) * 16);
#pragma unroll
        for (int kc = 0; kc < 4; ++kc)
            ldsm4(qf[kc], a_addr + kc * 32);
    }
    __syncthreads();   // all warps hold Q fragments; stage-0 can be overwritten

    attn_issue(K, V, sb, 0, tid);
    CP_COMMIT();

    float m0 = -INFINITY, m1 = -INFINITY, l0 = 0.f, l1 = 0.f;
    float oac[8][4];
#pragma unroll
    for (int nt = 0; nt < 8; ++nt)
#pragma unroll
        for (int j = 0; j < 4; ++j) oac[nt][j] = 0.f;

    const int trow0 = qt * 128 + w * 16 + (lane >> 2);
    const int scb = (lane & 3) * 2;
    const uint32_t b_off = (uint32_t)(((lane & 7) + ((lane & 16) >> 1)) * AT_STRIDE
                         + ((lane >> 3) & 1) * 16);
    const uint32_t v_off = (uint32_t)((((lane >> 3) & 1) * 8 + (lane & 7)) * AT_STRIDE
                         + (lane >> 4) * 16);

    for (int kb = 0; kb < nkb; ++kb) {
        uint32_t stage = sb + (uint32_t)(kb & 1) * AT_STAGE;
        if (kb + 1 < nkb) {
            attn_issue(K, V, sb + (uint32_t)((kb + 1) & 1) * AT_STAGE, kb + 1, tid);
            CP_COMMIT();
            CP_WAIT1();
        } else {
            CP_WAIT0();
        }
        __syncthreads();

        // ---- S = Q.K^T (pre-scaled), single fp16 pass
        float sac[8][4];
#pragma unroll
        for (int nt = 0; nt < 8; ++nt)
#pragma unroll
            for (int j = 0; j < 4; ++j) sac[nt][j] = 0.f;

#pragma unroll
        for (int kc = 0; kc < 4; ++kc) {
            uint32_t kf[4][4];
#pragma unroll
            for (int ng = 0; ng < 4; ++ng)
                ldsm4(kf[ng], stage + (uint32_t)(ng * 16) * AT_STRIDE + b_off + kc * 32);
#pragma unroll
            for (int ng = 0; ng < 4; ++ng) {
                mma16816h(sac[2 * ng],     qf[kc], &kf[ng][0]);
                mma16816h(sac[2 * ng + 1], qf[kc], &kf[ng][2]);
            }
        }

        // ---- causal mask (s > t)
        if (kb * 64 + 63 > trow0) {
#pragma unroll
            for (int nt = 0; nt < 8; ++nt) {
                int s0 = kb * 64 + nt * 8 + scb;
                if (s0     > trow0)     sac[nt][0] = -INFINITY;
                if (s0 + 1 > trow0)     sac[nt][1] = -INFINITY;
                if (s0     > trow0 + 8) sac[nt][2] = -INFINITY;
                if (s0 + 1 > trow0 + 8) sac[nt][3] = -INFINITY;
            }
        }

        // ---- online softmax (rows r and r+8)
        float mx0 = -INFINITY, mx1 = -INFINITY;
#pragma unroll
        for (int nt = 0; nt < 8; ++nt) {
            mx0 = fmaxf(mx0, fmaxf(sac[nt][0], sac[nt][1]));
            mx1 = fmaxf(mx1, fmaxf(sac[nt][2], sac[nt][3]));
        }
        mx0 = fmaxf(mx0, __shfl_xor_sync(0xffffffffu, mx0, 1));
        mx0 = fmaxf(mx0, __shfl_xor_sync(0xffffffffu, mx0, 2));
        mx1 = fmaxf(mx1, __shfl_xor_sync(0xffffffffu, mx1, 1));
        mx1 = fmaxf(mx1, __shfl_xor_sync(0xffffffffu, mx1, 2));

        float mn0 = fmaxf(m0, mx0), mn1 = fmaxf(m1, mx1);
        float cr0 = __expf(m0 - mn0), cr1 = __expf(m1 - mn1);
        float s0 = 0.f, s1 = 0.f;
#pragma unroll
        for (int nt = 0; nt < 8; ++nt) {
            float p0 = __expf(sac[nt][0] - mn0);
            float p1 = __expf(sac[nt][1] - mn0);
            float p2 = __expf(sac[nt][2] - mn1);
            float p3 = __expf(sac[nt][3] - mn1);
            sac[nt][0] = p0; sac[nt][1] = p1; sac[nt][2] = p2; sac[nt][3] = p3;
            s0 += p0 + p1;
            s1 += p2 + p3;
        }
        s0 += __shfl_xor_sync(0xffffffffu, s0, 1);
        s0 += __shfl_xor_sync(0xffffffffu, s0, 2);
        s1 += __shfl_xor_sync(0xffffffffu, s1, 1);
        s1 += __shfl_xor_sync(0xffffffffu, s1, 2);
        l0 = l0 * cr0 + s0;
        l1 = l1 * cr1 + s1;
        m0 = mn0; m1 = mn1;
#pragma unroll
        for (int nt = 0; nt < 8; ++nt) {
            oac[nt][0] *= cr0; oac[nt][1] *= cr0;
            oac[nt][2] *= cr1; oac[nt][3] *= cr1;
        }

        // ---- O += P.V, P packed fp16 in registers, single pass
#pragma unroll
        for (int kc = 0; kc < 4; ++kc) {
            uint32_t ph[4];
            ph[0] = pack2h(sac[2 * kc][0],     sac[2 * kc][1]);
            ph[1] = pack2h(sac[2 * kc][2],     sac[2 * kc][3]);
            ph[2] = pack2h(sac[2 * kc + 1][0], sac[2 * kc + 1][1]);
            ph[3] = pack2h(sac[2 * kc + 1][2], sac[2 * kc + 1][3]);

            uint32_t vaddr = stage + AT_TILE + (uint32_t)(kc * 16) * AT_STRIDE + v_off;
#pragma unroll
            for (int nt2 = 0; nt2 < 4; ++nt2) {
                uint32_t f[4];
                ldsm4t(f, vaddr + nt2 * 32);
                mma16816h(oac[2 * nt2],     ph, &f[0]);
                mma16816h(oac[2 * nt2 + 1], ph, &f[2]);
            }
        }
        __syncthreads();
    }

    // epilogue: O /= l, fp16 round store for the Wo GEMM
    float i0 = 1.f / l0, i1 = 1.f / l1;
    size_t base0 = ((size_t)(b * TT) + trow0) * DDIM + h * DHD + scb;
    size_t base1 = base0 + (size_t)8 * DDIM;
#pragma unroll
    for (int nt = 0; nt < 8; ++nt) {
        *(uint32_t*)(g_ao_h + base0 + nt * 8) = pack2h(oac[nt][0] * i0, oac[nt][1] * i0);
        *(uint32_t*)(g_ao_h + base1 + nt * 8) = pack2h(oac[nt][2] * i1, oac[nt][3] * i1);
    }
}

// ---------------------------------------------------------------------------
extern "C" void kernel_launch(void* const* d_in, const int* in_sizes, int n_in,
                              void* d_out, int out_size)
{
    const float* x  = (const float*)d_in[0];
    const float* kc = (const float*)d_in[1];
    const float* vc = (const float*)d_in[2];
    const float* Wq = (const float*)d_in[3];
    const float* Wo = (const float*)d_in[4];
    float* out = (float*)d_out;
    (void)in_sizes; (void)n_in; (void)out_size;

    cudaFuncSetAttribute(attn_kernel, cudaFuncAttributeMaxDynamicSharedMemorySize, ATTN_SMEM);
    cudaFuncSetAttribute(qgemm_rope_kernel, cudaFuncAttributeMaxDynamicSharedMemorySize, GEMM_SMEM);
    cudaFuncSetAttribute(ogemm_kernel, cudaFuncAttributeMaxDynamicSharedMemorySize, GEMM_SMEM);

    __half *xh, *wqh, *woh;
    cudaGetSymbolAddress((void**)&xh,  g_x_h);
    cudaGetSymbolAddress((void**)&wqh, g_wq_h);
    cudaGetSymbolAddress((void**)&woh, g_wo_h);

    initfreq_kernel<<<1, 32>>>();

    const int nx4 = (BB * TT * DDIM) / 4;
    const int nw4 = (DDIM * DDIM) / 4;
    round16_kernel<<<nx4 / 256, 256>>>((const float4*)x,  (uint2*)xh,  nx4);
    round16_kernel<<<nw4 / 256, 256>>>((const float4*)Wq, (uint2*)wqh, nw4);
    round16_kernel<<<nw4 / 256, 256>>>((const float4*)Wo, (uint2*)woh, nw4);

    const int nkv4 = (BB * NKV * WIN * DHD) / 4;
    kvround_kernel<<<nkv4 / 256, 256>>>((const float4*)kc, (const float4*)vc);

    dim3 ggrid(DDIM / 128, (BB * TT) / 128);   // (16, 64)
    qgemm_rope_kernel<<<ggrid, 256, GEMM_SMEM>>>();

    dim3 agrid(TT / 128, BB * NH);             // (32, 64)
    attn_kernel<<<agrid, 256, ATTN_SMEM>>>();

    ogemm_kernel<<<ggrid, 256, GEMM_SMEM>>>(out);
}